// round 13
// baseline (speedup 1.0000x reference)
#include <cuda_runtime.h>
#include <cuda_bf16.h>
#include <math.h>
#include <stdint.h>

// ---------------------------------------------------------------------------
// Problem constants
// ---------------------------------------------------------------------------
#define LAYERS 12
#define CDIM   768
#define HEADS  12
#define HD     64
#define NTOK   196
#define BATCH  16
#define DFF    3072
#define NCLS   1000
#define TOKENS (BATCH * NTOK)        // 3136
#define QKVDIM (3 * CDIM)            // 2304
#define NROWS_ATT (BATCH * HEADS * NTOK) // 37632
#define BN_RSTD 0.99999500003749969f

// ---------------------------------------------------------------------------
// fp32 scratch
// ---------------------------------------------------------------------------
#define OFF_X      0
#define OFF_QKV    (OFF_X + (size_t)TOKENS * CDIM)
#define OFF_QQ     (OFF_QKV + (size_t)TOKENS * QKVDIM)
#define OFF_KK     (OFF_QQ + NROWS_ATT)
#define OFF_P      (OFF_KK + NROWS_ATT)
#define OFF_QK     (OFF_P + (size_t)BATCH * HEADS * NTOK * NTOK)
#define OFF_POOLED (OFF_QK + (size_t)BATCH * HEADS * NTOK * NTOK)
#define SCRATCH_TOTAL (OFF_POOLED + BATCH * CDIM)

__device__ __align__(256) float g_scratch[SCRATCH_TOTAL];

// ---------------------------------------------------------------------------
// bf16 scratch
// ---------------------------------------------------------------------------
#define NB_WQKV  ((size_t)LAYERS * QKVDIM * CDIM)
#define NB_WPROJ ((size_t)LAYERS * CDIM * CDIM)
#define NB_WFF1  ((size_t)LAYERS * DFF * CDIM)
#define NB_WFF2  ((size_t)LAYERS * CDIM * DFF)
#define NB_ACT   ((size_t)TOKENS * CDIM)
#define NB_F     ((size_t)TOKENS * DFF)
#define NB_QKVA  ((size_t)TOKENS * QKVDIM)

#define BO_WQKV_HI  ((size_t)0)
#define BO_WQKV_LO  (BO_WQKV_HI + NB_WQKV)
#define BO_WPROJ_HI (BO_WQKV_LO + NB_WQKV)
#define BO_WPROJ_LO (BO_WPROJ_HI + NB_WPROJ)
#define BO_WFF1_HI  (BO_WPROJ_LO + NB_WPROJ)
#define BO_WFF1_LO  (BO_WFF1_HI + NB_WFF1)
#define BO_WFF2_HI  (BO_WFF1_LO + NB_WFF1)
#define BO_WFF2_LO  (BO_WFF2_HI + NB_WFF2)
#define BO_H_HI     (BO_WFF2_LO + NB_WFF2)
#define BO_H_LO     (BO_H_HI + NB_ACT)
#define BO_O_HI     (BO_H_LO + NB_ACT)
#define BO_O_LO     (BO_O_HI + NB_ACT)
#define BO_X_HI     (BO_O_LO + NB_ACT)
#define BO_X_LO     (BO_X_HI + NB_ACT)
#define BO_F_HI     (BO_X_LO + NB_ACT)
#define BO_F_LO     (BO_F_HI + NB_F)
#define BO_QKV_HI   (BO_F_LO + NB_F)
#define BO_QKV_LO   (BO_QKV_HI + NB_QKVA)
#define BF_TOTAL    (BO_QKV_LO + NB_QKVA)

__device__ __align__(256) __nv_bfloat16 g_bf[BF_TOTAL];

// ---------------------------------------------------------------------------
// helpers
// ---------------------------------------------------------------------------
__device__ __forceinline__ uint32_t smem_u32(const void* p) {
    uint32_t a;
    asm("{ .reg .u64 t; cvta.to.shared.u64 t, %1; cvt.u32.u64 %0, t; }"
        : "=r"(a) : "l"(p));
    return a;
}
__device__ __forceinline__ float wsum(float v) {
    #pragma unroll
    for (int o = 16; o; o >>= 1) v += __shfl_xor_sync(0xffffffffu, v, o);
    return v;
}
__device__ __forceinline__ float wmax(float v) {
    #pragma unroll
    for (int o = 16; o; o >>= 1) v = fmaxf(v, __shfl_xor_sync(0xffffffffu, v, o));
    return v;
}
__device__ __forceinline__ void split_bf(float v, __nv_bfloat16& h, __nv_bfloat16& l) {
    h = __float2bfloat16(v);
    l = __float2bfloat16(v - __bfloat162float(h));
}
__device__ __forceinline__ void cp_async16(uint32_t dst, const void* src, int srcsize) {
    asm volatile("cp.async.cg.shared.global [%0], [%1], 16, %2;"
                 :: "r"(dst), "l"(src), "r"(srcsize) : "memory");
}
__device__ __forceinline__ void cp_commit() {
    asm volatile("cp.async.commit_group;" ::: "memory");
}
template <int N>
__device__ __forceinline__ void cp_wait() {
    asm volatile("cp.async.wait_group %0;" :: "n"(N) : "memory");
}
__device__ __forceinline__ void ldsm_x4(uint32_t addr, uint32_t* r) {
    asm volatile("ldmatrix.sync.aligned.m8n8.x4.shared.b16 {%0,%1,%2,%3}, [%4];"
        : "=r"(r[0]), "=r"(r[1]), "=r"(r[2]), "=r"(r[3]) : "r"(addr));
}
__device__ __forceinline__ void ldsm_x2(uint32_t addr, uint32_t* r) {
    asm volatile("ldmatrix.sync.aligned.m8n8.x2.shared.b16 {%0,%1}, [%2];"
        : "=r"(r[0]), "=r"(r[1]) : "r"(addr));
}
__device__ __forceinline__ void ldsm_x2_trans(uint32_t addr, uint32_t* r) {
    asm volatile("ldmatrix.sync.aligned.m8n8.x2.trans.shared.b16 {%0,%1}, [%2];"
        : "=r"(r[0]), "=r"(r[1]) : "r"(addr));
}
__device__ __forceinline__ void mma_bf16(float* d, const uint32_t* a, const uint32_t* b) {
    asm volatile("mma.sync.aligned.m16n8k16.row.col.f32.bf16.bf16.f32 "
        "{%0,%1,%2,%3}, {%4,%5,%6,%7}, {%8,%9}, {%0,%1,%2,%3};"
        : "+f"(d[0]), "+f"(d[1]), "+f"(d[2]), "+f"(d[3])
        : "r"(a[0]), "r"(a[1]), "r"(a[2]), "r"(a[3]), "r"(b[0]), "r"(b[1]));
}

// ---------------------------------------------------------------------------
// fp32 -> bf16 hi/lo conversion (vectorized)
// ---------------------------------------------------------------------------
__global__ void cvt_hilo_kernel(const float4* __restrict__ w,
                                __nv_bfloat162* __restrict__ hi,
                                __nv_bfloat162* __restrict__ lo, size_t n4) {
    size_t i = (size_t)blockIdx.x * blockDim.x + threadIdx.x;
    size_t stride = (size_t)gridDim.x * blockDim.x;
    for (; i < n4; i += stride) {
        float4 v = w[i];
        __nv_bfloat16 h0, l0, h1, l1, h2, l2, h3, l3;
        split_bf(v.x, h0, l0); split_bf(v.y, h1, l1);
        split_bf(v.z, h2, l2); split_bf(v.w, h3, l3);
        __nv_bfloat162 a, b;
        a.x = h0; a.y = h1; b.x = h2; b.y = h3;
        hi[2 * i] = a; hi[2 * i + 1] = b;
        a.x = l0; a.y = l1; b.x = l2; b.y = l3;
        lo[2 * i] = a; lo[2 * i + 1] = b;
    }
}

// ---------------------------------------------------------------------------
// x = x_in + pos_emb
// ---------------------------------------------------------------------------
__global__ void addpos_kernel(const float* __restrict__ x,
                              const float* __restrict__ pe,
                              float* __restrict__ gx) {
    int idx = blockIdx.x * blockDim.x + threadIdx.x;
    if (idx >= TOKENS * CDIM) return;
    int c = idx % CDIM;
    int n = (idx / CDIM) % NTOK;
    gx[idx] = x[idx] + pe[n * CDIM + c];
}

// ---------------------------------------------------------------------------
// LayerNorm. MODE 0: fp32 out. MODE 1: bf16 hi/lo out. MODE 2: both.
// ---------------------------------------------------------------------------
template <int MODE>
__global__ void ln_kernel(const float* __restrict__ in, float* __restrict__ outf,
                          __nv_bfloat16* __restrict__ oh, __nv_bfloat16* __restrict__ ol,
                          const float* __restrict__ g, const float* __restrict__ b,
                          int D) {
    extern __shared__ float row[];
    __shared__ float red[34];
    int r = blockIdx.x;
    const float* ip = in + (size_t)r * D;
    int tid = threadIdx.x, lane = tid & 31, w = tid >> 5;

    float s = 0.f;
    for (int c = tid; c < D; c += blockDim.x) { float v = ip[c]; row[c] = v; s += v; }
    s = wsum(s);
    if (lane == 0) red[w] = s;
    __syncthreads();
    if (tid == 0) { float t = 0; for (int q = 0; q < 8; q++) t += red[q]; red[32] = t / D; }
    __syncthreads();
    float mean = red[32];

    float vs = 0.f;
    for (int c = tid; c < D; c += blockDim.x) { float d = row[c] - mean; vs += d * d; }
    vs = wsum(vs);
    if (lane == 0) red[w] = vs;
    __syncthreads();
    if (tid == 0) { float t = 0; for (int q = 0; q < 8; q++) t += red[q]; red[33] = rsqrtf(t / D + 1e-5f); }
    __syncthreads();
    float rstd = red[33];

    for (int c = tid; c < D; c += blockDim.x) {
        float v = (row[c] - mean) * rstd * g[c] + b[c];
        size_t idx = (size_t)r * D + c;
        if (MODE == 0 || MODE == 2) outf[idx] = v;
        if (MODE == 1 || MODE == 2) {
            __nv_bfloat16 h, l;
            split_bf(v, h, l);
            oh[idx] = h; ol[idx] = l;
        }
    }
}

// ---------------------------------------------------------------------------
// Fused qkv LayerNorm (D=2304, in place) + bf16 hi/lo copy + per-head norms.
// ---------------------------------------------------------------------------
__global__ void ln_qkv_kernel(float* __restrict__ qkvbuf,
                              const float* __restrict__ g, const float* __restrict__ b,
                              __nv_bfloat16* __restrict__ oh, __nv_bfloat16* __restrict__ ol,
                              float* __restrict__ qq, float* __restrict__ kk) {
    __shared__ float row[QKVDIM];
    __shared__ float red[34];
    int r = blockIdx.x;
    float* ip = qkvbuf + (size_t)r * QKVDIM;
    int tid = threadIdx.x, lane = tid & 31, w = tid >> 5;

    float s = 0.f;
    for (int c = tid; c < QKVDIM; c += 256) { float v = ip[c]; row[c] = v; s += v; }
    s = wsum(s);
    if (lane == 0) red[w] = s;
    __syncthreads();
    if (tid == 0) { float t = 0; for (int q = 0; q < 8; q++) t += red[q]; red[32] = t / QKVDIM; }
    __syncthreads();
    float mean = red[32];

    float vs = 0.f;
    for (int c = tid; c < QKVDIM; c += 256) { float d = row[c] - mean; vs += d * d; }
    vs = wsum(vs);
    if (lane == 0) red[w] = vs;
    __syncthreads();
    if (tid == 0) { float t = 0; for (int q = 0; q < 8; q++) t += red[q]; red[33] = rsqrtf(t / QKVDIM + 1e-5f); }
    __syncthreads();
    float rstd = red[33];

    for (int c = tid; c < QKVDIM; c += 256) {
        float v = (row[c] - mean) * rstd * g[c] + b[c];
        row[c] = v;
        ip[c] = v;
        size_t idx = (size_t)r * QKVDIM + c;
        __nv_bfloat16 h, l;
        split_bf(v, h, l);
        oh[idx] = h; ol[idx] = l;
    }
    __syncthreads();

    int bb = r / NTOK, n = r % NTOK;
    for (int seg = w; seg < 24; seg += 8) {
        int base = seg * 64;
        float v0 = row[base + lane], v1 = row[base + lane + 32];
        float ssum = wsum(v0 * v0 + v1 * v1);
        if (lane == 0) {
            int h = seg % 12;
            float* dst = (seg < 12) ? qq : kk;
            dst[((size_t)bb * HEADS + h) * NTOK + n] = ssum;
        }
    }
}

// ---------------------------------------------------------------------------
// mma.sync bf16x3 GEMM (3-stage cp.async ring)
// ---------------------------------------------------------------------------
#define APAD 40
#define TILE_BYTES (128 * APAD * 2)
#define STAGE_BYTES (4 * TILE_BYTES)
#define NSTAGE 3
#define GSMEM (NSTAGE * STAGE_BYTES)

__device__ __forceinline__ void load_stage(
    uint32_t sbase, const __nv_bfloat16* __restrict__ Ah,
    const __nv_bfloat16* __restrict__ Al, const __nv_bfloat16* __restrict__ Bh,
    const __nv_bfloat16* __restrict__ Bl, int m0, int n0, int M, int K, int kc,
    int tid) {
    const __nv_bfloat16* gsrc[4] = {Ah, Al, Bh, Bl};
    #pragma unroll
    for (int tI = 0; tI < 4; tI++) {
        bool isA = tI < 2;
        int row0 = isA ? m0 : n0;
        uint32_t tb = sbase + tI * TILE_BYTES;
        #pragma unroll
        for (int c = 0; c < 2; c++) {
            int e = tid + c * 256;
            int rowi = e >> 2, qc = e & 3;
            int gr = row0 + rowi;
            int ok = (!isA || gr < M) ? 16 : 0;
            const __nv_bfloat16* src =
                gsrc[tI] + (size_t)(ok ? gr : row0) * K + kc + qc * 8;
            cp_async16(tb + rowi * 80 + qc * 16, src, ok);
        }
    }
}

template <int EPI>
__global__ __launch_bounds__(256, 1)
void gemm_mma(const __nv_bfloat16* __restrict__ Ah, const __nv_bfloat16* __restrict__ Al,
              const __nv_bfloat16* __restrict__ Bh, const __nv_bfloat16* __restrict__ Bl,
              const float* __restrict__ bias, float* __restrict__ Cf,
              __nv_bfloat16* __restrict__ Ch, __nv_bfloat16* __restrict__ Cl,
              int M, int N, int K) {
    extern __shared__ char smem[];
    uint32_t sb = smem_u32(smem);

    int tid = threadIdx.x, lane = tid & 31, wid = tid >> 5;
    int wm = wid >> 2, wn = wid & 3;
    int m0 = blockIdx.y * 128, n0 = blockIdx.x * 128;
    int NIT = K >> 5;

    float acc[4][4][4];
    #pragma unroll
    for (int i = 0; i < 4; i++)
        #pragma unroll
        for (int j = 0; j < 4; j++)
            #pragma unroll
            for (int q = 0; q < 4; q++) acc[i][j][q] = 0.f;

    int ar = lane & 15, ac = lane >> 4;
    int br = lane & 7, bc = (lane >> 3) & 1;

    load_stage(sb, Ah, Al, Bh, Bl, m0, n0, M, K, 0, tid);
    cp_commit();
    load_stage(sb + STAGE_BYTES, Ah, Al, Bh, Bl, m0, n0, M, K, 32, tid);
    cp_commit();

    int bufidx = 0;
    for (int it = 0; it < NIT; it++) {
        uint32_t buf = sb + (uint32_t)bufidx * STAGE_BYTES;
        if (it + 2 < NIT) {
            int li = (bufidx + 2) % NSTAGE;
            load_stage(sb + (uint32_t)li * STAGE_BYTES,
                       Ah, Al, Bh, Bl, m0, n0, M, K, (it + 2) * 32, tid);
            cp_commit();
            cp_wait<2>();
        } else if (it + 2 == NIT) {
            cp_wait<1>();
        } else {
            cp_wait<0>();
        }
        __syncthreads();

        uint32_t AhB = buf, AlB = buf + TILE_BYTES;
        uint32_t BhB = buf + 2 * TILE_BYTES, BlB = buf + 3 * TILE_BYTES;

        #pragma unroll
        for (int ks = 0; ks < 2; ks++) {
            uint32_t aH[4][4], aL[4][4], bF[4][2];
            int koff = (ks * 16 + ac * 8) * 2;
            int koffb = (ks * 16 + bc * 8) * 2;
            #pragma unroll
            for (int mt = 0; mt < 4; mt++) {
                uint32_t ra = (uint32_t)((wm * 64 + mt * 16 + ar) * 80) + koff;
                ldsm_x4(AhB + ra, aH[mt]);
                ldsm_x4(AlB + ra, aL[mt]);
            }
            #pragma unroll
            for (int nt = 0; nt < 4; nt++) {
                uint32_t rb = (uint32_t)((wn * 32 + nt * 8 + br) * 80) + koffb;
                ldsm_x2(BhB + rb, bF[nt]);
            }
            #pragma unroll
            for (int mt = 0; mt < 4; mt++)
                #pragma unroll
                for (int nt = 0; nt < 4; nt++) {
                    mma_bf16(acc[mt][nt], aH[mt], bF[nt]);
                    mma_bf16(acc[mt][nt], aL[mt], bF[nt]);
                }
            #pragma unroll
            for (int nt = 0; nt < 4; nt++) {
                uint32_t rb = (uint32_t)((wn * 32 + nt * 8 + br) * 80) + koffb;
                ldsm_x2(BlB + rb, bF[nt]);
            }
            #pragma unroll
            for (int mt = 0; mt < 4; mt++)
                #pragma unroll
                for (int nt = 0; nt < 4; nt++)
                    mma_bf16(acc[mt][nt], aH[mt], bF[nt]);
        }
        __syncthreads();
        bufidx = (bufidx + 1) % NSTAGE;
    }

    int qrow = lane >> 2, qcol = 2 * (lane & 3);
    #pragma unroll
    for (int mt = 0; mt < 4; mt++) {
        #pragma unroll
        for (int half = 0; half < 2; half++) {
            int gm = m0 + wm * 64 + mt * 16 + qrow + half * 8;
            if (gm >= M) continue;
            #pragma unroll
            for (int nt = 0; nt < 4; nt++) {
                int gn = n0 + wn * 32 + nt * 8 + qcol;
                float v0 = acc[mt][nt][half * 2 + 0] + bias[gn + 0];
                float v1 = acc[mt][nt][half * 2 + 1] + bias[gn + 1];
                size_t o = (size_t)gm * N + gn;
                if (EPI == 1) { v0 += Cf[o]; v1 += Cf[o + 1]; }
                if (EPI == 2) {
                    v0 = 0.5f * v0 * (1.f + erff(v0 * 0.70710678118654752f));
                    v1 = 0.5f * v1 * (1.f + erff(v1 * 0.70710678118654752f));
                    __nv_bfloat16 h, l;
                    split_bf(v0, h, l); Ch[o] = h;     Cl[o] = l;
                    split_bf(v1, h, l); Ch[o + 1] = h; Cl[o + 1] = l;
                } else {
                    Cf[o] = v0; Cf[o + 1] = v1;
                }
            }
        }
    }
}

// ---------------------------------------------------------------------------
// qk_mma: QK[b,h,i,j] = q_bh[i,:64] . k_bh[j,:64] via bf16x3 mma.
// ---------------------------------------------------------------------------
#define QKPAD 144
#define QKTILE (128 * QKPAD)
#define QKSMEM (4 * QKTILE)

__global__ __launch_bounds__(256, 1)
void qk_mma(const __nv_bfloat16* __restrict__ qkvh,
            const __nv_bfloat16* __restrict__ qkvl,
            float* __restrict__ QK) {
    extern __shared__ char smem[];
    uint32_t sb = smem_u32(smem);

    int tid = threadIdx.x, lane = tid & 31, wid = tid >> 5;
    int wm = wid >> 2, wn = wid & 3;
    int bh = blockIdx.z;
    int b = bh / HEADS, h = bh % HEADS;
    int m0 = blockIdx.y * 128, n0 = blockIdx.x * 128;

    {
        const __nv_bfloat16* srcs[4] = {qkvh, qkvl, qkvh, qkvl};
        int offs[4] = {h * HD, h * HD, CDIM + h * HD, CDIM + h * HD};
        int r0s[4] = {m0, m0, n0, n0};
        #pragma unroll
        for (int tI = 0; tI < 4; tI++) {
            uint32_t tb = sb + tI * QKTILE;
            #pragma unroll
            for (int t = 0; t < 4; t++) {
                int e = tid + t * 256;
                int rowi = e >> 3, qc = e & 7;
                int gr = r0s[tI] + rowi;
                int ok = (gr < NTOK) ? 16 : 0;
                const __nv_bfloat16* src = srcs[tI] +
                    (size_t)(b * NTOK + (ok ? gr : 0)) * QKVDIM + offs[tI] + qc * 8;
                cp_async16(tb + rowi * QKPAD + qc * 16, src, ok);
            }
        }
    }
    cp_commit();
    cp_wait<0>();
    __syncthreads();

    float acc[4][4][4];
    #pragma unroll
    for (int i = 0; i < 4; i++)
        #pragma unroll
        for (int j = 0; j < 4; j++)
            #pragma unroll
            for (int q = 0; q < 4; q++) acc[i][j][q] = 0.f;

    int ar = lane & 15, ac = lane >> 4;
    int br = lane & 7, bc = (lane >> 3) & 1;
    uint32_t qhB = sb, qlB = sb + QKTILE, khB = sb + 2 * QKTILE, klB = sb + 3 * QKTILE;

    #pragma unroll
    for (int ks = 0; ks < 4; ks++) {
        uint32_t aH[4][4], aL[4][4], bF[4][2];
        int koff = (ks * 16 + ac * 8) * 2;
        int koffb = (ks * 16 + bc * 8) * 2;
        #pragma unroll
        for (int mt = 0; mt < 4; mt++) {
            uint32_t ra = (uint32_t)((wm * 64 + mt * 16 + ar) * QKPAD) + koff;
            ldsm_x4(qhB + ra, aH[mt]);
            ldsm_x4(qlB + ra, aL[mt]);
        }
        #pragma unroll
        for (int nt = 0; nt < 4; nt++) {
            uint32_t rb = (uint32_t)((wn * 32 + nt * 8 + br) * QKPAD) + koffb;
            ldsm_x2(khB + rb, bF[nt]);
        }
        #pragma unroll
        for (int mt = 0; mt < 4; mt++)
            #pragma unroll
            for (int nt = 0; nt < 4; nt++) {
                mma_bf16(acc[mt][nt], aH[mt], bF[nt]);
                mma_bf16(acc[mt][nt], aL[mt], bF[nt]);
            }
        #pragma unroll
        for (int nt = 0; nt < 4; nt++) {
            uint32_t rb = (uint32_t)((wn * 32 + nt * 8 + br) * QKPAD) + koffb;
            ldsm_x2(klB + rb, bF[nt]);
        }
        #pragma unroll
        for (int mt = 0; mt < 4; mt++)
            #pragma unroll
            for (int nt = 0; nt < 4; nt++)
                mma_bf16(acc[mt][nt], aH[mt], bF[nt]);
    }

    int qrow = lane >> 2, qcol = 2 * (lane & 3);
    float* Qbase = QK + (size_t)bh * NTOK * NTOK;
    #pragma unroll
    for (int mt = 0; mt < 4; mt++) {
        #pragma unroll
        for (int half = 0; half < 2; half++) {
            int gm = m0 + wm * 64 + mt * 16 + qrow + half * 8;
            if (gm >= NTOK) continue;
            #pragma unroll
            for (int nt = 0; nt < 4; nt++) {
                int gn = n0 + wn * 32 + nt * 8 + qcol;
                if (gn >= NTOK) continue;
                float2 v;
                v.x = acc[mt][nt][half * 2 + 0];
                v.y = acc[mt][nt][half * 2 + 1];
                *(float2*)(Qbase + (size_t)gm * NTOK + gn) = v;
            }
        }
    }
}

// ---------------------------------------------------------------------------
// attn_post: P from QK dots + riemann + BN affine + 2H->H conv.
// ---------------------------------------------------------------------------
__global__ __launch_bounds__(256)
void attn_post(const float* __restrict__ QK, const float* __restrict__ qq,
               const float* __restrict__ kk, const float* __restrict__ scale_l,
               const float* __restrict__ riem_scale_l, const float* __restrict__ temp_l,
               const float* __restrict__ bn_g_l, const float* __restrict__ bn_b_l,
               const float* __restrict__ conv_w_l, const float* __restrict__ conv_b_l,
               float* __restrict__ P) {
    __shared__ float s_qk[HEADS * NTOK];
    __shared__ float s_kk[HEADS * NTOK];
    __shared__ float s_qq[HEADS];
    __shared__ float cw[288], mch[24], bch[24], cb[12];

    int i = blockIdx.x, b = blockIdx.y;
    int tid = threadIdx.x;

    for (int idx = tid; idx < HEADS * NTOK; idx += 256) {
        int h = idx / NTOK, j = idx - h * NTOK;
        s_qk[idx] = QK[(((size_t)b * HEADS + h) * NTOK + i) * NTOK + j];
        s_kk[idx] = kk[((size_t)b * HEADS + h) * NTOK + j];
    }
    if (tid < HEADS) {
        s_qq[tid] = qq[((size_t)b * HEADS + tid) * NTOK + i];
        cb[tid] = conv_b_l[tid];
    }
    for (int idx = tid; idx < 288; idx += 256) cw[idx] = conv_w_l[idx];
    if (tid < 24) {
        mch[tid] = temp_l[tid] * BN_RSTD * bn_g_l[tid];
        bch[tid] = bn_b_l[tid];
    }
    __syncthreads();
    if (tid >= NTOK) return;

    float scale = scale_l[0], riem = riem_scale_l[0];
    float a[24];
    #pragma unroll
    for (int h = 0; h < HEADS; h++) {
        float qk = s_qk[h * NTOK + tid];
        a[h] = qk * scale;
        float qv = s_qq[h];
        float kv = s_kk[h * NTOK + tid];
        float d2 = qv * qv + kv * kv - 2.f * qk * qk;
        a[HEADS + h] = sqrtf(fmaxf(d2, 0.f) + 1e-12f) * riem;
    }
    #pragma unroll
    for (int c = 0; c < 24; c++) a[c] = a[c] * mch[c] + bch[c];
    #pragma unroll
    for (int hh = 0; hh < HEADS; hh++) {
        float o = cb[hh];
        #pragma unroll
        for (int c = 0; c < 24; c++) o += cw[hh * 24 + c] * a[c];
        P[(((size_t)b * HEADS + hh) * NTOK + i) * NTOK + tid] = o;
    }
}

// ---------------------------------------------------------------------------
// av_mma: softmax(P) @ V on tensor cores (bf16x3).
// Block = (i-tile of 128, bh). Softmax stats read from gmem; P converted to
// bf16 hi/lo in smem; V hi/lo tiles from qkv bf16; mma with ldmatrix.trans B.
// ---------------------------------------------------------------------------
#define AV_PSTR 464                   // bytes per P smem row (224 bf16 + pad)
#define AV_VSTR 144                   // bytes per V smem row (64 bf16 + pad)
#define AV_PH 0
#define AV_PL (128 * AV_PSTR)         // 59392
#define AV_VH (2 * 128 * AV_PSTR)     // 118784
#define AV_VL (AV_VH + 224 * AV_VSTR) // 151040
#define AV_RMX (AV_VL + 224 * AV_VSTR)  // 183296
#define AV_RINV (AV_RMX + 512)
#define AV_SMEM (AV_RINV + 512)       // 184320

__global__ __launch_bounds__(256, 1)
void av_mma_kernel(const float* __restrict__ P,
                   const __nv_bfloat16* __restrict__ qkvh,
                   const __nv_bfloat16* __restrict__ qkvl,
                   __nv_bfloat16* __restrict__ oh, __nv_bfloat16* __restrict__ ol) {
    extern __shared__ char smem[];
    uint32_t sb = smem_u32(smem);
    float* rmxp = (float*)(smem + AV_RMX);
    float* rinvp = (float*)(smem + AV_RINV);

    int tid = threadIdx.x, lane = tid & 31, wid = tid >> 5;
    int wm = wid >> 2, wn = wid & 3;       // 2 x 4 warps; warp tile 64(i) x 16(d)
    int bh = blockIdx.y;
    int b = bh / HEADS, h = bh % HEADS;
    int i0 = blockIdx.x * 128;

    // V tiles (hi/lo), rows j=0..223 zero-padded past NTOK
    #pragma unroll
    for (int t = 0; t < 7; t++) {
        int e = tid + t * 256;             // 0..1791 = 224 rows x 8 chunks
        int row = e >> 3, qc = e & 7;
        int ok = (row < NTOK) ? 16 : 0;
        size_t goff = (size_t)(b * NTOK + (ok ? row : 0)) * QKVDIM + 2 * CDIM + h * HD + qc * 8;
        cp_async16(sb + AV_VH + row * AV_VSTR + qc * 16, qkvh + goff, ok);
        cp_async16(sb + AV_VL + row * AV_VSTR + qc * 16, qkvl + goff, ok);
    }
    cp_commit();

    // Row softmax stats (read P from gmem; 16 rows per warp)
    for (int rr = wid; rr < 128; rr += 8) {
        int gi = i0 + rr;
        float mx = 0.f, inv = 0.f;
        if (gi < NTOK) {
            const float* prow = P + ((size_t)bh * NTOK + gi) * NTOK;
            float m = -1e30f;
            for (int c = lane; c < NTOK; c += 32) m = fmaxf(m, prow[c]);
            m = wmax(m);
            float s = 0.f;
            for (int c = lane; c < NTOK; c += 32) s += expf(prow[c] - m);
            s = wsum(s);
            mx = m; inv = 1.f / s;
        }
        if (lane == 0) { rmxp[rr] = mx; rinvp[rr] = inv; }
    }
    __syncthreads();

    // Fill P bf16 hi/lo smem (zero-padded)
    for (int idx = tid; idx < 128 * 224; idx += 256) {
        int row = idx / 224, col = idx - row * 224;
        int gi = i0 + row;
        float val = 0.f;
        if (gi < NTOK && col < NTOK)
            val = expf(P[((size_t)bh * NTOK + gi) * NTOK + col] - rmxp[row]) * rinvp[row];
        __nv_bfloat16 hh, ll;
        split_bf(val, hh, ll);
        *(__nv_bfloat16*)(smem + AV_PH + row * AV_PSTR + col * 2) = hh;
        *(__nv_bfloat16*)(smem + AV_PL + row * AV_PSTR + col * 2) = ll;
    }
    cp_wait<0>();
    __syncthreads();

    // MMA: o[128 x 64] = P[128 x 224] @ V[224 x 64]
    float acc[4][2][4];
    #pragma unroll
    for (int i = 0; i < 4; i++)
        #pragma unroll
        for (int j = 0; j < 2; j++)
            #pragma unroll
            for (int q = 0; q < 4; q++) acc[i][j][q] = 0.f;

    int ar = lane & 15, ac = lane >> 4;
    int bl = lane & 15;
    int brow_off = (bl & 7) + 8 * ((bl >> 3) & 1);

    #pragma unroll
    for (int ks = 0; ks < 14; ks++) {
        int k = ks * 16;
        uint32_t aH[4][4], aL[4][4], bH[2][2], bL[2][2];
        int koff = (k + ac * 8) * 2;
        #pragma unroll
        for (int mt = 0; mt < 4; mt++) {
            uint32_t ra = sb + AV_PH + (uint32_t)((wm * 64 + mt * 16 + ar) * AV_PSTR) + koff;
            ldsm_x4(ra, aH[mt]);
            ldsm_x4(ra + (AV_PL - AV_PH), aL[mt]);
        }
        #pragma unroll
        for (int nt = 0; nt < 2; nt++) {
            uint32_t rb = sb + AV_VH + (uint32_t)((k + brow_off) * AV_VSTR)
                          + (wn * 16 + nt * 8) * 2;
            ldsm_x2_trans(rb, bH[nt]);
            ldsm_x2_trans(rb + (AV_VL - AV_VH), bL[nt]);
        }
        #pragma unroll
        for (int mt = 0; mt < 4; mt++)
            #pragma unroll
            for (int nt = 0; nt < 2; nt++) {
                mma_bf16(acc[mt][nt], aH[mt], bH[nt]);
                mma_bf16(acc[mt][nt], aH[mt], bL[nt]);
                mma_bf16(acc[mt][nt], aL[mt], bH[nt]);
            }
    }

    // Epilogue: split to bf16 hi/lo, store
    int qrow = lane >> 2, qcol = 2 * (lane & 3);
    #pragma unroll
    for (int mt = 0; mt < 4; mt++) {
        #pragma unroll
        for (int half = 0; half < 2; half++) {
            int gi = i0 + wm * 64 + mt * 16 + qrow + half * 8;
            if (gi >= NTOK) continue;
            #pragma unroll
            for (int nt = 0; nt < 2; nt++) {
                int d = wn * 16 + nt * 8 + qcol;
                size_t idx = ((size_t)(b * NTOK) + gi) * CDIM + h * HD + d;
                __nv_bfloat16 hh, ll;
                split_bf(acc[mt][nt][half * 2 + 0], hh, ll);
                oh[idx] = hh; ol[idx] = ll;
                split_bf(acc[mt][nt][half * 2 + 1], hh, ll);
                oh[idx + 1] = hh; ol[idx + 1] = ll;
            }
        }
    }
}

// ---------------------------------------------------------------------------
// seq_pool
// ---------------------------------------------------------------------------
__global__ void pool_kernel(const float* __restrict__ x, const float* __restrict__ pw,
                            const float* __restrict__ pb, float* __restrict__ pooled) {
    int b = blockIdx.x;
    __shared__ float s[NTOK];
    __shared__ float red[32];
    int tid = threadIdx.x, lane = tid & 31, w = tid >> 5;

    for (int n = w; n < NTOK; n += 8) {
        const float* xp = x + ((size_t)b * NTOK + n) * CDIM;
        float acc = 0.f;
        for (int c = lane; c < CDIM; c += 32) acc += xp[c] * pw[c];
        acc = wsum(acc);
        if (lane == 0) s[n] = acc + pb[0];
    }
    __syncthreads();

    float mx = -1e30f;
    for (int n = tid; n < NTOK; n += 256) mx = fmaxf(mx, s[n]);
    mx = wmax(mx);
    if (lane == 0) red[w] = mx;
    __syncthreads();
    if (tid == 0) { float m = red[0]; for (int q = 1; q < 8; q++) m = fmaxf(m, red[q]); red[16] = m; }
    __syncthreads();
    mx = red[16];

    float ps = 0.f;
    for (int n = tid; n < NTOK; n += 256) { float e = expf(s[n] - mx); s[n] = e; ps += e; }
    ps = wsum(ps);
    if (lane == 0) red[w] = ps;
    __syncthreads();
    if (tid == 0) { float t = 0; for (int q = 0; q < 8; q++) t += red[q]; red[17] = 1.f / t; }
    __syncthreads();
    float inv = red[17];

    for (int c = tid; c < CDIM; c += 256) {
        float acc = 0.f;
        for (int n = 0; n < NTOK; n++)
            acc += s[n] * x[((size_t)b * NTOK + n) * CDIM + c];
        pooled[b * CDIM + c] = acc * inv;
    }
}

// ---------------------------------------------------------------------------
// fc
// ---------------------------------------------------------------------------
__global__ void fc_kernel(const float* __restrict__ pooled, const float* __restrict__ fw,
                          const float* __restrict__ fb, float* __restrict__ out) {
    int gw = (blockIdx.x * blockDim.x + threadIdx.x) >> 5;
    int lane = threadIdx.x & 31;
    if (gw >= BATCH * NCLS) return;
    int b = gw / NCLS, o = gw % NCLS;
    const float* pp = pooled + b * CDIM;
    const float* wp = fw + (size_t)o * CDIM;
    float acc = 0.f;
    for (int c = lane; c < CDIM; c += 32) acc += pp[c] * wp[c];
    acc = wsum(acc);
    if (lane == 0) out[gw] = acc + fb[o];
}

// ---------------------------------------------------------------------------
// Launch
// ---------------------------------------------------------------------------
extern "C" void kernel_launch(void* const* d_in, const int* in_sizes, int n_in,
                              void* d_out, int out_size) {
    const float* x_in      = (const float*)d_in[0];
    const float* pos_emb   = (const float*)d_in[1];
    const float* ln0_g     = (const float*)d_in[2];
    const float* ln0_b     = (const float*)d_in[3];
    const float* qkv_w     = (const float*)d_in[4];
    const float* qkv_b     = (const float*)d_in[5];
    const float* qkvln_g   = (const float*)d_in[6];
    const float* qkvln_b   = (const float*)d_in[7];
    const float* scale     = (const float*)d_in[8];
    const float* riem_sc   = (const float*)d_in[9];
    const float* temp      = (const float*)d_in[10];
    const float* bn_g      = (const float*)d_in[11];
    const float* bn_b      = (const float*)d_in[12];
    const float* conv_w    = (const float*)d_in[13];
    const float* conv_b    = (const float*)d_in[14];
    const float* proj_w    = (const float*)d_in[15];
    const float* proj_b    = (const float*)d_in[16];
    const float* ln1_g     = (const float*)d_in[17];
    const float* ln1_b     = (const float*)d_in[18];
    const float* ff1_w     = (const float*)d_in[19];
    const float* ff1_b     = (const float*)d_in[20];
    const float* ff2_w     = (const float*)d_in[21];
    const float* ff2_b     = (const float*)d_in[22];
    const float* norm_g    = (const float*)d_in[23];
    const float* norm_b    = (const float*)d_in[24];
    const float* pool_w    = (const float*)d_in[25];
    const float* pool_b    = (const float*)d_in[26];
    const float* fc_w      = (const float*)d_in[27];
    const float* fc_b      = (const float*)d_in[28];

    float* S = nullptr;
    cudaGetSymbolAddress((void**)&S, g_scratch);
    __nv_bfloat16* BF = nullptr;
    cudaGetSymbolAddress((void**)&BF, g_bf);

    float* gx      = S + OFF_X;
    float* gqkv    = S + OFF_QKV;
    float* gqq     = S + OFF_QQ;
    float* gkk     = S + OFF_KK;
    float* gP      = S + OFF_P;
    float* gQK     = S + OFF_QK;
    float* gpooled = S + OFF_POOLED;

    __nv_bfloat16* wqkv_h  = BF + BO_WQKV_HI,  *wqkv_l  = BF + BO_WQKV_LO;
    __nv_bfloat16* wproj_h = BF + BO_WPROJ_HI, *wproj_l = BF + BO_WPROJ_LO;
    __nv_bfloat16* wff1_h  = BF + BO_WFF1_HI,  *wff1_l  = BF + BO_WFF1_LO;
    __nv_bfloat16* wff2_h  = BF + BO_WFF2_HI,  *wff2_l  = BF + BO_WFF2_LO;
    __nv_bfloat16* h_h = BF + BO_H_HI, *h_l = BF + BO_H_LO;
    __nv_bfloat16* o_h = BF + BO_O_HI, *o_l = BF + BO_O_LO;
    __nv_bfloat16* x_h = BF + BO_X_HI, *x_l = BF + BO_X_LO;
    __nv_bfloat16* f_h = BF + BO_F_HI, *f_l = BF + BO_F_LO;
    __nv_bfloat16* qkv_hh = BF + BO_QKV_HI, *qkv_ll = BF + BO_QKV_LO;

    cudaFuncSetAttribute(gemm_mma<0>, cudaFuncAttributeMaxDynamicSharedMemorySize, GSMEM);
    cudaFuncSetAttribute(gemm_mma<1>, cudaFuncAttributeMaxDynamicSharedMemorySize, GSMEM);
    cudaFuncSetAttribute(gemm_mma<2>, cudaFuncAttributeMaxDynamicSharedMemorySize, GSMEM);
    cudaFuncSetAttribute(qk_mma, cudaFuncAttributeMaxDynamicSharedMemorySize, QKSMEM);
    cudaFuncSetAttribute(av_mma_kernel, cudaFuncAttributeMaxDynamicSharedMemorySize, AV_SMEM);

    cvt_hilo_kernel<<<2048, 256>>>((const float4*)qkv_w,  (__nv_bfloat162*)wqkv_h,
                                   (__nv_bfloat162*)wqkv_l,  NB_WQKV / 4);
    cvt_hilo_kernel<<<2048, 256>>>((const float4*)proj_w, (__nv_bfloat162*)wproj_h,
                                   (__nv_bfloat162*)wproj_l, NB_WPROJ / 4);
    cvt_hilo_kernel<<<2048, 256>>>((const float4*)ff1_w,  (__nv_bfloat162*)wff1_h,
                                   (__nv_bfloat162*)wff1_l,  NB_WFF1 / 4);
    cvt_hilo_kernel<<<2048, 256>>>((const float4*)ff2_w,  (__nv_bfloat162*)wff2_h,
                                   (__nv_bfloat162*)wff2_l,  NB_WFF2 / 4);

    addpos_kernel<<<(TOKENS * CDIM + 255) / 256, 256>>>(x_in, pos_emb, gx);

    const int MB = (TOKENS + 127) / 128;  // 25
    for (int l = 0; l < LAYERS; l++) {
        // h = LN0(x) -> bf16 hi/lo
        ln_kernel<1><<<TOKENS, 256, CDIM * sizeof(float)>>>(
            gx, nullptr, h_h, h_l, ln0_g + l * CDIM, ln0_b + l * CDIM, CDIM);
        // qkv = h @ qkv_w^T + b
        gemm_mma<0><<<dim3(QKVDIM / 128, MB), 256, GSMEM>>>(
            h_h, h_l, wqkv_h + (size_t)l * QKVDIM * CDIM, wqkv_l + (size_t)l * QKVDIM * CDIM,
            qkv_b + l * QKVDIM, gqkv, nullptr, nullptr, TOKENS, QKVDIM, CDIM);
        // qkv = LN(qkv) in place + bf16 hi/lo + per-head q/k norms
        ln_qkv_kernel<<<TOKENS, 256>>>(gqkv, qkvln_g + l * QKVDIM,
                                       qkvln_b + l * QKVDIM, qkv_hh, qkv_ll, gqq, gkk);
        // QK dots via tensor cores
        qk_mma<<<dim3(2, 2, BATCH * HEADS), 256, QKSMEM>>>(qkv_hh, qkv_ll, gQK);
        // riem + BN affine + conv -> P
        attn_post<<<dim3(NTOK, BATCH), 256>>>(
            gQK, gqq, gkk, scale + l, riem_sc + l, temp + l * 24,
            bn_g + l * 24, bn_b + l * 24, conv_w + l * 288, conv_b + l * 12, gP);
        // softmax + (P @ v) via tensor cores -> bf16 hi/lo
        av_mma_kernel<<<dim3(2, BATCH * HEADS), 256, AV_SMEM>>>(
            gP, qkv_hh, qkv_ll, o_h, o_l);
        // x = x + o @ proj_w^T + proj_b
        gemm_mma<1><<<dim3(CDIM / 128, MB), 256, GSMEM>>>(
            o_h, o_l, wproj_h + (size_t)l * CDIM * CDIM, wproj_l + (size_t)l * CDIM * CDIM,
            proj_b + l * CDIM, gx, nullptr, nullptr, TOKENS, CDIM, CDIM);
        // x = LN1(x) in-place + bf16 hi/lo
        ln_kernel<2><<<TOKENS, 256, CDIM * sizeof(float)>>>(
            gx, gx, x_h, x_l, ln1_g + l * CDIM, ln1_b + l * CDIM, CDIM);
        // f = gelu(x @ ff1^T + b) -> bf16 hi/lo
        gemm_mma<2><<<dim3(DFF / 128, MB), 256, GSMEM>>>(
            x_h, x_l, wff1_h + (size_t)l * DFF * CDIM, wff1_l + (size_t)l * DFF * CDIM,
            ff1_b + l * DFF, nullptr, f_h, f_l, TOKENS, DFF, CDIM);
        // x = x + f @ ff2^T + b
        gemm_mma<1><<<dim3(CDIM / 128, MB), 256, GSMEM>>>(
            f_h, f_l, wff2_h + (size_t)l * CDIM * DFF, wff2_l + (size_t)l * CDIM * DFF,
            ff2_b + l * CDIM, gx, nullptr, nullptr, TOKENS, CDIM, DFF);
    }

    ln_kernel<0><<<TOKENS, 256, CDIM * sizeof(float)>>>(
        gx, gx, nullptr, nullptr, norm_g, norm_b, CDIM);
    pool_kernel<<<BATCH, 256>>>(gx, pool_w, pool_b, gpooled);
    fc_kernel<<<(BATCH * NCLS * 32 + 255) / 256, 256>>>(gpooled, fc_w, fc_b,
                                                        (float*)d_out);
}

// round 14
// speedup vs baseline: 1.0014x; 1.0014x over previous
#include <cuda_runtime.h>
#include <cuda_bf16.h>
#include <math.h>
#include <stdint.h>

// ---------------------------------------------------------------------------
// Problem constants
// ---------------------------------------------------------------------------
#define LAYERS 12
#define CDIM   768
#define HEADS  12
#define HD     64
#define NTOK   196
#define BATCH  16
#define DFF    3072
#define NCLS   1000
#define TOKENS (BATCH * NTOK)        // 3136
#define QKVDIM (3 * CDIM)            // 2304
#define NROWS_ATT (BATCH * HEADS * NTOK) // 37632
#define BN_RSTD 0.99999500003749969f

// ---------------------------------------------------------------------------
// fp32 scratch
// ---------------------------------------------------------------------------
#define OFF_X      0
#define OFF_QKV    (OFF_X + (size_t)TOKENS * CDIM)
#define OFF_QQ     (OFF_QKV + (size_t)TOKENS * QKVDIM)
#define OFF_KK     (OFF_QQ + NROWS_ATT)
#define OFF_P      (OFF_KK + NROWS_ATT)
#define OFF_QK     (OFF_P + (size_t)BATCH * HEADS * NTOK * NTOK)
#define OFF_POOLED (OFF_QK + (size_t)BATCH * HEADS * NTOK * NTOK)
#define SCRATCH_TOTAL (OFF_POOLED + BATCH * CDIM)

__device__ __align__(256) float g_scratch[SCRATCH_TOTAL];

// ---------------------------------------------------------------------------
// bf16 scratch
// ---------------------------------------------------------------------------
#define NB_WQKV  ((size_t)LAYERS * QKVDIM * CDIM)
#define NB_WPROJ ((size_t)LAYERS * CDIM * CDIM)
#define NB_WFF1  ((size_t)LAYERS * DFF * CDIM)
#define NB_WFF2  ((size_t)LAYERS * CDIM * DFF)
#define NB_ACT   ((size_t)TOKENS * CDIM)
#define NB_F     ((size_t)TOKENS * DFF)
#define NB_QKVA  ((size_t)TOKENS * QKVDIM)

#define BO_WQKV_HI  ((size_t)0)
#define BO_WQKV_LO  (BO_WQKV_HI + NB_WQKV)
#define BO_WPROJ_HI (BO_WQKV_LO + NB_WQKV)
#define BO_WPROJ_LO (BO_WPROJ_HI + NB_WPROJ)
#define BO_WFF1_HI  (BO_WPROJ_LO + NB_WPROJ)
#define BO_WFF1_LO  (BO_WFF1_HI + NB_WFF1)
#define BO_WFF2_HI  (BO_WFF1_LO + NB_WFF1)
#define BO_WFF2_LO  (BO_WFF2_HI + NB_WFF2)
#define BO_H_HI     (BO_WFF2_LO + NB_WFF2)
#define BO_H_LO     (BO_H_HI + NB_ACT)
#define BO_O_HI     (BO_H_LO + NB_ACT)
#define BO_O_LO     (BO_O_HI + NB_ACT)
#define BO_X_HI     (BO_O_LO + NB_ACT)
#define BO_X_LO     (BO_X_HI + NB_ACT)
#define BO_F_HI     (BO_X_LO + NB_ACT)
#define BO_F_LO     (BO_F_HI + NB_F)
#define BO_QKV_HI   (BO_F_LO + NB_F)
#define BO_QKV_LO   (BO_QKV_HI + NB_QKVA)
#define BF_TOTAL    (BO_QKV_LO + NB_QKVA)

__device__ __align__(256) __nv_bfloat16 g_bf[BF_TOTAL];

// ---------------------------------------------------------------------------
// helpers
// ---------------------------------------------------------------------------
__device__ __forceinline__ uint32_t smem_u32(const void* p) {
    uint32_t a;
    asm("{ .reg .u64 t; cvta.to.shared.u64 t, %1; cvt.u32.u64 %0, t; }"
        : "=r"(a) : "l"(p));
    return a;
}
__device__ __forceinline__ float wsum(float v) {
    #pragma unroll
    for (int o = 16; o; o >>= 1) v += __shfl_xor_sync(0xffffffffu, v, o);
    return v;
}
__device__ __forceinline__ float wmax(float v) {
    #pragma unroll
    for (int o = 16; o; o >>= 1) v = fmaxf(v, __shfl_xor_sync(0xffffffffu, v, o));
    return v;
}
__device__ __forceinline__ void split_bf(float v, __nv_bfloat16& h, __nv_bfloat16& l) {
    h = __float2bfloat16(v);
    l = __float2bfloat16(v - __bfloat162float(h));
}
__device__ __forceinline__ void cp_async16(uint32_t dst, const void* src, int srcsize) {
    asm volatile("cp.async.cg.shared.global [%0], [%1], 16, %2;"
                 :: "r"(dst), "l"(src), "r"(srcsize) : "memory");
}
__device__ __forceinline__ void cp_commit() {
    asm volatile("cp.async.commit_group;" ::: "memory");
}
template <int N>
__device__ __forceinline__ void cp_wait() {
    asm volatile("cp.async.wait_group %0;" :: "n"(N) : "memory");
}
__device__ __forceinline__ void ldsm_x4(uint32_t addr, uint32_t* r) {
    asm volatile("ldmatrix.sync.aligned.m8n8.x4.shared.b16 {%0,%1,%2,%3}, [%4];"
        : "=r"(r[0]), "=r"(r[1]), "=r"(r[2]), "=r"(r[3]) : "r"(addr));
}
__device__ __forceinline__ void ldsm_x2(uint32_t addr, uint32_t* r) {
    asm volatile("ldmatrix.sync.aligned.m8n8.x2.shared.b16 {%0,%1}, [%2];"
        : "=r"(r[0]), "=r"(r[1]) : "r"(addr));
}
__device__ __forceinline__ void ldsm_x2_trans(uint32_t addr, uint32_t* r) {
    asm volatile("ldmatrix.sync.aligned.m8n8.x2.trans.shared.b16 {%0,%1}, [%2];"
        : "=r"(r[0]), "=r"(r[1]) : "r"(addr));
}
__device__ __forceinline__ void mma_bf16(float* d, const uint32_t* a, const uint32_t* b) {
    asm volatile("mma.sync.aligned.m16n8k16.row.col.f32.bf16.bf16.f32 "
        "{%0,%1,%2,%3}, {%4,%5,%6,%7}, {%8,%9}, {%0,%1,%2,%3};"
        : "+f"(d[0]), "+f"(d[1]), "+f"(d[2]), "+f"(d[3])
        : "r"(a[0]), "r"(a[1]), "r"(a[2]), "r"(a[3]), "r"(b[0]), "r"(b[1]));
}

// ---------------------------------------------------------------------------
// fp32 -> bf16 hi/lo conversion (vectorized)
// ---------------------------------------------------------------------------
__global__ void cvt_hilo_kernel(const float4* __restrict__ w,
                                __nv_bfloat162* __restrict__ hi,
                                __nv_bfloat162* __restrict__ lo, size_t n4) {
    size_t i = (size_t)blockIdx.x * blockDim.x + threadIdx.x;
    size_t stride = (size_t)gridDim.x * blockDim.x;
    for (; i < n4; i += stride) {
        float4 v = w[i];
        __nv_bfloat16 h0, l0, h1, l1, h2, l2, h3, l3;
        split_bf(v.x, h0, l0); split_bf(v.y, h1, l1);
        split_bf(v.z, h2, l2); split_bf(v.w, h3, l3);
        __nv_bfloat162 a, b;
        a.x = h0; a.y = h1; b.x = h2; b.y = h3;
        hi[2 * i] = a; hi[2 * i + 1] = b;
        a.x = l0; a.y = l1; b.x = l2; b.y = l3;
        lo[2 * i] = a; lo[2 * i + 1] = b;
    }
}

// ---------------------------------------------------------------------------
// x = x_in + pos_emb
// ---------------------------------------------------------------------------
__global__ void addpos_kernel(const float* __restrict__ x,
                              const float* __restrict__ pe,
                              float* __restrict__ gx) {
    int idx = blockIdx.x * blockDim.x + threadIdx.x;
    if (idx >= TOKENS * CDIM) return;
    int c = idx % CDIM;
    int n = (idx / CDIM) % NTOK;
    gx[idx] = x[idx] + pe[n * CDIM + c];
}

// ---------------------------------------------------------------------------
// LayerNorm. MODE 0: fp32 out. MODE 1: bf16 hi/lo out. MODE 2: both.
// ---------------------------------------------------------------------------
template <int MODE>
__global__ void ln_kernel(const float* __restrict__ in, float* __restrict__ outf,
                          __nv_bfloat16* __restrict__ oh, __nv_bfloat16* __restrict__ ol,
                          const float* __restrict__ g, const float* __restrict__ b,
                          int D) {
    extern __shared__ float row[];
    __shared__ float red[34];
    int r = blockIdx.x;
    const float* ip = in + (size_t)r * D;
    int tid = threadIdx.x, lane = tid & 31, w = tid >> 5;

    float s = 0.f;
    for (int c = tid; c < D; c += blockDim.x) { float v = ip[c]; row[c] = v; s += v; }
    s = wsum(s);
    if (lane == 0) red[w] = s;
    __syncthreads();
    if (tid == 0) { float t = 0; for (int q = 0; q < 8; q++) t += red[q]; red[32] = t / D; }
    __syncthreads();
    float mean = red[32];

    float vs = 0.f;
    for (int c = tid; c < D; c += blockDim.x) { float d = row[c] - mean; vs += d * d; }
    vs = wsum(vs);
    if (lane == 0) red[w] = vs;
    __syncthreads();
    if (tid == 0) { float t = 0; for (int q = 0; q < 8; q++) t += red[q]; red[33] = rsqrtf(t / D + 1e-5f); }
    __syncthreads();
    float rstd = red[33];

    for (int c = tid; c < D; c += blockDim.x) {
        float v = (row[c] - mean) * rstd * g[c] + b[c];
        size_t idx = (size_t)r * D + c;
        if (MODE == 0 || MODE == 2) outf[idx] = v;
        if (MODE == 1 || MODE == 2) {
            __nv_bfloat16 h, l;
            split_bf(v, h, l);
            oh[idx] = h; ol[idx] = l;
        }
    }
}

// ---------------------------------------------------------------------------
// Fused qkv LayerNorm (D=2304, in place) + bf16 hi/lo copy + per-head norms.
// ---------------------------------------------------------------------------
__global__ void ln_qkv_kernel(float* __restrict__ qkvbuf,
                              const float* __restrict__ g, const float* __restrict__ b,
                              __nv_bfloat16* __restrict__ oh, __nv_bfloat16* __restrict__ ol,
                              float* __restrict__ qq, float* __restrict__ kk) {
    __shared__ float row[QKVDIM];
    __shared__ float red[34];
    int r = blockIdx.x;
    float* ip = qkvbuf + (size_t)r * QKVDIM;
    int tid = threadIdx.x, lane = tid & 31, w = tid >> 5;

    float s = 0.f;
    for (int c = tid; c < QKVDIM; c += 256) { float v = ip[c]; row[c] = v; s += v; }
    s = wsum(s);
    if (lane == 0) red[w] = s;
    __syncthreads();
    if (tid == 0) { float t = 0; for (int q = 0; q < 8; q++) t += red[q]; red[32] = t / QKVDIM; }
    __syncthreads();
    float mean = red[32];

    float vs = 0.f;
    for (int c = tid; c < QKVDIM; c += 256) { float d = row[c] - mean; vs += d * d; }
    vs = wsum(vs);
    if (lane == 0) red[w] = vs;
    __syncthreads();
    if (tid == 0) { float t = 0; for (int q = 0; q < 8; q++) t += red[q]; red[33] = rsqrtf(t / QKVDIM + 1e-5f); }
    __syncthreads();
    float rstd = red[33];

    for (int c = tid; c < QKVDIM; c += 256) {
        float v = (row[c] - mean) * rstd * g[c] + b[c];
        row[c] = v;
        ip[c] = v;
        size_t idx = (size_t)r * QKVDIM + c;
        __nv_bfloat16 h, l;
        split_bf(v, h, l);
        oh[idx] = h; ol[idx] = l;
    }
    __syncthreads();

    int bb = r / NTOK, n = r % NTOK;
    for (int seg = w; seg < 24; seg += 8) {
        int base = seg * 64;
        float v0 = row[base + lane], v1 = row[base + lane + 32];
        float ssum = wsum(v0 * v0 + v1 * v1);
        if (lane == 0) {
            int h = seg % 12;
            float* dst = (seg < 12) ? qq : kk;
            dst[((size_t)bb * HEADS + h) * NTOK + n] = ssum;
        }
    }
}

// ---------------------------------------------------------------------------
// mma.sync bf16x3 GEMM (3-stage cp.async ring)
// ---------------------------------------------------------------------------
#define APAD 40
#define TILE_BYTES (128 * APAD * 2)
#define STAGE_BYTES (4 * TILE_BYTES)
#define NSTAGE 3
#define GSMEM (NSTAGE * STAGE_BYTES)

__device__ __forceinline__ void load_stage(
    uint32_t sbase, const __nv_bfloat16* __restrict__ Ah,
    const __nv_bfloat16* __restrict__ Al, const __nv_bfloat16* __restrict__ Bh,
    const __nv_bfloat16* __restrict__ Bl, int m0, int n0, int M, int K, int kc,
    int tid) {
    const __nv_bfloat16* gsrc[4] = {Ah, Al, Bh, Bl};
    #pragma unroll
    for (int tI = 0; tI < 4; tI++) {
        bool isA = tI < 2;
        int row0 = isA ? m0 : n0;
        uint32_t tb = sbase + tI * TILE_BYTES;
        #pragma unroll
        for (int c = 0; c < 2; c++) {
            int e = tid + c * 256;
            int rowi = e >> 2, qc = e & 3;
            int gr = row0 + rowi;
            int ok = (!isA || gr < M) ? 16 : 0;
            const __nv_bfloat16* src =
                gsrc[tI] + (size_t)(ok ? gr : row0) * K + kc + qc * 8;
            cp_async16(tb + rowi * 80 + qc * 16, src, ok);
        }
    }
}

template <int EPI>
__global__ __launch_bounds__(256, 1)
void gemm_mma(const __nv_bfloat16* __restrict__ Ah, const __nv_bfloat16* __restrict__ Al,
              const __nv_bfloat16* __restrict__ Bh, const __nv_bfloat16* __restrict__ Bl,
              const float* __restrict__ bias, float* __restrict__ Cf,
              __nv_bfloat16* __restrict__ Ch, __nv_bfloat16* __restrict__ Cl,
              int M, int N, int K) {
    extern __shared__ char smem[];
    uint32_t sb = smem_u32(smem);

    int tid = threadIdx.x, lane = tid & 31, wid = tid >> 5;
    int wm = wid >> 2, wn = wid & 3;
    int m0 = blockIdx.y * 128, n0 = blockIdx.x * 128;
    int NIT = K >> 5;

    float acc[4][4][4];
    #pragma unroll
    for (int i = 0; i < 4; i++)
        #pragma unroll
        for (int j = 0; j < 4; j++)
            #pragma unroll
            for (int q = 0; q < 4; q++) acc[i][j][q] = 0.f;

    int ar = lane & 15, ac = lane >> 4;
    int br = lane & 7, bc = (lane >> 3) & 1;

    load_stage(sb, Ah, Al, Bh, Bl, m0, n0, M, K, 0, tid);
    cp_commit();
    load_stage(sb + STAGE_BYTES, Ah, Al, Bh, Bl, m0, n0, M, K, 32, tid);
    cp_commit();

    int bufidx = 0;
    for (int it = 0; it < NIT; it++) {
        uint32_t buf = sb + (uint32_t)bufidx * STAGE_BYTES;
        if (it + 2 < NIT) {
            int li = (bufidx + 2) % NSTAGE;
            load_stage(sb + (uint32_t)li * STAGE_BYTES,
                       Ah, Al, Bh, Bl, m0, n0, M, K, (it + 2) * 32, tid);
            cp_commit();
            cp_wait<2>();
        } else if (it + 2 == NIT) {
            cp_wait<1>();
        } else {
            cp_wait<0>();
        }
        __syncthreads();

        uint32_t AhB = buf, AlB = buf + TILE_BYTES;
        uint32_t BhB = buf + 2 * TILE_BYTES, BlB = buf + 3 * TILE_BYTES;

        #pragma unroll
        for (int ks = 0; ks < 2; ks++) {
            uint32_t aH[4][4], aL[4][4], bF[4][2];
            int koff = (ks * 16 + ac * 8) * 2;
            int koffb = (ks * 16 + bc * 8) * 2;
            #pragma unroll
            for (int mt = 0; mt < 4; mt++) {
                uint32_t ra = (uint32_t)((wm * 64 + mt * 16 + ar) * 80) + koff;
                ldsm_x4(AhB + ra, aH[mt]);
                ldsm_x4(AlB + ra, aL[mt]);
            }
            #pragma unroll
            for (int nt = 0; nt < 4; nt++) {
                uint32_t rb = (uint32_t)((wn * 32 + nt * 8 + br) * 80) + koffb;
                ldsm_x2(BhB + rb, bF[nt]);
            }
            #pragma unroll
            for (int mt = 0; mt < 4; mt++)
                #pragma unroll
                for (int nt = 0; nt < 4; nt++) {
                    mma_bf16(acc[mt][nt], aH[mt], bF[nt]);
                    mma_bf16(acc[mt][nt], aL[mt], bF[nt]);
                }
            #pragma unroll
            for (int nt = 0; nt < 4; nt++) {
                uint32_t rb = (uint32_t)((wn * 32 + nt * 8 + br) * 80) + koffb;
                ldsm_x2(BlB + rb, bF[nt]);
            }
            #pragma unroll
            for (int mt = 0; mt < 4; mt++)
                #pragma unroll
                for (int nt = 0; nt < 4; nt++)
                    mma_bf16(acc[mt][nt], aH[mt], bF[nt]);
        }
        __syncthreads();
        bufidx = (bufidx + 1) % NSTAGE;
    }

    int qrow = lane >> 2, qcol = 2 * (lane & 3);
    #pragma unroll
    for (int mt = 0; mt < 4; mt++) {
        #pragma unroll
        for (int half = 0; half < 2; half++) {
            int gm = m0 + wm * 64 + mt * 16 + qrow + half * 8;
            if (gm >= M) continue;
            #pragma unroll
            for (int nt = 0; nt < 4; nt++) {
                int gn = n0 + wn * 32 + nt * 8 + qcol;
                float v0 = acc[mt][nt][half * 2 + 0] + bias[gn + 0];
                float v1 = acc[mt][nt][half * 2 + 1] + bias[gn + 1];
                size_t o = (size_t)gm * N + gn;
                if (EPI == 1) { v0 += Cf[o]; v1 += Cf[o + 1]; }
                if (EPI == 2) {
                    v0 = 0.5f * v0 * (1.f + erff(v0 * 0.70710678118654752f));
                    v1 = 0.5f * v1 * (1.f + erff(v1 * 0.70710678118654752f));
                    __nv_bfloat16 h, l;
                    split_bf(v0, h, l); Ch[o] = h;     Cl[o] = l;
                    split_bf(v1, h, l); Ch[o + 1] = h; Cl[o + 1] = l;
                } else {
                    Cf[o] = v0; Cf[o + 1] = v1;
                }
            }
        }
    }
}

// ---------------------------------------------------------------------------
// qk_mma: QK[b,h,i,j] = q_bh[i,:64] . k_bh[j,:64] via bf16x3 mma.
// ---------------------------------------------------------------------------
#define QKPAD 144
#define QKTILE (128 * QKPAD)
#define QKSMEM (4 * QKTILE)

__global__ __launch_bounds__(256, 1)
void qk_mma(const __nv_bfloat16* __restrict__ qkvh,
            const __nv_bfloat16* __restrict__ qkvl,
            float* __restrict__ QK) {
    extern __shared__ char smem[];
    uint32_t sb = smem_u32(smem);

    int tid = threadIdx.x, lane = tid & 31, wid = tid >> 5;
    int wm = wid >> 2, wn = wid & 3;
    int bh = blockIdx.z;
    int b = bh / HEADS, h = bh % HEADS;
    int m0 = blockIdx.y * 128, n0 = blockIdx.x * 128;

    {
        const __nv_bfloat16* srcs[4] = {qkvh, qkvl, qkvh, qkvl};
        int offs[4] = {h * HD, h * HD, CDIM + h * HD, CDIM + h * HD};
        int r0s[4] = {m0, m0, n0, n0};
        #pragma unroll
        for (int tI = 0; tI < 4; tI++) {
            uint32_t tb = sb + tI * QKTILE;
            #pragma unroll
            for (int t = 0; t < 4; t++) {
                int e = tid + t * 256;
                int rowi = e >> 3, qc = e & 7;
                int gr = r0s[tI] + rowi;
                int ok = (gr < NTOK) ? 16 : 0;
                const __nv_bfloat16* src = srcs[tI] +
                    (size_t)(b * NTOK + (ok ? gr : 0)) * QKVDIM + offs[tI] + qc * 8;
                cp_async16(tb + rowi * QKPAD + qc * 16, src, ok);
            }
        }
    }
    cp_commit();
    cp_wait<0>();
    __syncthreads();

    float acc[4][4][4];
    #pragma unroll
    for (int i = 0; i < 4; i++)
        #pragma unroll
        for (int j = 0; j < 4; j++)
            #pragma unroll
            for (int q = 0; q < 4; q++) acc[i][j][q] = 0.f;

    int ar = lane & 15, ac = lane >> 4;
    int br = lane & 7, bc = (lane >> 3) & 1;
    uint32_t qhB = sb, qlB = sb + QKTILE, khB = sb + 2 * QKTILE, klB = sb + 3 * QKTILE;

    #pragma unroll
    for (int ks = 0; ks < 4; ks++) {
        uint32_t aH[4][4], aL[4][4], bF[4][2];
        int koff = (ks * 16 + ac * 8) * 2;
        int koffb = (ks * 16 + bc * 8) * 2;
        #pragma unroll
        for (int mt = 0; mt < 4; mt++) {
            uint32_t ra = (uint32_t)((wm * 64 + mt * 16 + ar) * QKPAD) + koff;
            ldsm_x4(qhB + ra, aH[mt]);
            ldsm_x4(qlB + ra, aL[mt]);
        }
        #pragma unroll
        for (int nt = 0; nt < 4; nt++) {
            uint32_t rb = (uint32_t)((wn * 32 + nt * 8 + br) * QKPAD) + koffb;
            ldsm_x2(khB + rb, bF[nt]);
        }
        #pragma unroll
        for (int mt = 0; mt < 4; mt++)
            #pragma unroll
            for (int nt = 0; nt < 4; nt++) {
                mma_bf16(acc[mt][nt], aH[mt], bF[nt]);
                mma_bf16(acc[mt][nt], aL[mt], bF[nt]);
            }
        #pragma unroll
        for (int nt = 0; nt < 4; nt++) {
            uint32_t rb = (uint32_t)((wn * 32 + nt * 8 + br) * QKPAD) + koffb;
            ldsm_x2(klB + rb, bF[nt]);
        }
        #pragma unroll
        for (int mt = 0; mt < 4; mt++)
            #pragma unroll
            for (int nt = 0; nt < 4; nt++)
                mma_bf16(acc[mt][nt], aH[mt], bF[nt]);
    }

    int qrow = lane >> 2, qcol = 2 * (lane & 3);
    float* Qbase = QK + (size_t)bh * NTOK * NTOK;
    #pragma unroll
    for (int mt = 0; mt < 4; mt++) {
        #pragma unroll
        for (int half = 0; half < 2; half++) {
            int gm = m0 + wm * 64 + mt * 16 + qrow + half * 8;
            if (gm >= NTOK) continue;
            #pragma unroll
            for (int nt = 0; nt < 4; nt++) {
                int gn = n0 + wn * 32 + nt * 8 + qcol;
                if (gn >= NTOK) continue;
                float2 v;
                v.x = acc[mt][nt][half * 2 + 0];
                v.y = acc[mt][nt][half * 2 + 1];
                *(float2*)(Qbase + (size_t)gm * NTOK + gn) = v;
            }
        }
    }
}

// ---------------------------------------------------------------------------
// attn_post: P from QK dots + riemann + BN affine + 2H->H conv.
// ---------------------------------------------------------------------------
__global__ __launch_bounds__(256)
void attn_post(const float* __restrict__ QK, const float* __restrict__ qq,
               const float* __restrict__ kk, const float* __restrict__ scale_l,
               const float* __restrict__ riem_scale_l, const float* __restrict__ temp_l,
               const float* __restrict__ bn_g_l, const float* __restrict__ bn_b_l,
               const float* __restrict__ conv_w_l, const float* __restrict__ conv_b_l,
               float* __restrict__ P) {
    __shared__ float s_qk[HEADS * NTOK];
    __shared__ float s_kk[HEADS * NTOK];
    __shared__ float s_qq[HEADS];
    __shared__ float cw[288], mch[24], bch[24], cb[12];

    int i = blockIdx.x, b = blockIdx.y;
    int tid = threadIdx.x;

    for (int idx = tid; idx < HEADS * NTOK; idx += 256) {
        int h = idx / NTOK, j = idx - h * NTOK;
        s_qk[idx] = QK[(((size_t)b * HEADS + h) * NTOK + i) * NTOK + j];
        s_kk[idx] = kk[((size_t)b * HEADS + h) * NTOK + j];
    }
    if (tid < HEADS) {
        s_qq[tid] = qq[((size_t)b * HEADS + tid) * NTOK + i];
        cb[tid] = conv_b_l[tid];
    }
    for (int idx = tid; idx < 288; idx += 256) cw[idx] = conv_w_l[idx];
    if (tid < 24) {
        mch[tid] = temp_l[tid] * BN_RSTD * bn_g_l[tid];
        bch[tid] = bn_b_l[tid];
    }
    __syncthreads();
    if (tid >= NTOK) return;

    float scale = scale_l[0], riem = riem_scale_l[0];
    float a[24];
    #pragma unroll
    for (int h = 0; h < HEADS; h++) {
        float qk = s_qk[h * NTOK + tid];
        a[h] = qk * scale;
        float qv = s_qq[h];
        float kv = s_kk[h * NTOK + tid];
        float d2 = qv * qv + kv * kv - 2.f * qk * qk;
        a[HEADS + h] = sqrtf(fmaxf(d2, 0.f) + 1e-12f) * riem;
    }
    #pragma unroll
    for (int c = 0; c < 24; c++) a[c] = a[c] * mch[c] + bch[c];
    #pragma unroll
    for (int hh = 0; hh < HEADS; hh++) {
        float o = cb[hh];
        #pragma unroll
        for (int c = 0; c < 24; c++) o += cw[hh * 24 + c] * a[c];
        P[(((size_t)b * HEADS + hh) * NTOK + i) * NTOK + tid] = o;
    }
}

// ---------------------------------------------------------------------------
// av_mma: softmax(P) @ V on tensor cores (bf16x3).
// Block = (i-tile of 128, bh). Softmax stats read from gmem; P converted to
// bf16 hi/lo in smem; V hi/lo tiles from qkv bf16; mma with ldmatrix.trans B.
// ---------------------------------------------------------------------------
#define AV_PSTR 464                   // bytes per P smem row (224 bf16 + pad)
#define AV_VSTR 144                   // bytes per V smem row (64 bf16 + pad)
#define AV_PH 0
#define AV_PL (128 * AV_PSTR)         // 59392
#define AV_VH (2 * 128 * AV_PSTR)     // 118784
#define AV_VL (AV_VH + 224 * AV_VSTR) // 151040
#define AV_RMX (AV_VL + 224 * AV_VSTR)  // 183296
#define AV_RINV (AV_RMX + 512)
#define AV_SMEM (AV_RINV + 512)       // 184320

__global__ __launch_bounds__(256, 1)
void av_mma_kernel(const float* __restrict__ P,
                   const __nv_bfloat16* __restrict__ qkvh,
                   const __nv_bfloat16* __restrict__ qkvl,
                   __nv_bfloat16* __restrict__ oh, __nv_bfloat16* __restrict__ ol) {
    extern __shared__ char smem[];
    uint32_t sb = smem_u32(smem);
    float* rmxp = (float*)(smem + AV_RMX);
    float* rinvp = (float*)(smem + AV_RINV);

    int tid = threadIdx.x, lane = tid & 31, wid = tid >> 5;
    int wm = wid >> 2, wn = wid & 3;       // 2 x 4 warps; warp tile 64(i) x 16(d)
    int bh = blockIdx.y;
    int b = bh / HEADS, h = bh % HEADS;
    int i0 = blockIdx.x * 128;

    // V tiles (hi/lo), rows j=0..223 zero-padded past NTOK
    #pragma unroll
    for (int t = 0; t < 7; t++) {
        int e = tid + t * 256;             // 0..1791 = 224 rows x 8 chunks
        int row = e >> 3, qc = e & 7;
        int ok = (row < NTOK) ? 16 : 0;
        size_t goff = (size_t)(b * NTOK + (ok ? row : 0)) * QKVDIM + 2 * CDIM + h * HD + qc * 8;
        cp_async16(sb + AV_VH + row * AV_VSTR + qc * 16, qkvh + goff, ok);
        cp_async16(sb + AV_VL + row * AV_VSTR + qc * 16, qkvl + goff, ok);
    }
    cp_commit();

    // Row softmax stats (read P from gmem; 16 rows per warp)
    for (int rr = wid; rr < 128; rr += 8) {
        int gi = i0 + rr;
        float mx = 0.f, inv = 0.f;
        if (gi < NTOK) {
            const float* prow = P + ((size_t)bh * NTOK + gi) * NTOK;
            float m = -1e30f;
            for (int c = lane; c < NTOK; c += 32) m = fmaxf(m, prow[c]);
            m = wmax(m);
            float s = 0.f;
            for (int c = lane; c < NTOK; c += 32) s += expf(prow[c] - m);
            s = wsum(s);
            mx = m; inv = 1.f / s;
        }
        if (lane == 0) { rmxp[rr] = mx; rinvp[rr] = inv; }
    }
    __syncthreads();

    // Fill P bf16 hi/lo smem (zero-padded)
    for (int idx = tid; idx < 128 * 224; idx += 256) {
        int row = idx / 224, col = idx - row * 224;
        int gi = i0 + row;
        float val = 0.f;
        if (gi < NTOK && col < NTOK)
            val = expf(P[((size_t)bh * NTOK + gi) * NTOK + col] - rmxp[row]) * rinvp[row];
        __nv_bfloat16 hh, ll;
        split_bf(val, hh, ll);
        *(__nv_bfloat16*)(smem + AV_PH + row * AV_PSTR + col * 2) = hh;
        *(__nv_bfloat16*)(smem + AV_PL + row * AV_PSTR + col * 2) = ll;
    }
    cp_wait<0>();
    __syncthreads();

    // MMA: o[128 x 64] = P[128 x 224] @ V[224 x 64]
    float acc[4][2][4];
    #pragma unroll
    for (int i = 0; i < 4; i++)
        #pragma unroll
        for (int j = 0; j < 2; j++)
            #pragma unroll
            for (int q = 0; q < 4; q++) acc[i][j][q] = 0.f;

    int ar = lane & 15, ac = lane >> 4;
    int bl = lane & 15;
    int brow_off = (bl & 7) + 8 * ((bl >> 3) & 1);

    #pragma unroll
    for (int ks = 0; ks < 14; ks++) {
        int k = ks * 16;
        uint32_t aH[4][4], aL[4][4], bH[2][2], bL[2][2];
        int koff = (k + ac * 8) * 2;
        #pragma unroll
        for (int mt = 0; mt < 4; mt++) {
            uint32_t ra = sb + AV_PH + (uint32_t)((wm * 64 + mt * 16 + ar) * AV_PSTR) + koff;
            ldsm_x4(ra, aH[mt]);
            ldsm_x4(ra + (AV_PL - AV_PH), aL[mt]);
        }
        #pragma unroll
        for (int nt = 0; nt < 2; nt++) {
            uint32_t rb = sb + AV_VH + (uint32_t)((k + brow_off) * AV_VSTR)
                          + (wn * 16 + nt * 8) * 2;
            ldsm_x2_trans(rb, bH[nt]);
            ldsm_x2_trans(rb + (AV_VL - AV_VH), bL[nt]);
        }
        #pragma unroll
        for (int mt = 0; mt < 4; mt++)
            #pragma unroll
            for (int nt = 0; nt < 2; nt++) {
                mma_bf16(acc[mt][nt], aH[mt], bH[nt]);
                mma_bf16(acc[mt][nt], aH[mt], bL[nt]);
                mma_bf16(acc[mt][nt], aL[mt], bH[nt]);
            }
    }

    // Epilogue: split to bf16 hi/lo, store
    int qrow = lane >> 2, qcol = 2 * (lane & 3);
    #pragma unroll
    for (int mt = 0; mt < 4; mt++) {
        #pragma unroll
        for (int half = 0; half < 2; half++) {
            int gi = i0 + wm * 64 + mt * 16 + qrow + half * 8;
            if (gi >= NTOK) continue;
            #pragma unroll
            for (int nt = 0; nt < 2; nt++) {
                int d = wn * 16 + nt * 8 + qcol;
                size_t idx = ((size_t)(b * NTOK) + gi) * CDIM + h * HD + d;
                __nv_bfloat16 hh, ll;
                split_bf(acc[mt][nt][half * 2 + 0], hh, ll);
                oh[idx] = hh; ol[idx] = ll;
                split_bf(acc[mt][nt][half * 2 + 1], hh, ll);
                oh[idx + 1] = hh; ol[idx + 1] = ll;
            }
        }
    }
}

// ---------------------------------------------------------------------------
// seq_pool
// ---------------------------------------------------------------------------
__global__ void pool_kernel(const float* __restrict__ x, const float* __restrict__ pw,
                            const float* __restrict__ pb, float* __restrict__ pooled) {
    int b = blockIdx.x;
    __shared__ float s[NTOK];
    __shared__ float red[32];
    int tid = threadIdx.x, lane = tid & 31, w = tid >> 5;

    for (int n = w; n < NTOK; n += 8) {
        const float* xp = x + ((size_t)b * NTOK + n) * CDIM;
        float acc = 0.f;
        for (int c = lane; c < CDIM; c += 32) acc += xp[c] * pw[c];
        acc = wsum(acc);
        if (lane == 0) s[n] = acc + pb[0];
    }
    __syncthreads();

    float mx = -1e30f;
    for (int n = tid; n < NTOK; n += 256) mx = fmaxf(mx, s[n]);
    mx = wmax(mx);
    if (lane == 0) red[w] = mx;
    __syncthreads();
    if (tid == 0) { float m = red[0]; for (int q = 1; q < 8; q++) m = fmaxf(m, red[q]); red[16] = m; }
    __syncthreads();
    mx = red[16];

    float ps = 0.f;
    for (int n = tid; n < NTOK; n += 256) { float e = expf(s[n] - mx); s[n] = e; ps += e; }
    ps = wsum(ps);
    if (lane == 0) red[w] = ps;
    __syncthreads();
    if (tid == 0) { float t = 0; for (int q = 0; q < 8; q++) t += red[q]; red[17] = 1.f / t; }
    __syncthreads();
    float inv = red[17];

    for (int c = tid; c < CDIM; c += 256) {
        float acc = 0.f;
        for (int n = 0; n < NTOK; n++)
            acc += s[n] * x[((size_t)b * NTOK + n) * CDIM + c];
        pooled[b * CDIM + c] = acc * inv;
    }
}

// ---------------------------------------------------------------------------
// fc
// ---------------------------------------------------------------------------
__global__ void fc_kernel(const float* __restrict__ pooled, const float* __restrict__ fw,
                          const float* __restrict__ fb, float* __restrict__ out) {
    int gw = (blockIdx.x * blockDim.x + threadIdx.x) >> 5;
    int lane = threadIdx.x & 31;
    if (gw >= BATCH * NCLS) return;
    int b = gw / NCLS, o = gw % NCLS;
    const float* pp = pooled + b * CDIM;
    const float* wp = fw + (size_t)o * CDIM;
    float acc = 0.f;
    for (int c = lane; c < CDIM; c += 32) acc += pp[c] * wp[c];
    acc = wsum(acc);
    if (lane == 0) out[gw] = acc + fb[o];
}

// ---------------------------------------------------------------------------
// Launch
// ---------------------------------------------------------------------------
extern "C" void kernel_launch(void* const* d_in, const int* in_sizes, int n_in,
                              void* d_out, int out_size) {
    const float* x_in      = (const float*)d_in[0];
    const float* pos_emb   = (const float*)d_in[1];
    const float* ln0_g     = (const float*)d_in[2];
    const float* ln0_b     = (const float*)d_in[3];
    const float* qkv_w     = (const float*)d_in[4];
    const float* qkv_b     = (const float*)d_in[5];
    const float* qkvln_g   = (const float*)d_in[6];
    const float* qkvln_b   = (const float*)d_in[7];
    const float* scale     = (const float*)d_in[8];
    const float* riem_sc   = (const float*)d_in[9];
    const float* temp      = (const float*)d_in[10];
    const float* bn_g      = (const float*)d_in[11];
    const float* bn_b      = (const float*)d_in[12];
    const float* conv_w    = (const float*)d_in[13];
    const float* conv_b    = (const float*)d_in[14];
    const float* proj_w    = (const float*)d_in[15];
    const float* proj_b    = (const float*)d_in[16];
    const float* ln1_g     = (const float*)d_in[17];
    const float* ln1_b     = (const float*)d_in[18];
    const float* ff1_w     = (const float*)d_in[19];
    const float* ff1_b     = (const float*)d_in[20];
    const float* ff2_w     = (const float*)d_in[21];
    const float* ff2_b     = (const float*)d_in[22];
    const float* norm_g    = (const float*)d_in[23];
    const float* norm_b    = (const float*)d_in[24];
    const float* pool_w    = (const float*)d_in[25];
    const float* pool_b    = (const float*)d_in[26];
    const float* fc_w      = (const float*)d_in[27];
    const float* fc_b      = (const float*)d_in[28];

    float* S = nullptr;
    cudaGetSymbolAddress((void**)&S, g_scratch);
    __nv_bfloat16* BF = nullptr;
    cudaGetSymbolAddress((void**)&BF, g_bf);

    float* gx      = S + OFF_X;
    float* gqkv    = S + OFF_QKV;
    float* gqq     = S + OFF_QQ;
    float* gkk     = S + OFF_KK;
    float* gP      = S + OFF_P;
    float* gQK     = S + OFF_QK;
    float* gpooled = S + OFF_POOLED;

    __nv_bfloat16* wqkv_h  = BF + BO_WQKV_HI,  *wqkv_l  = BF + BO_WQKV_LO;
    __nv_bfloat16* wproj_h = BF + BO_WPROJ_HI, *wproj_l = BF + BO_WPROJ_LO;
    __nv_bfloat16* wff1_h  = BF + BO_WFF1_HI,  *wff1_l  = BF + BO_WFF1_LO;
    __nv_bfloat16* wff2_h  = BF + BO_WFF2_HI,  *wff2_l  = BF + BO_WFF2_LO;
    __nv_bfloat16* h_h = BF + BO_H_HI, *h_l = BF + BO_H_LO;
    __nv_bfloat16* o_h = BF + BO_O_HI, *o_l = BF + BO_O_LO;
    __nv_bfloat16* x_h = BF + BO_X_HI, *x_l = BF + BO_X_LO;
    __nv_bfloat16* f_h = BF + BO_F_HI, *f_l = BF + BO_F_LO;
    __nv_bfloat16* qkv_hh = BF + BO_QKV_HI, *qkv_ll = BF + BO_QKV_LO;

    cudaFuncSetAttribute(gemm_mma<0>, cudaFuncAttributeMaxDynamicSharedMemorySize, GSMEM);
    cudaFuncSetAttribute(gemm_mma<1>, cudaFuncAttributeMaxDynamicSharedMemorySize, GSMEM);
    cudaFuncSetAttribute(gemm_mma<2>, cudaFuncAttributeMaxDynamicSharedMemorySize, GSMEM);
    cudaFuncSetAttribute(qk_mma, cudaFuncAttributeMaxDynamicSharedMemorySize, QKSMEM);
    cudaFuncSetAttribute(av_mma_kernel, cudaFuncAttributeMaxDynamicSharedMemorySize, AV_SMEM);

    cvt_hilo_kernel<<<2048, 256>>>((const float4*)qkv_w,  (__nv_bfloat162*)wqkv_h,
                                   (__nv_bfloat162*)wqkv_l,  NB_WQKV / 4);
    cvt_hilo_kernel<<<2048, 256>>>((const float4*)proj_w, (__nv_bfloat162*)wproj_h,
                                   (__nv_bfloat162*)wproj_l, NB_WPROJ / 4);
    cvt_hilo_kernel<<<2048, 256>>>((const float4*)ff1_w,  (__nv_bfloat162*)wff1_h,
                                   (__nv_bfloat162*)wff1_l,  NB_WFF1 / 4);
    cvt_hilo_kernel<<<2048, 256>>>((const float4*)ff2_w,  (__nv_bfloat162*)wff2_h,
                                   (__nv_bfloat162*)wff2_l,  NB_WFF2 / 4);

    addpos_kernel<<<(TOKENS * CDIM + 255) / 256, 256>>>(x_in, pos_emb, gx);

    const int MB = (TOKENS + 127) / 128;  // 25
    for (int l = 0; l < LAYERS; l++) {
        // h = LN0(x) -> bf16 hi/lo
        ln_kernel<1><<<TOKENS, 256, CDIM * sizeof(float)>>>(
            gx, nullptr, h_h, h_l, ln0_g + l * CDIM, ln0_b + l * CDIM, CDIM);
        // qkv = h @ qkv_w^T + b
        gemm_mma<0><<<dim3(QKVDIM / 128, MB), 256, GSMEM>>>(
            h_h, h_l, wqkv_h + (size_t)l * QKVDIM * CDIM, wqkv_l + (size_t)l * QKVDIM * CDIM,
            qkv_b + l * QKVDIM, gqkv, nullptr, nullptr, TOKENS, QKVDIM, CDIM);
        // qkv = LN(qkv) in place + bf16 hi/lo + per-head q/k norms
        ln_qkv_kernel<<<TOKENS, 256>>>(gqkv, qkvln_g + l * QKVDIM,
                                       qkvln_b + l * QKVDIM, qkv_hh, qkv_ll, gqq, gkk);
        // QK dots via tensor cores
        qk_mma<<<dim3(2, 2, BATCH * HEADS), 256, QKSMEM>>>(qkv_hh, qkv_ll, gQK);
        // riem + BN affine + conv -> P
        attn_post<<<dim3(NTOK, BATCH), 256>>>(
            gQK, gqq, gkk, scale + l, riem_sc + l, temp + l * 24,
            bn_g + l * 24, bn_b + l * 24, conv_w + l * 288, conv_b + l * 12, gP);
        // softmax + (P @ v) via tensor cores -> bf16 hi/lo
        av_mma_kernel<<<dim3(2, BATCH * HEADS), 256, AV_SMEM>>>(
            gP, qkv_hh, qkv_ll, o_h, o_l);
        // x = x + o @ proj_w^T + proj_b
        gemm_mma<1><<<dim3(CDIM / 128, MB), 256, GSMEM>>>(
            o_h, o_l, wproj_h + (size_t)l * CDIM * CDIM, wproj_l + (size_t)l * CDIM * CDIM,
            proj_b + l * CDIM, gx, nullptr, nullptr, TOKENS, CDIM, CDIM);
        // x = LN1(x) in-place + bf16 hi/lo
        ln_kernel<2><<<TOKENS, 256, CDIM * sizeof(float)>>>(
            gx, gx, x_h, x_l, ln1_g + l * CDIM, ln1_b + l * CDIM, CDIM);
        // f = gelu(x @ ff1^T + b) -> bf16 hi/lo
        gemm_mma<2><<<dim3(DFF / 128, MB), 256, GSMEM>>>(
            x_h, x_l, wff1_h + (size_t)l * DFF * CDIM, wff1_l + (size_t)l * DFF * CDIM,
            ff1_b + l * DFF, nullptr, f_h, f_l, TOKENS, DFF, CDIM);
        // x = x + f @ ff2^T + b
        gemm_mma<1><<<dim3(CDIM / 128, MB), 256, GSMEM>>>(
            f_h, f_l, wff2_h + (size_t)l * CDIM * DFF, wff2_l + (size_t)l * CDIM * DFF,
            ff2_b + l * CDIM, gx, nullptr, nullptr, TOKENS, CDIM, DFF);
    }

    ln_kernel<0><<<TOKENS, 256, CDIM * sizeof(float)>>>(
        gx, gx, nullptr, nullptr, norm_g, norm_b, CDIM);
    pool_kernel<<<BATCH, 256>>>(gx, pool_w, pool_b, gpooled);
    fc_kernel<<<(BATCH * NCLS * 32 + 255) / 256, 256>>>(gpooled, fc_w, fc_b,
                                                        (float*)d_out);
}

// round 15
// speedup vs baseline: 1.1425x; 1.1409x over previous
#include <cuda_runtime.h>
#include <cuda_bf16.h>
#include <math.h>
#include <stdint.h>

// ---------------------------------------------------------------------------
// Problem constants
// ---------------------------------------------------------------------------
#define LAYERS 12
#define CDIM   768
#define HEADS  12
#define HD     64
#define NTOK   196
#define BATCH  16
#define DFF    3072
#define NCLS   1000
#define TOKENS (BATCH * NTOK)        // 3136
#define QKVDIM (3 * CDIM)            // 2304
#define NROWS_ATT (BATCH * HEADS * NTOK) // 37632
#define BN_RSTD 0.99999500003749969f

// ---------------------------------------------------------------------------
// fp32 scratch
// ---------------------------------------------------------------------------
#define OFF_X      0
#define OFF_QKV    (OFF_X + (size_t)TOKENS * CDIM)
#define OFF_QQ     (OFF_QKV + (size_t)TOKENS * QKVDIM)
#define OFF_KK     (OFF_QQ + NROWS_ATT)
#define OFF_P      (OFF_KK + NROWS_ATT)
#define OFF_QK     (OFF_P + (size_t)BATCH * HEADS * NTOK * NTOK)
#define OFF_POOLED (OFF_QK + (size_t)BATCH * HEADS * NTOK * NTOK)
#define SCRATCH_TOTAL (OFF_POOLED + BATCH * CDIM)

__device__ __align__(256) float g_scratch[SCRATCH_TOTAL];

// ---------------------------------------------------------------------------
// bf16 scratch
// ---------------------------------------------------------------------------
#define NB_WQKV  ((size_t)LAYERS * QKVDIM * CDIM)
#define NB_WPROJ ((size_t)LAYERS * CDIM * CDIM)
#define NB_WFF1  ((size_t)LAYERS * DFF * CDIM)
#define NB_WFF2  ((size_t)LAYERS * CDIM * DFF)
#define NB_ACT   ((size_t)TOKENS * CDIM)
#define NB_F     ((size_t)TOKENS * DFF)
#define NB_QKVA  ((size_t)TOKENS * QKVDIM)

#define BO_WQKV_HI  ((size_t)0)
#define BO_WQKV_LO  (BO_WQKV_HI + NB_WQKV)
#define BO_WPROJ_HI (BO_WQKV_LO + NB_WQKV)
#define BO_WPROJ_LO (BO_WPROJ_HI + NB_WPROJ)
#define BO_WFF1_HI  (BO_WPROJ_LO + NB_WPROJ)
#define BO_WFF1_LO  (BO_WFF1_HI + NB_WFF1)
#define BO_WFF2_HI  (BO_WFF1_LO + NB_WFF1)
#define BO_WFF2_LO  (BO_WFF2_HI + NB_WFF2)
#define BO_H_HI     (BO_WFF2_LO + NB_WFF2)
#define BO_H_LO     (BO_H_HI + NB_ACT)
#define BO_O_HI     (BO_H_LO + NB_ACT)
#define BO_O_LO     (BO_O_HI + NB_ACT)
#define BO_X_HI     (BO_O_LO + NB_ACT)
#define BO_X_LO     (BO_X_HI + NB_ACT)
#define BO_F_HI     (BO_X_LO + NB_ACT)
#define BO_F_LO     (BO_F_HI + NB_F)
#define BO_QKV_HI   (BO_F_LO + NB_F)
#define BO_QKV_LO   (BO_QKV_HI + NB_QKVA)
#define BF_TOTAL    (BO_QKV_LO + NB_QKVA)

__device__ __align__(256) __nv_bfloat16 g_bf[BF_TOTAL];

// ---------------------------------------------------------------------------
// helpers
// ---------------------------------------------------------------------------
__device__ __forceinline__ uint32_t smem_u32(const void* p) {
    uint32_t a;
    asm("{ .reg .u64 t; cvta.to.shared.u64 t, %1; cvt.u32.u64 %0, t; }"
        : "=r"(a) : "l"(p));
    return a;
}
__device__ __forceinline__ float wsum(float v) {
    #pragma unroll
    for (int o = 16; o; o >>= 1) v += __shfl_xor_sync(0xffffffffu, v, o);
    return v;
}
__device__ __forceinline__ float wmax(float v) {
    #pragma unroll
    for (int o = 16; o; o >>= 1) v = fmaxf(v, __shfl_xor_sync(0xffffffffu, v, o));
    return v;
}
__device__ __forceinline__ void split_bf(float v, __nv_bfloat16& h, __nv_bfloat16& l) {
    h = __float2bfloat16(v);
    l = __float2bfloat16(v - __bfloat162float(h));
}
__device__ __forceinline__ void cp_async16(uint32_t dst, const void* src, int srcsize) {
    asm volatile("cp.async.cg.shared.global [%0], [%1], 16, %2;"
                 :: "r"(dst), "l"(src), "r"(srcsize) : "memory");
}
__device__ __forceinline__ void cp_commit() {
    asm volatile("cp.async.commit_group;" ::: "memory");
}
template <int N>
__device__ __forceinline__ void cp_wait() {
    asm volatile("cp.async.wait_group %0;" :: "n"(N) : "memory");
}
__device__ __forceinline__ void ldsm_x4(uint32_t addr, uint32_t* r) {
    asm volatile("ldmatrix.sync.aligned.m8n8.x4.shared.b16 {%0,%1,%2,%3}, [%4];"
        : "=r"(r[0]), "=r"(r[1]), "=r"(r[2]), "=r"(r[3]) : "r"(addr));
}
__device__ __forceinline__ void ldsm_x2(uint32_t addr, uint32_t* r) {
    asm volatile("ldmatrix.sync.aligned.m8n8.x2.shared.b16 {%0,%1}, [%2];"
        : "=r"(r[0]), "=r"(r[1]) : "r"(addr));
}
__device__ __forceinline__ void mma_bf16(float* d, const uint32_t* a, const uint32_t* b) {
    asm volatile("mma.sync.aligned.m16n8k16.row.col.f32.bf16.bf16.f32 "
        "{%0,%1,%2,%3}, {%4,%5,%6,%7}, {%8,%9}, {%0,%1,%2,%3};"
        : "+f"(d[0]), "+f"(d[1]), "+f"(d[2]), "+f"(d[3])
        : "r"(a[0]), "r"(a[1]), "r"(a[2]), "r"(a[3]), "r"(b[0]), "r"(b[1]));
}

// ---------------------------------------------------------------------------
// fp32 -> bf16 hi/lo conversion (vectorized)
// ---------------------------------------------------------------------------
__global__ void cvt_hilo_kernel(const float4* __restrict__ w,
                                __nv_bfloat162* __restrict__ hi,
                                __nv_bfloat162* __restrict__ lo, size_t n4) {
    size_t i = (size_t)blockIdx.x * blockDim.x + threadIdx.x;
    size_t stride = (size_t)gridDim.x * blockDim.x;
    for (; i < n4; i += stride) {
        float4 v = w[i];
        __nv_bfloat16 h0, l0, h1, l1, h2, l2, h3, l3;
        split_bf(v.x, h0, l0); split_bf(v.y, h1, l1);
        split_bf(v.z, h2, l2); split_bf(v.w, h3, l3);
        __nv_bfloat162 a, b;
        a.x = h0; a.y = h1; b.x = h2; b.y = h3;
        hi[2 * i] = a; hi[2 * i + 1] = b;
        a.x = l0; a.y = l1; b.x = l2; b.y = l3;
        lo[2 * i] = a; lo[2 * i + 1] = b;
    }
}

// ---------------------------------------------------------------------------
// x = x_in + pos_emb
// ---------------------------------------------------------------------------
__global__ void addpos_kernel(const float* __restrict__ x,
                              const float* __restrict__ pe,
                              float* __restrict__ gx) {
    int idx = blockIdx.x * blockDim.x + threadIdx.x;
    if (idx >= TOKENS * CDIM) return;
    int c = idx % CDIM;
    int n = (idx / CDIM) % NTOK;
    gx[idx] = x[idx] + pe[n * CDIM + c];
}

// ---------------------------------------------------------------------------
// LayerNorm. MODE 0: fp32 out. MODE 1: bf16 hi/lo out. MODE 2: both.
// ---------------------------------------------------------------------------
template <int MODE>
__global__ void ln_kernel(const float* __restrict__ in, float* __restrict__ outf,
                          __nv_bfloat16* __restrict__ oh, __nv_bfloat16* __restrict__ ol,
                          const float* __restrict__ g, const float* __restrict__ b,
                          int D) {
    extern __shared__ float row[];
    __shared__ float red[34];
    int r = blockIdx.x;
    const float* ip = in + (size_t)r * D;
    int tid = threadIdx.x, lane = tid & 31, w = tid >> 5;

    float s = 0.f;
    for (int c = tid; c < D; c += blockDim.x) { float v = ip[c]; row[c] = v; s += v; }
    s = wsum(s);
    if (lane == 0) red[w] = s;
    __syncthreads();
    if (tid == 0) { float t = 0; for (int q = 0; q < 8; q++) t += red[q]; red[32] = t / D; }
    __syncthreads();
    float mean = red[32];

    float vs = 0.f;
    for (int c = tid; c < D; c += blockDim.x) { float d = row[c] - mean; vs += d * d; }
    vs = wsum(vs);
    if (lane == 0) red[w] = vs;
    __syncthreads();
    if (tid == 0) { float t = 0; for (int q = 0; q < 8; q++) t += red[q]; red[33] = rsqrtf(t / D + 1e-5f); }
    __syncthreads();
    float rstd = red[33];

    for (int c = tid; c < D; c += blockDim.x) {
        float v = (row[c] - mean) * rstd * g[c] + b[c];
        size_t idx = (size_t)r * D + c;
        if (MODE == 0 || MODE == 2) outf[idx] = v;
        if (MODE == 1 || MODE == 2) {
            __nv_bfloat16 h, l;
            split_bf(v, h, l);
            oh[idx] = h; ol[idx] = l;
        }
    }
}

// ---------------------------------------------------------------------------
// Fused qkv LayerNorm (D=2304, in place) + bf16 hi/lo copy + per-head norms.
// ---------------------------------------------------------------------------
__global__ void ln_qkv_kernel(float* __restrict__ qkvbuf,
                              const float* __restrict__ g, const float* __restrict__ b,
                              __nv_bfloat16* __restrict__ oh, __nv_bfloat16* __restrict__ ol,
                              float* __restrict__ qq, float* __restrict__ kk) {
    __shared__ float row[QKVDIM];
    __shared__ float red[34];
    int r = blockIdx.x;
    float* ip = qkvbuf + (size_t)r * QKVDIM;
    int tid = threadIdx.x, lane = tid & 31, w = tid >> 5;

    float s = 0.f;
    for (int c = tid; c < QKVDIM; c += 256) { float v = ip[c]; row[c] = v; s += v; }
    s = wsum(s);
    if (lane == 0) red[w] = s;
    __syncthreads();
    if (tid == 0) { float t = 0; for (int q = 0; q < 8; q++) t += red[q]; red[32] = t / QKVDIM; }
    __syncthreads();
    float mean = red[32];

    float vs = 0.f;
    for (int c = tid; c < QKVDIM; c += 256) { float d = row[c] - mean; vs += d * d; }
    vs = wsum(vs);
    if (lane == 0) red[w] = vs;
    __syncthreads();
    if (tid == 0) { float t = 0; for (int q = 0; q < 8; q++) t += red[q]; red[33] = rsqrtf(t / QKVDIM + 1e-5f); }
    __syncthreads();
    float rstd = red[33];

    for (int c = tid; c < QKVDIM; c += 256) {
        float v = (row[c] - mean) * rstd * g[c] + b[c];
        row[c] = v;
        ip[c] = v;
        size_t idx = (size_t)r * QKVDIM + c;
        __nv_bfloat16 h, l;
        split_bf(v, h, l);
        oh[idx] = h; ol[idx] = l;
    }
    __syncthreads();

    int bb = r / NTOK, n = r % NTOK;
    for (int seg = w; seg < 24; seg += 8) {
        int base = seg * 64;
        float v0 = row[base + lane], v1 = row[base + lane + 32];
        float ssum = wsum(v0 * v0 + v1 * v1);
        if (lane == 0) {
            int h = seg % 12;
            float* dst = (seg < 12) ? qq : kk;
            dst[((size_t)bb * HEADS + h) * NTOK + n] = ssum;
        }
    }
}

// ---------------------------------------------------------------------------
// mma.sync bf16x3 GEMM (3-stage cp.async ring)
// ---------------------------------------------------------------------------
#define APAD 40
#define TILE_BYTES (128 * APAD * 2)
#define STAGE_BYTES (4 * TILE_BYTES)
#define NSTAGE 3
#define GSMEM (NSTAGE * STAGE_BYTES)

__device__ __forceinline__ void load_stage(
    uint32_t sbase, const __nv_bfloat16* __restrict__ Ah,
    const __nv_bfloat16* __restrict__ Al, const __nv_bfloat16* __restrict__ Bh,
    const __nv_bfloat16* __restrict__ Bl, int m0, int n0, int M, int K, int kc,
    int tid) {
    const __nv_bfloat16* gsrc[4] = {Ah, Al, Bh, Bl};
    #pragma unroll
    for (int tI = 0; tI < 4; tI++) {
        bool isA = tI < 2;
        int row0 = isA ? m0 : n0;
        uint32_t tb = sbase + tI * TILE_BYTES;
        #pragma unroll
        for (int c = 0; c < 2; c++) {
            int e = tid + c * 256;
            int rowi = e >> 2, qc = e & 3;
            int gr = row0 + rowi;
            int ok = (!isA || gr < M) ? 16 : 0;
            const __nv_bfloat16* src =
                gsrc[tI] + (size_t)(ok ? gr : row0) * K + kc + qc * 8;
            cp_async16(tb + rowi * 80 + qc * 16, src, ok);
        }
    }
}

template <int EPI>
__global__ __launch_bounds__(256, 1)
void gemm_mma(const __nv_bfloat16* __restrict__ Ah, const __nv_bfloat16* __restrict__ Al,
              const __nv_bfloat16* __restrict__ Bh, const __nv_bfloat16* __restrict__ Bl,
              const float* __restrict__ bias, float* __restrict__ Cf,
              __nv_bfloat16* __restrict__ Ch, __nv_bfloat16* __restrict__ Cl,
              int M, int N, int K) {
    extern __shared__ char smem[];
    uint32_t sb = smem_u32(smem);

    int tid = threadIdx.x, lane = tid & 31, wid = tid >> 5;
    int wm = wid >> 2, wn = wid & 3;
    int m0 = blockIdx.y * 128, n0 = blockIdx.x * 128;
    int NIT = K >> 5;

    float acc[4][4][4];
    #pragma unroll
    for (int i = 0; i < 4; i++)
        #pragma unroll
        for (int j = 0; j < 4; j++)
            #pragma unroll
            for (int q = 0; q < 4; q++) acc[i][j][q] = 0.f;

    int ar = lane & 15, ac = lane >> 4;
    int br = lane & 7, bc = (lane >> 3) & 1;

    load_stage(sb, Ah, Al, Bh, Bl, m0, n0, M, K, 0, tid);
    cp_commit();
    load_stage(sb + STAGE_BYTES, Ah, Al, Bh, Bl, m0, n0, M, K, 32, tid);
    cp_commit();

    int bufidx = 0;
    for (int it = 0; it < NIT; it++) {
        uint32_t buf = sb + (uint32_t)bufidx * STAGE_BYTES;
        if (it + 2 < NIT) {
            int li = (bufidx + 2) % NSTAGE;
            load_stage(sb + (uint32_t)li * STAGE_BYTES,
                       Ah, Al, Bh, Bl, m0, n0, M, K, (it + 2) * 32, tid);
            cp_commit();
            cp_wait<2>();
        } else if (it + 2 == NIT) {
            cp_wait<1>();
        } else {
            cp_wait<0>();
        }
        __syncthreads();

        uint32_t AhB = buf, AlB = buf + TILE_BYTES;
        uint32_t BhB = buf + 2 * TILE_BYTES, BlB = buf + 3 * TILE_BYTES;

        #pragma unroll
        for (int ks = 0; ks < 2; ks++) {
            uint32_t aH[4][4], aL[4][4], bF[4][2];
            int koff = (ks * 16 + ac * 8) * 2;
            int koffb = (ks * 16 + bc * 8) * 2;
            #pragma unroll
            for (int mt = 0; mt < 4; mt++) {
                uint32_t ra = (uint32_t)((wm * 64 + mt * 16 + ar) * 80) + koff;
                ldsm_x4(AhB + ra, aH[mt]);
                ldsm_x4(AlB + ra, aL[mt]);
            }
            #pragma unroll
            for (int nt = 0; nt < 4; nt++) {
                uint32_t rb = (uint32_t)((wn * 32 + nt * 8 + br) * 80) + koffb;
                ldsm_x2(BhB + rb, bF[nt]);
            }
            #pragma unroll
            for (int mt = 0; mt < 4; mt++)
                #pragma unroll
                for (int nt = 0; nt < 4; nt++) {
                    mma_bf16(acc[mt][nt], aH[mt], bF[nt]);
                    mma_bf16(acc[mt][nt], aL[mt], bF[nt]);
                }
            #pragma unroll
            for (int nt = 0; nt < 4; nt++) {
                uint32_t rb = (uint32_t)((wn * 32 + nt * 8 + br) * 80) + koffb;
                ldsm_x2(BlB + rb, bF[nt]);
            }
            #pragma unroll
            for (int mt = 0; mt < 4; mt++)
                #pragma unroll
                for (int nt = 0; nt < 4; nt++)
                    mma_bf16(acc[mt][nt], aH[mt], bF[nt]);
        }
        __syncthreads();
        bufidx = (bufidx + 1) % NSTAGE;
    }

    int qrow = lane >> 2, qcol = 2 * (lane & 3);
    #pragma unroll
    for (int mt = 0; mt < 4; mt++) {
        #pragma unroll
        for (int half = 0; half < 2; half++) {
            int gm = m0 + wm * 64 + mt * 16 + qrow + half * 8;
            if (gm >= M) continue;
            #pragma unroll
            for (int nt = 0; nt < 4; nt++) {
                int gn = n0 + wn * 32 + nt * 8 + qcol;
                float v0 = acc[mt][nt][half * 2 + 0] + bias[gn + 0];
                float v1 = acc[mt][nt][half * 2 + 1] + bias[gn + 1];
                size_t o = (size_t)gm * N + gn;
                if (EPI == 1) { v0 += Cf[o]; v1 += Cf[o + 1]; }
                if (EPI == 2) {
                    v0 = 0.5f * v0 * (1.f + erff(v0 * 0.70710678118654752f));
                    v1 = 0.5f * v1 * (1.f + erff(v1 * 0.70710678118654752f));
                    __nv_bfloat16 h, l;
                    split_bf(v0, h, l); Ch[o] = h;     Cl[o] = l;
                    split_bf(v1, h, l); Ch[o + 1] = h; Cl[o + 1] = l;
                } else {
                    Cf[o] = v0; Cf[o + 1] = v1;
                }
            }
        }
    }
}

// ---------------------------------------------------------------------------
// qk_mma: QK[b,h,i,j] = q_bh[i,:64] . k_bh[j,:64] via bf16x3 mma.
// ---------------------------------------------------------------------------
#define QKPAD 144
#define QKTILE (128 * QKPAD)
#define QKSMEM (4 * QKTILE)

__global__ __launch_bounds__(256, 1)
void qk_mma(const __nv_bfloat16* __restrict__ qkvh,
            const __nv_bfloat16* __restrict__ qkvl,
            float* __restrict__ QK) {
    extern __shared__ char smem[];
    uint32_t sb = smem_u32(smem);

    int tid = threadIdx.x, lane = tid & 31, wid = tid >> 5;
    int wm = wid >> 2, wn = wid & 3;
    int bh = blockIdx.z;
    int b = bh / HEADS, h = bh % HEADS;
    int m0 = blockIdx.y * 128, n0 = blockIdx.x * 128;

    {
        const __nv_bfloat16* srcs[4] = {qkvh, qkvl, qkvh, qkvl};
        int offs[4] = {h * HD, h * HD, CDIM + h * HD, CDIM + h * HD};
        int r0s[4] = {m0, m0, n0, n0};
        #pragma unroll
        for (int tI = 0; tI < 4; tI++) {
            uint32_t tb = sb + tI * QKTILE;
            #pragma unroll
            for (int t = 0; t < 4; t++) {
                int e = tid + t * 256;
                int rowi = e >> 3, qc = e & 7;
                int gr = r0s[tI] + rowi;
                int ok = (gr < NTOK) ? 16 : 0;
                const __nv_bfloat16* src = srcs[tI] +
                    (size_t)(b * NTOK + (ok ? gr : 0)) * QKVDIM + offs[tI] + qc * 8;
                cp_async16(tb + rowi * QKPAD + qc * 16, src, ok);
            }
        }
    }
    cp_commit();
    cp_wait<0>();
    __syncthreads();

    float acc[4][4][4];
    #pragma unroll
    for (int i = 0; i < 4; i++)
        #pragma unroll
        for (int j = 0; j < 4; j++)
            #pragma unroll
            for (int q = 0; q < 4; q++) acc[i][j][q] = 0.f;

    int ar = lane & 15, ac = lane >> 4;
    int br = lane & 7, bc = (lane >> 3) & 1;
    uint32_t qhB = sb, qlB = sb + QKTILE, khB = sb + 2 * QKTILE, klB = sb + 3 * QKTILE;

    #pragma unroll
    for (int ks = 0; ks < 4; ks++) {
        uint32_t aH[4][4], aL[4][4], bF[4][2];
        int koff = (ks * 16 + ac * 8) * 2;
        int koffb = (ks * 16 + bc * 8) * 2;
        #pragma unroll
        for (int mt = 0; mt < 4; mt++) {
            uint32_t ra = (uint32_t)((wm * 64 + mt * 16 + ar) * QKPAD) + koff;
            ldsm_x4(qhB + ra, aH[mt]);
            ldsm_x4(qlB + ra, aL[mt]);
        }
        #pragma unroll
        for (int nt = 0; nt < 4; nt++) {
            uint32_t rb = (uint32_t)((wn * 32 + nt * 8 + br) * QKPAD) + koffb;
            ldsm_x2(khB + rb, bF[nt]);
        }
        #pragma unroll
        for (int mt = 0; mt < 4; mt++)
            #pragma unroll
            for (int nt = 0; nt < 4; nt++) {
                mma_bf16(acc[mt][nt], aH[mt], bF[nt]);
                mma_bf16(acc[mt][nt], aL[mt], bF[nt]);
            }
        #pragma unroll
        for (int nt = 0; nt < 4; nt++) {
            uint32_t rb = (uint32_t)((wn * 32 + nt * 8 + br) * QKPAD) + koffb;
            ldsm_x2(klB + rb, bF[nt]);
        }
        #pragma unroll
        for (int mt = 0; mt < 4; mt++)
            #pragma unroll
            for (int nt = 0; nt < 4; nt++)
                mma_bf16(acc[mt][nt], aH[mt], bF[nt]);
    }

    int qrow = lane >> 2, qcol = 2 * (lane & 3);
    float* Qbase = QK + (size_t)bh * NTOK * NTOK;
    #pragma unroll
    for (int mt = 0; mt < 4; mt++) {
        #pragma unroll
        for (int half = 0; half < 2; half++) {
            int gm = m0 + wm * 64 + mt * 16 + qrow + half * 8;
            if (gm >= NTOK) continue;
            #pragma unroll
            for (int nt = 0; nt < 4; nt++) {
                int gn = n0 + wn * 32 + nt * 8 + qcol;
                if (gn >= NTOK) continue;
                float2 v;
                v.x = acc[mt][nt][half * 2 + 0];
                v.y = acc[mt][nt][half * 2 + 1];
                *(float2*)(Qbase + (size_t)gm * NTOK + gn) = v;
            }
        }
    }
}

// ---------------------------------------------------------------------------
// attn_post: P = softmax(conv(BN(temp * [euclid, riemann]))) — softmax fused.
// Block per (i, b); thread j computes all 24 channels + conv; then one warp
// per head normalizes the row (it lives entirely in this block) and writes
// ready-to-use probabilities to P.
// ---------------------------------------------------------------------------
__global__ __launch_bounds__(256)
void attn_post(const float* __restrict__ QK, const float* __restrict__ qq,
               const float* __restrict__ kk, const float* __restrict__ scale_l,
               const float* __restrict__ riem_scale_l, const float* __restrict__ temp_l,
               const float* __restrict__ bn_g_l, const float* __restrict__ bn_b_l,
               const float* __restrict__ conv_w_l, const float* __restrict__ conv_b_l,
               float* __restrict__ P) {
    __shared__ float s_qk[HEADS * NTOK];
    __shared__ float s_kk[HEADS * NTOK];
    __shared__ float s_out[HEADS * 224];
    __shared__ float s_qq[HEADS];
    __shared__ float cw[288], mch[24], bch[24], cb[12];

    int i = blockIdx.x, b = blockIdx.y;
    int tid = threadIdx.x;
    int lane = tid & 31, wid = tid >> 5;

    for (int idx = tid; idx < HEADS * NTOK; idx += 256) {
        int h = idx / NTOK, j = idx - h * NTOK;
        s_qk[idx] = QK[(((size_t)b * HEADS + h) * NTOK + i) * NTOK + j];
        s_kk[idx] = kk[((size_t)b * HEADS + h) * NTOK + j];
    }
    if (tid < HEADS) {
        s_qq[tid] = qq[((size_t)b * HEADS + tid) * NTOK + i];
        cb[tid] = conv_b_l[tid];
    }
    for (int idx = tid; idx < 288; idx += 256) cw[idx] = conv_w_l[idx];
    if (tid < 24) {
        mch[tid] = temp_l[tid] * BN_RSTD * bn_g_l[tid];
        bch[tid] = bn_b_l[tid];
    }
    __syncthreads();

    if (tid < NTOK) {
        float scale = scale_l[0], riem = riem_scale_l[0];
        float a[24];
        #pragma unroll
        for (int h = 0; h < HEADS; h++) {
            float qk = s_qk[h * NTOK + tid];
            a[h] = qk * scale;
            float qv = s_qq[h];
            float kv = s_kk[h * NTOK + tid];
            float d2 = qv * qv + kv * kv - 2.f * qk * qk;
            a[HEADS + h] = sqrtf(fmaxf(d2, 0.f) + 1e-12f) * riem;
        }
        #pragma unroll
        for (int c = 0; c < 24; c++) a[c] = a[c] * mch[c] + bch[c];
        #pragma unroll
        for (int hh = 0; hh < HEADS; hh++) {
            float o = cb[hh];
            #pragma unroll
            for (int c = 0; c < 24; c++) o += cw[hh * 24 + c] * a[c];
            s_out[hh * 224 + tid] = o;
        }
    }
    __syncthreads();

    // Fused row softmax: one warp per head (heads w, w+8 for warp w)
    for (int h = wid; h < HEADS; h += 8) {
        const float* rowp = s_out + h * 224;
        float mx = -1e30f;
        for (int c = lane; c < NTOK; c += 32) mx = fmaxf(mx, rowp[c]);
        mx = wmax(mx);
        float s = 0.f;
        for (int c = lane; c < NTOK; c += 32) s += expf(rowp[c] - mx);
        s = wsum(s);
        float inv = 1.f / s;
        float* pdst = P + (((size_t)b * HEADS + h) * NTOK + i) * NTOK;
        for (int c = lane; c < NTOK; c += 32)
            pdst[c] = expf(rowp[c] - mx) * inv;
    }
}

// ---------------------------------------------------------------------------
// av_prob: o = P @ v where P already holds probabilities. No stats, no exp.
// Block: (64,4) threads, 16 i-rows per block. Output bf16 hi/lo.
// ---------------------------------------------------------------------------
#define PSW 224

__global__ __launch_bounds__(256)
void av_prob_kernel(const float* __restrict__ P, const float* __restrict__ qkv,
                    __nv_bfloat16* __restrict__ oh, __nv_bfloat16* __restrict__ ol) {
    __shared__ float Ps[16 * PSW];
    __shared__ float vs[32][64];

    int bh = blockIdx.y;
    int b = bh / HEADS, hh = bh % HEADS;
    int i0 = blockIdx.x * 16;
    int d = threadIdx.x, iy = threadIdx.y;
    int tid = iy * 64 + d;

    // Load probabilities (zero-padded)
    for (int idx = tid; idx < 16 * PSW; idx += 256) {
        int row = idx / PSW, col = idx - row * PSW;
        int gi = i0 + row;
        Ps[idx] = (gi < NTOK && col < NTOK)
            ? P[((size_t)bh * NTOK + gi) * NTOK + col] : 0.f;
    }
    __syncthreads();

    float acc[4] = {0.f, 0.f, 0.f, 0.f};
    for (int j0 = 0; j0 < NTOK; j0 += 32) {
        #pragma unroll
        for (int t = 0; t < 8; t++) {
            int e = tid + t * 256;
            int rr = e >> 6, cc = e & 63;
            int gj = j0 + rr;
            vs[rr][cc] = (gj < NTOK)
                ? qkv[((size_t)(b * NTOK + gj) * 3 + 2) * CDIM + hh * HD + cc] : 0.f;
        }
        __syncthreads();
        #pragma unroll
        for (int jj = 0; jj < 32; jj++) {
            float vv = vs[jj][d];
            #pragma unroll
            for (int r = 0; r < 4; r++)
                acc[r] += Ps[(iy + 4 * r) * PSW + j0 + jj] * vv;
        }
        __syncthreads();
    }
    #pragma unroll
    for (int r = 0; r < 4; r++) {
        int i = i0 + iy + 4 * r;
        if (i < NTOK) {
            size_t idx = ((size_t)(b * NTOK) + i) * CDIM + hh * HD + d;
            __nv_bfloat16 h, l;
            split_bf(acc[r], h, l);
            oh[idx] = h; ol[idx] = l;
        }
    }
}

// ---------------------------------------------------------------------------
// seq_pool
// ---------------------------------------------------------------------------
__global__ void pool_kernel(const float* __restrict__ x, const float* __restrict__ pw,
                            const float* __restrict__ pb, float* __restrict__ pooled) {
    int b = blockIdx.x;
    __shared__ float s[NTOK];
    __shared__ float red[32];
    int tid = threadIdx.x, lane = tid & 31, w = tid >> 5;

    for (int n = w; n < NTOK; n += 8) {
        const float* xp = x + ((size_t)b * NTOK + n) * CDIM;
        float acc = 0.f;
        for (int c = lane; c < CDIM; c += 32) acc += xp[c] * pw[c];
        acc = wsum(acc);
        if (lane == 0) s[n] = acc + pb[0];
    }
    __syncthreads();

    float mx = -1e30f;
    for (int n = tid; n < NTOK; n += 256) mx = fmaxf(mx, s[n]);
    mx = wmax(mx);
    if (lane == 0) red[w] = mx;
    __syncthreads();
    if (tid == 0) { float m = red[0]; for (int q = 1; q < 8; q++) m = fmaxf(m, red[q]); red[16] = m; }
    __syncthreads();
    mx = red[16];

    float ps = 0.f;
    for (int n = tid; n < NTOK; n += 256) { float e = expf(s[n] - mx); s[n] = e; ps += e; }
    ps = wsum(ps);
    if (lane == 0) red[w] = ps;
    __syncthreads();
    if (tid == 0) { float t = 0; for (int q = 0; q < 8; q++) t += red[q]; red[17] = 1.f / t; }
    __syncthreads();
    float inv = red[17];

    for (int c = tid; c < CDIM; c += 256) {
        float acc = 0.f;
        for (int n = 0; n < NTOK; n++)
            acc += s[n] * x[((size_t)b * NTOK + n) * CDIM + c];
        pooled[b * CDIM + c] = acc * inv;
    }
}

// ---------------------------------------------------------------------------
// fc
// ---------------------------------------------------------------------------
__global__ void fc_kernel(const float* __restrict__ pooled, const float* __restrict__ fw,
                          const float* __restrict__ fb, float* __restrict__ out) {
    int gw = (blockIdx.x * blockDim.x + threadIdx.x) >> 5;
    int lane = threadIdx.x & 31;
    if (gw >= BATCH * NCLS) return;
    int b = gw / NCLS, o = gw % NCLS;
    const float* pp = pooled + b * CDIM;
    const float* wp = fw + (size_t)o * CDIM;
    float acc = 0.f;
    for (int c = lane; c < CDIM; c += 32) acc += pp[c] * wp[c];
    acc = wsum(acc);
    if (lane == 0) out[gw] = acc + fb[o];
}

// ---------------------------------------------------------------------------
// Launch
// ---------------------------------------------------------------------------
extern "C" void kernel_launch(void* const* d_in, const int* in_sizes, int n_in,
                              void* d_out, int out_size) {
    const float* x_in      = (const float*)d_in[0];
    const float* pos_emb   = (const float*)d_in[1];
    const float* ln0_g     = (const float*)d_in[2];
    const float* ln0_b     = (const float*)d_in[3];
    const float* qkv_w     = (const float*)d_in[4];
    const float* qkv_b     = (const float*)d_in[5];
    const float* qkvln_g   = (const float*)d_in[6];
    const float* qkvln_b   = (const float*)d_in[7];
    const float* scale     = (const float*)d_in[8];
    const float* riem_sc   = (const float*)d_in[9];
    const float* temp      = (const float*)d_in[10];
    const float* bn_g      = (const float*)d_in[11];
    const float* bn_b      = (const float*)d_in[12];
    const float* conv_w    = (const float*)d_in[13];
    const float* conv_b    = (const float*)d_in[14];
    const float* proj_w    = (const float*)d_in[15];
    const float* proj_b    = (const float*)d_in[16];
    const float* ln1_g     = (const float*)d_in[17];
    const float* ln1_b     = (const float*)d_in[18];
    const float* ff1_w     = (const float*)d_in[19];
    const float* ff1_b     = (const float*)d_in[20];
    const float* ff2_w     = (const float*)d_in[21];
    const float* ff2_b     = (const float*)d_in[22];
    const float* norm_g    = (const float*)d_in[23];
    const float* norm_b    = (const float*)d_in[24];
    const float* pool_w    = (const float*)d_in[25];
    const float* pool_b    = (const float*)d_in[26];
    const float* fc_w      = (const float*)d_in[27];
    const float* fc_b      = (const float*)d_in[28];

    float* S = nullptr;
    cudaGetSymbolAddress((void**)&S, g_scratch);
    __nv_bfloat16* BF = nullptr;
    cudaGetSymbolAddress((void**)&BF, g_bf);

    float* gx      = S + OFF_X;
    float* gqkv    = S + OFF_QKV;
    float* gqq     = S + OFF_QQ;
    float* gkk     = S + OFF_KK;
    float* gP      = S + OFF_P;
    float* gQK     = S + OFF_QK;
    float* gpooled = S + OFF_POOLED;

    __nv_bfloat16* wqkv_h  = BF + BO_WQKV_HI,  *wqkv_l  = BF + BO_WQKV_LO;
    __nv_bfloat16* wproj_h = BF + BO_WPROJ_HI, *wproj_l = BF + BO_WPROJ_LO;
    __nv_bfloat16* wff1_h  = BF + BO_WFF1_HI,  *wff1_l  = BF + BO_WFF1_LO;
    __nv_bfloat16* wff2_h  = BF + BO_WFF2_HI,  *wff2_l  = BF + BO_WFF2_LO;
    __nv_bfloat16* h_h = BF + BO_H_HI, *h_l = BF + BO_H_LO;
    __nv_bfloat16* o_h = BF + BO_O_HI, *o_l = BF + BO_O_LO;
    __nv_bfloat16* x_h = BF + BO_X_HI, *x_l = BF + BO_X_LO;
    __nv_bfloat16* f_h = BF + BO_F_HI, *f_l = BF + BO_F_LO;
    __nv_bfloat16* qkv_hh = BF + BO_QKV_HI, *qkv_ll = BF + BO_QKV_LO;

    cudaFuncSetAttribute(gemm_mma<0>, cudaFuncAttributeMaxDynamicSharedMemorySize, GSMEM);
    cudaFuncSetAttribute(gemm_mma<1>, cudaFuncAttributeMaxDynamicSharedMemorySize, GSMEM);
    cudaFuncSetAttribute(gemm_mma<2>, cudaFuncAttributeMaxDynamicSharedMemorySize, GSMEM);
    cudaFuncSetAttribute(qk_mma, cudaFuncAttributeMaxDynamicSharedMemorySize, QKSMEM);

    cvt_hilo_kernel<<<2048, 256>>>((const float4*)qkv_w,  (__nv_bfloat162*)wqkv_h,
                                   (__nv_bfloat162*)wqkv_l,  NB_WQKV / 4);
    cvt_hilo_kernel<<<2048, 256>>>((const float4*)proj_w, (__nv_bfloat162*)wproj_h,
                                   (__nv_bfloat162*)wproj_l, NB_WPROJ / 4);
    cvt_hilo_kernel<<<2048, 256>>>((const float4*)ff1_w,  (__nv_bfloat162*)wff1_h,
                                   (__nv_bfloat162*)wff1_l,  NB_WFF1 / 4);
    cvt_hilo_kernel<<<2048, 256>>>((const float4*)ff2_w,  (__nv_bfloat162*)wff2_h,
                                   (__nv_bfloat162*)wff2_l,  NB_WFF2 / 4);

    addpos_kernel<<<(TOKENS * CDIM + 255) / 256, 256>>>(x_in, pos_emb, gx);

    const int MB = (TOKENS + 127) / 128;  // 25
    for (int l = 0; l < LAYERS; l++) {
        // h = LN0(x) -> bf16 hi/lo
        ln_kernel<1><<<TOKENS, 256, CDIM * sizeof(float)>>>(
            gx, nullptr, h_h, h_l, ln0_g + l * CDIM, ln0_b + l * CDIM, CDIM);
        // qkv = h @ qkv_w^T + b
        gemm_mma<0><<<dim3(QKVDIM / 128, MB), 256, GSMEM>>>(
            h_h, h_l, wqkv_h + (size_t)l * QKVDIM * CDIM, wqkv_l + (size_t)l * QKVDIM * CDIM,
            qkv_b + l * QKVDIM, gqkv, nullptr, nullptr, TOKENS, QKVDIM, CDIM);
        // qkv = LN(qkv) in place + bf16 hi/lo + per-head q/k norms
        ln_qkv_kernel<<<TOKENS, 256>>>(gqkv, qkvln_g + l * QKVDIM,
                                       qkvln_b + l * QKVDIM, qkv_hh, qkv_ll, gqq, gkk);
        // QK dots via tensor cores
        qk_mma<<<dim3(2, 2, BATCH * HEADS), 256, QKSMEM>>>(qkv_hh, qkv_ll, gQK);
        // riem + BN affine + conv + FUSED softmax -> P (probabilities)
        attn_post<<<dim3(NTOK, BATCH), 256>>>(
            gQK, gqq, gkk, scale + l, riem_sc + l, temp + l * 24,
            bn_g + l * 24, bn_b + l * 24, conv_w + l * 288, conv_b + l * 12, gP);
        // o = P @ v (P already softmaxed) -> bf16 hi/lo
        av_prob_kernel<<<dim3(13, BATCH * HEADS), dim3(64, 4)>>>(gP, gqkv, o_h, o_l);
        // x = x + o @ proj_w^T + proj_b
        gemm_mma<1><<<dim3(CDIM / 128, MB), 256, GSMEM>>>(
            o_h, o_l, wproj_h + (size_t)l * CDIM * CDIM, wproj_l + (size_t)l * CDIM * CDIM,
            proj_b + l * CDIM, gx, nullptr, nullptr, TOKENS, CDIM, CDIM);
        // x = LN1(x) in-place + bf16 hi/lo
        ln_kernel<2><<<TOKENS, 256, CDIM * sizeof(float)>>>(
            gx, gx, x_h, x_l, ln1_g + l * CDIM, ln1_b + l * CDIM, CDIM);
        // f = gelu(x @ ff1^T + b) -> bf16 hi/lo
        gemm_mma<2><<<dim3(DFF / 128, MB), 256, GSMEM>>>(
            x_h, x_l, wff1_h + (size_t)l * DFF * CDIM, wff1_l + (size_t)l * DFF * CDIM,
            ff1_b + l * DFF, nullptr, f_h, f_l, TOKENS, DFF, CDIM);
        // x = x + f @ ff2^T + b
        gemm_mma<1><<<dim3(CDIM / 128, MB), 256, GSMEM>>>(
            f_h, f_l, wff2_h + (size_t)l * CDIM * DFF, wff2_l + (size_t)l * CDIM * DFF,
            ff2_b + l * CDIM, gx, nullptr, nullptr, TOKENS, CDIM, DFF);
    }

    ln_kernel<0><<<TOKENS, 256, CDIM * sizeof(float)>>>(
        gx, gx, nullptr, nullptr, norm_g, norm_b, CDIM);
    pool_kernel<<<BATCH, 256>>>(gx, pool_w, pool_b, gpooled);
    fc_kernel<<<(BATCH * NCLS * 32 + 255) / 256, 256>>>(gpooled, fc_w, fc_b,
                                                        (float*)d_out);
}

// round 16
// speedup vs baseline: 1.1682x; 1.0225x over previous
#include <cuda_runtime.h>
#include <cuda_bf16.h>
#include <math.h>
#include <stdint.h>

// ---------------------------------------------------------------------------
// Problem constants
// ---------------------------------------------------------------------------
#define LAYERS 12
#define CDIM   768
#define HEADS  12
#define HD     64
#define NTOK   196
#define BATCH  16
#define DFF    3072
#define NCLS   1000
#define TOKENS (BATCH * NTOK)        // 3136
#define QKVDIM (3 * CDIM)            // 2304
#define NROWS_ATT (BATCH * HEADS * NTOK) // 37632
#define BN_RSTD 0.99999500003749969f

// ---------------------------------------------------------------------------
// fp32 scratch
// ---------------------------------------------------------------------------
#define OFF_X      0
#define OFF_QKV    (OFF_X + (size_t)TOKENS * CDIM)
#define OFF_QQ     (OFF_QKV + (size_t)TOKENS * QKVDIM)
#define OFF_KK     (OFF_QQ + NROWS_ATT)
#define OFF_P      (OFF_KK + NROWS_ATT)
#define OFF_QK     (OFF_P + (size_t)BATCH * HEADS * NTOK * NTOK)
#define OFF_POOLED (OFF_QK + (size_t)BATCH * HEADS * NTOK * NTOK)
#define SCRATCH_TOTAL (OFF_POOLED + BATCH * CDIM)

__device__ __align__(256) float g_scratch[SCRATCH_TOTAL];

// ---------------------------------------------------------------------------
// bf16 scratch
// ---------------------------------------------------------------------------
#define NB_WQKV  ((size_t)LAYERS * QKVDIM * CDIM)
#define NB_WPROJ ((size_t)LAYERS * CDIM * CDIM)
#define NB_WFF1  ((size_t)LAYERS * DFF * CDIM)
#define NB_WFF2  ((size_t)LAYERS * CDIM * DFF)
#define NB_ACT   ((size_t)TOKENS * CDIM)
#define NB_F     ((size_t)TOKENS * DFF)
#define NB_QKVA  ((size_t)TOKENS * QKVDIM)

#define BO_WQKV_HI  ((size_t)0)
#define BO_WQKV_LO  (BO_WQKV_HI + NB_WQKV)
#define BO_WPROJ_HI (BO_WQKV_LO + NB_WQKV)
#define BO_WPROJ_LO (BO_WPROJ_HI + NB_WPROJ)
#define BO_WFF1_HI  (BO_WPROJ_LO + NB_WPROJ)
#define BO_WFF1_LO  (BO_WFF1_HI + NB_WFF1)
#define BO_WFF2_HI  (BO_WFF1_LO + NB_WFF1)
#define BO_WFF2_LO  (BO_WFF2_HI + NB_WFF2)
#define BO_H_HI     (BO_WFF2_LO + NB_WFF2)
#define BO_H_LO     (BO_H_HI + NB_ACT)
#define BO_O_HI     (BO_H_LO + NB_ACT)
#define BO_O_LO     (BO_O_HI + NB_ACT)
#define BO_X_HI     (BO_O_LO + NB_ACT)
#define BO_X_LO     (BO_X_HI + NB_ACT)
#define BO_F_HI     (BO_X_LO + NB_ACT)
#define BO_F_LO     (BO_F_HI + NB_F)
#define BO_QKV_HI   (BO_F_LO + NB_F)
#define BO_QKV_LO   (BO_QKV_HI + NB_QKVA)
#define BF_TOTAL    (BO_QKV_LO + NB_QKVA)

__device__ __align__(256) __nv_bfloat16 g_bf[BF_TOTAL];

// ---------------------------------------------------------------------------
// helpers
// ---------------------------------------------------------------------------
__device__ __forceinline__ uint32_t smem_u32(const void* p) {
    uint32_t a;
    asm("{ .reg .u64 t; cvta.to.shared.u64 t, %1; cvt.u32.u64 %0, t; }"
        : "=r"(a) : "l"(p));
    return a;
}
__device__ __forceinline__ float wsum(float v) {
    #pragma unroll
    for (int o = 16; o; o >>= 1) v += __shfl_xor_sync(0xffffffffu, v, o);
    return v;
}
__device__ __forceinline__ float wmax(float v) {
    #pragma unroll
    for (int o = 16; o; o >>= 1) v = fmaxf(v, __shfl_xor_sync(0xffffffffu, v, o));
    return v;
}
__device__ __forceinline__ void split_bf(float v, __nv_bfloat16& h, __nv_bfloat16& l) {
    h = __float2bfloat16(v);
    l = __float2bfloat16(v - __bfloat162float(h));
}
__device__ __forceinline__ void cp_async16(uint32_t dst, const void* src, int srcsize) {
    asm volatile("cp.async.cg.shared.global [%0], [%1], 16, %2;"
                 :: "r"(dst), "l"(src), "r"(srcsize) : "memory");
}
__device__ __forceinline__ void cp_commit() {
    asm volatile("cp.async.commit_group;" ::: "memory");
}
template <int N>
__device__ __forceinline__ void cp_wait() {
    asm volatile("cp.async.wait_group %0;" :: "n"(N) : "memory");
}
__device__ __forceinline__ void ldsm_x4(uint32_t addr, uint32_t* r) {
    asm volatile("ldmatrix.sync.aligned.m8n8.x4.shared.b16 {%0,%1,%2,%3}, [%4];"
        : "=r"(r[0]), "=r"(r[1]), "=r"(r[2]), "=r"(r[3]) : "r"(addr));
}
__device__ __forceinline__ void ldsm_x2(uint32_t addr, uint32_t* r) {
    asm volatile("ldmatrix.sync.aligned.m8n8.x2.shared.b16 {%0,%1}, [%2];"
        : "=r"(r[0]), "=r"(r[1]) : "r"(addr));
}
__device__ __forceinline__ void mma_bf16(float* d, const uint32_t* a, const uint32_t* b) {
    asm volatile("mma.sync.aligned.m16n8k16.row.col.f32.bf16.bf16.f32 "
        "{%0,%1,%2,%3}, {%4,%5,%6,%7}, {%8,%9}, {%0,%1,%2,%3};"
        : "+f"(d[0]), "+f"(d[1]), "+f"(d[2]), "+f"(d[3])
        : "r"(a[0]), "r"(a[1]), "r"(a[2]), "r"(a[3]), "r"(b[0]), "r"(b[1]));
}

// ---------------------------------------------------------------------------
// fp32 -> bf16 hi/lo conversion (vectorized)
// ---------------------------------------------------------------------------
__global__ void cvt_hilo_kernel(const float4* __restrict__ w,
                                __nv_bfloat162* __restrict__ hi,
                                __nv_bfloat162* __restrict__ lo, size_t n4) {
    size_t i = (size_t)blockIdx.x * blockDim.x + threadIdx.x;
    size_t stride = (size_t)gridDim.x * blockDim.x;
    for (; i < n4; i += stride) {
        float4 v = w[i];
        __nv_bfloat16 h0, l0, h1, l1, h2, l2, h3, l3;
        split_bf(v.x, h0, l0); split_bf(v.y, h1, l1);
        split_bf(v.z, h2, l2); split_bf(v.w, h3, l3);
        __nv_bfloat162 a, b;
        a.x = h0; a.y = h1; b.x = h2; b.y = h3;
        hi[2 * i] = a; hi[2 * i + 1] = b;
        a.x = l0; a.y = l1; b.x = l2; b.y = l3;
        lo[2 * i] = a; lo[2 * i + 1] = b;
    }
}

// ---------------------------------------------------------------------------
// x = x_in + pos_emb
// ---------------------------------------------------------------------------
__global__ void addpos_kernel(const float* __restrict__ x,
                              const float* __restrict__ pe,
                              float* __restrict__ gx) {
    int idx = blockIdx.x * blockDim.x + threadIdx.x;
    if (idx >= TOKENS * CDIM) return;
    int c = idx % CDIM;
    int n = (idx / CDIM) % NTOK;
    gx[idx] = x[idx] + pe[n * CDIM + c];
}

// ---------------------------------------------------------------------------
// LayerNorm, vectorized float4 I/O. MODE 0: fp32. MODE 1: bf16 hi/lo. MODE 2: both.
// D % 4 == 0 required.
// ---------------------------------------------------------------------------
template <int MODE>
__global__ void ln_kernel(const float* __restrict__ in, float* __restrict__ outf,
                          __nv_bfloat16* __restrict__ oh, __nv_bfloat16* __restrict__ ol,
                          const float* __restrict__ g, const float* __restrict__ b,
                          int D) {
    extern __shared__ float row[];
    __shared__ float red[34];
    int r = blockIdx.x;
    int D4 = D >> 2;
    const float4* ip4 = (const float4*)(in + (size_t)r * D);
    float4* row4 = (float4*)row;
    int tid = threadIdx.x, lane = tid & 31, w = tid >> 5;

    float s = 0.f;
    for (int c4 = tid; c4 < D4; c4 += blockDim.x) {
        float4 v = ip4[c4];
        row4[c4] = v;
        s += v.x + v.y + v.z + v.w;
    }
    s = wsum(s);
    if (lane == 0) red[w] = s;
    __syncthreads();
    if (tid == 0) { float t = 0; for (int q = 0; q < 8; q++) t += red[q]; red[32] = t / D; }
    __syncthreads();
    float mean = red[32];

    float vs = 0.f;
    for (int c4 = tid; c4 < D4; c4 += blockDim.x) {
        float4 v = row4[c4];
        float d0 = v.x - mean, d1 = v.y - mean, d2 = v.z - mean, d3 = v.w - mean;
        vs += d0 * d0 + d1 * d1 + d2 * d2 + d3 * d3;
    }
    vs = wsum(vs);
    if (lane == 0) red[w] = vs;
    __syncthreads();
    if (tid == 0) { float t = 0; for (int q = 0; q < 8; q++) t += red[q]; red[33] = rsqrtf(t / D + 1e-5f); }
    __syncthreads();
    float rstd = red[33];

    const float4* g4 = (const float4*)g;
    const float4* b4 = (const float4*)b;
    for (int c4 = tid; c4 < D4; c4 += blockDim.x) {
        float4 v = row4[c4], gg = g4[c4], bb = b4[c4];
        float4 o;
        o.x = (v.x - mean) * rstd * gg.x + bb.x;
        o.y = (v.y - mean) * rstd * gg.y + bb.y;
        o.z = (v.z - mean) * rstd * gg.z + bb.z;
        o.w = (v.w - mean) * rstd * gg.w + bb.w;
        if (MODE == 0 || MODE == 2)
            ((float4*)(outf + (size_t)r * D))[c4] = o;
        if (MODE == 1 || MODE == 2) {
            __nv_bfloat16 h0, l0, h1, l1, h2, l2, h3, l3;
            split_bf(o.x, h0, l0); split_bf(o.y, h1, l1);
            split_bf(o.z, h2, l2); split_bf(o.w, h3, l3);
            __nv_bfloat162* oh2 = (__nv_bfloat162*)(oh + (size_t)r * D);
            __nv_bfloat162* ol2 = (__nv_bfloat162*)(ol + (size_t)r * D);
            __nv_bfloat162 p;
            p.x = h0; p.y = h1; oh2[c4 * 2] = p;
            p.x = h2; p.y = h3; oh2[c4 * 2 + 1] = p;
            p.x = l0; p.y = l1; ol2[c4 * 2] = p;
            p.x = l2; p.y = l3; ol2[c4 * 2 + 1] = p;
        }
    }
}

// ---------------------------------------------------------------------------
// Fused qkv LayerNorm: bf16 hi/lo out ONLY (no fp32 writeback) + per-head norms.
// ---------------------------------------------------------------------------
__global__ void ln_qkv_kernel(const float* __restrict__ qkvbuf,
                              const float* __restrict__ g, const float* __restrict__ b,
                              __nv_bfloat16* __restrict__ oh, __nv_bfloat16* __restrict__ ol,
                              float* __restrict__ qq, float* __restrict__ kk) {
    __shared__ float row[QKVDIM];
    __shared__ float red[34];
    int r = blockIdx.x;
    const float4* ip4 = (const float4*)(qkvbuf + (size_t)r * QKVDIM);
    float4* row4 = (float4*)row;
    int tid = threadIdx.x, lane = tid & 31, w = tid >> 5;
    const int D4 = QKVDIM >> 2;  // 576

    float s = 0.f;
    for (int c4 = tid; c4 < D4; c4 += 256) {
        float4 v = ip4[c4];
        row4[c4] = v;
        s += v.x + v.y + v.z + v.w;
    }
    s = wsum(s);
    if (lane == 0) red[w] = s;
    __syncthreads();
    if (tid == 0) { float t = 0; for (int q = 0; q < 8; q++) t += red[q]; red[32] = t / QKVDIM; }
    __syncthreads();
    float mean = red[32];

    float vs = 0.f;
    for (int c4 = tid; c4 < D4; c4 += 256) {
        float4 v = row4[c4];
        float d0 = v.x - mean, d1 = v.y - mean, d2 = v.z - mean, d3 = v.w - mean;
        vs += d0 * d0 + d1 * d1 + d2 * d2 + d3 * d3;
    }
    vs = wsum(vs);
    if (lane == 0) red[w] = vs;
    __syncthreads();
    if (tid == 0) { float t = 0; for (int q = 0; q < 8; q++) t += red[q]; red[33] = rsqrtf(t / QKVDIM + 1e-5f); }
    __syncthreads();
    float rstd = red[33];

    const float4* g4 = (const float4*)g;
    const float4* b4 = (const float4*)b;
    __nv_bfloat162* oh2 = (__nv_bfloat162*)(oh + (size_t)r * QKVDIM);
    __nv_bfloat162* ol2 = (__nv_bfloat162*)(ol + (size_t)r * QKVDIM);
    for (int c4 = tid; c4 < D4; c4 += 256) {
        float4 v = row4[c4], gg = g4[c4], bb = b4[c4];
        float4 o;
        o.x = (v.x - mean) * rstd * gg.x + bb.x;
        o.y = (v.y - mean) * rstd * gg.y + bb.y;
        o.z = (v.z - mean) * rstd * gg.z + bb.z;
        o.w = (v.w - mean) * rstd * gg.w + bb.w;
        row4[c4] = o;   // keep normalized row in smem for norms
        __nv_bfloat16 h0, l0, h1, l1, h2, l2, h3, l3;
        split_bf(o.x, h0, l0); split_bf(o.y, h1, l1);
        split_bf(o.z, h2, l2); split_bf(o.w, h3, l3);
        __nv_bfloat162 p;
        p.x = h0; p.y = h1; oh2[c4 * 2] = p;
        p.x = h2; p.y = h3; oh2[c4 * 2 + 1] = p;
        p.x = l0; p.y = l1; ol2[c4 * 2] = p;
        p.x = l2; p.y = l3; ol2[c4 * 2 + 1] = p;
    }
    __syncthreads();

    int bb_ = r / NTOK, n = r % NTOK;
    for (int seg = w; seg < 24; seg += 8) {
        int base = seg * 64;
        float v0 = row[base + lane], v1 = row[base + lane + 32];
        float ssum = wsum(v0 * v0 + v1 * v1);
        if (lane == 0) {
            int h = seg % 12;
            float* dst = (seg < 12) ? qq : kk;
            dst[((size_t)bb_ * HEADS + h) * NTOK + n] = ssum;
        }
    }
}

// ---------------------------------------------------------------------------
// mma.sync bf16x3 GEMM (3-stage cp.async ring) — unchanged
// ---------------------------------------------------------------------------
#define APAD 40
#define TILE_BYTES (128 * APAD * 2)
#define STAGE_BYTES (4 * TILE_BYTES)
#define NSTAGE 3
#define GSMEM (NSTAGE * STAGE_BYTES)

__device__ __forceinline__ void load_stage(
    uint32_t sbase, const __nv_bfloat16* __restrict__ Ah,
    const __nv_bfloat16* __restrict__ Al, const __nv_bfloat16* __restrict__ Bh,
    const __nv_bfloat16* __restrict__ Bl, int m0, int n0, int M, int K, int kc,
    int tid) {
    const __nv_bfloat16* gsrc[4] = {Ah, Al, Bh, Bl};
    #pragma unroll
    for (int tI = 0; tI < 4; tI++) {
        bool isA = tI < 2;
        int row0 = isA ? m0 : n0;
        uint32_t tb = sbase + tI * TILE_BYTES;
        #pragma unroll
        for (int c = 0; c < 2; c++) {
            int e = tid + c * 256;
            int rowi = e >> 2, qc = e & 3;
            int gr = row0 + rowi;
            int ok = (!isA || gr < M) ? 16 : 0;
            const __nv_bfloat16* src =
                gsrc[tI] + (size_t)(ok ? gr : row0) * K + kc + qc * 8;
            cp_async16(tb + rowi * 80 + qc * 16, src, ok);
        }
    }
}

template <int EPI>
__global__ __launch_bounds__(256, 1)
void gemm_mma(const __nv_bfloat16* __restrict__ Ah, const __nv_bfloat16* __restrict__ Al,
              const __nv_bfloat16* __restrict__ Bh, const __nv_bfloat16* __restrict__ Bl,
              const float* __restrict__ bias, float* __restrict__ Cf,
              __nv_bfloat16* __restrict__ Ch, __nv_bfloat16* __restrict__ Cl,
              int M, int N, int K) {
    extern __shared__ char smem[];
    uint32_t sb = smem_u32(smem);

    int tid = threadIdx.x, lane = tid & 31, wid = tid >> 5;
    int wm = wid >> 2, wn = wid & 3;
    int m0 = blockIdx.y * 128, n0 = blockIdx.x * 128;
    int NIT = K >> 5;

    float acc[4][4][4];
    #pragma unroll
    for (int i = 0; i < 4; i++)
        #pragma unroll
        for (int j = 0; j < 4; j++)
            #pragma unroll
            for (int q = 0; q < 4; q++) acc[i][j][q] = 0.f;

    int ar = lane & 15, ac = lane >> 4;
    int br = lane & 7, bc = (lane >> 3) & 1;

    load_stage(sb, Ah, Al, Bh, Bl, m0, n0, M, K, 0, tid);
    cp_commit();
    load_stage(sb + STAGE_BYTES, Ah, Al, Bh, Bl, m0, n0, M, K, 32, tid);
    cp_commit();

    int bufidx = 0;
    for (int it = 0; it < NIT; it++) {
        uint32_t buf = sb + (uint32_t)bufidx * STAGE_BYTES;
        if (it + 2 < NIT) {
            int li = (bufidx + 2) % NSTAGE;
            load_stage(sb + (uint32_t)li * STAGE_BYTES,
                       Ah, Al, Bh, Bl, m0, n0, M, K, (it + 2) * 32, tid);
            cp_commit();
            cp_wait<2>();
        } else if (it + 2 == NIT) {
            cp_wait<1>();
        } else {
            cp_wait<0>();
        }
        __syncthreads();

        uint32_t AhB = buf, AlB = buf + TILE_BYTES;
        uint32_t BhB = buf + 2 * TILE_BYTES, BlB = buf + 3 * TILE_BYTES;

        #pragma unroll
        for (int ks = 0; ks < 2; ks++) {
            uint32_t aH[4][4], aL[4][4], bF[4][2];
            int koff = (ks * 16 + ac * 8) * 2;
            int koffb = (ks * 16 + bc * 8) * 2;
            #pragma unroll
            for (int mt = 0; mt < 4; mt++) {
                uint32_t ra = (uint32_t)((wm * 64 + mt * 16 + ar) * 80) + koff;
                ldsm_x4(AhB + ra, aH[mt]);
                ldsm_x4(AlB + ra, aL[mt]);
            }
            #pragma unroll
            for (int nt = 0; nt < 4; nt++) {
                uint32_t rb = (uint32_t)((wn * 32 + nt * 8 + br) * 80) + koffb;
                ldsm_x2(BhB + rb, bF[nt]);
            }
            #pragma unroll
            for (int mt = 0; mt < 4; mt++)
                #pragma unroll
                for (int nt = 0; nt < 4; nt++) {
                    mma_bf16(acc[mt][nt], aH[mt], bF[nt]);
                    mma_bf16(acc[mt][nt], aL[mt], bF[nt]);
                }
            #pragma unroll
            for (int nt = 0; nt < 4; nt++) {
                uint32_t rb = (uint32_t)((wn * 32 + nt * 8 + br) * 80) + koffb;
                ldsm_x2(BlB + rb, bF[nt]);
            }
            #pragma unroll
            for (int mt = 0; mt < 4; mt++)
                #pragma unroll
                for (int nt = 0; nt < 4; nt++)
                    mma_bf16(acc[mt][nt], aH[mt], bF[nt]);
        }
        __syncthreads();
        bufidx = (bufidx + 1) % NSTAGE;
    }

    int qrow = lane >> 2, qcol = 2 * (lane & 3);
    #pragma unroll
    for (int mt = 0; mt < 4; mt++) {
        #pragma unroll
        for (int half = 0; half < 2; half++) {
            int gm = m0 + wm * 64 + mt * 16 + qrow + half * 8;
            if (gm >= M) continue;
            #pragma unroll
            for (int nt = 0; nt < 4; nt++) {
                int gn = n0 + wn * 32 + nt * 8 + qcol;
                float v0 = acc[mt][nt][half * 2 + 0] + bias[gn + 0];
                float v1 = acc[mt][nt][half * 2 + 1] + bias[gn + 1];
                size_t o = (size_t)gm * N + gn;
                if (EPI == 1) { v0 += Cf[o]; v1 += Cf[o + 1]; }
                if (EPI == 2) {
                    v0 = 0.5f * v0 * (1.f + erff(v0 * 0.70710678118654752f));
                    v1 = 0.5f * v1 * (1.f + erff(v1 * 0.70710678118654752f));
                    __nv_bfloat16 h, l;
                    split_bf(v0, h, l); Ch[o] = h;     Cl[o] = l;
                    split_bf(v1, h, l); Ch[o + 1] = h; Cl[o + 1] = l;
                } else {
                    Cf[o] = v0; Cf[o + 1] = v1;
                }
            }
        }
    }
}

// ---------------------------------------------------------------------------
// qk_mma — unchanged
// ---------------------------------------------------------------------------
#define QKPAD 144
#define QKTILE (128 * QKPAD)
#define QKSMEM (4 * QKTILE)

__global__ __launch_bounds__(256, 1)
void qk_mma(const __nv_bfloat16* __restrict__ qkvh,
            const __nv_bfloat16* __restrict__ qkvl,
            float* __restrict__ QK) {
    extern __shared__ char smem[];
    uint32_t sb = smem_u32(smem);

    int tid = threadIdx.x, lane = tid & 31, wid = tid >> 5;
    int wm = wid >> 2, wn = wid & 3;
    int bh = blockIdx.z;
    int b = bh / HEADS, h = bh % HEADS;
    int m0 = blockIdx.y * 128, n0 = blockIdx.x * 128;

    {
        const __nv_bfloat16* srcs[4] = {qkvh, qkvl, qkvh, qkvl};
        int offs[4] = {h * HD, h * HD, CDIM + h * HD, CDIM + h * HD};
        int r0s[4] = {m0, m0, n0, n0};
        #pragma unroll
        for (int tI = 0; tI < 4; tI++) {
            uint32_t tb = sb + tI * QKTILE;
            #pragma unroll
            for (int t = 0; t < 4; t++) {
                int e = tid + t * 256;
                int rowi = e >> 3, qc = e & 7;
                int gr = r0s[tI] + rowi;
                int ok = (gr < NTOK) ? 16 : 0;
                const __nv_bfloat16* src = srcs[tI] +
                    (size_t)(b * NTOK + (ok ? gr : 0)) * QKVDIM + offs[tI] + qc * 8;
                cp_async16(tb + rowi * QKPAD + qc * 16, src, ok);
            }
        }
    }
    cp_commit();
    cp_wait<0>();
    __syncthreads();

    float acc[4][4][4];
    #pragma unroll
    for (int i = 0; i < 4; i++)
        #pragma unroll
        for (int j = 0; j < 4; j++)
            #pragma unroll
            for (int q = 0; q < 4; q++) acc[i][j][q] = 0.f;

    int ar = lane & 15, ac = lane >> 4;
    int br = lane & 7, bc = (lane >> 3) & 1;
    uint32_t qhB = sb, qlB = sb + QKTILE, khB = sb + 2 * QKTILE, klB = sb + 3 * QKTILE;

    #pragma unroll
    for (int ks = 0; ks < 4; ks++) {
        uint32_t aH[4][4], aL[4][4], bF[4][2];
        int koff = (ks * 16 + ac * 8) * 2;
        int koffb = (ks * 16 + bc * 8) * 2;
        #pragma unroll
        for (int mt = 0; mt < 4; mt++) {
            uint32_t ra = (uint32_t)((wm * 64 + mt * 16 + ar) * QKPAD) + koff;
            ldsm_x4(qhB + ra, aH[mt]);
            ldsm_x4(qlB + ra, aL[mt]);
        }
        #pragma unroll
        for (int nt = 0; nt < 4; nt++) {
            uint32_t rb = (uint32_t)((wn * 32 + nt * 8 + br) * QKPAD) + koffb;
            ldsm_x2(khB + rb, bF[nt]);
        }
        #pragma unroll
        for (int mt = 0; mt < 4; mt++)
            #pragma unroll
            for (int nt = 0; nt < 4; nt++) {
                mma_bf16(acc[mt][nt], aH[mt], bF[nt]);
                mma_bf16(acc[mt][nt], aL[mt], bF[nt]);
            }
        #pragma unroll
        for (int nt = 0; nt < 4; nt++) {
            uint32_t rb = (uint32_t)((wn * 32 + nt * 8 + br) * QKPAD) + koffb;
            ldsm_x2(klB + rb, bF[nt]);
        }
        #pragma unroll
        for (int mt = 0; mt < 4; mt++)
            #pragma unroll
            for (int nt = 0; nt < 4; nt++)
                mma_bf16(acc[mt][nt], aH[mt], bF[nt]);
    }

    int qrow = lane >> 2, qcol = 2 * (lane & 3);
    float* Qbase = QK + (size_t)bh * NTOK * NTOK;
    #pragma unroll
    for (int mt = 0; mt < 4; mt++) {
        #pragma unroll
        for (int half = 0; half < 2; half++) {
            int gm = m0 + wm * 64 + mt * 16 + qrow + half * 8;
            if (gm >= NTOK) continue;
            #pragma unroll
            for (int nt = 0; nt < 4; nt++) {
                int gn = n0 + wn * 32 + nt * 8 + qcol;
                if (gn >= NTOK) continue;
                float2 v;
                v.x = acc[mt][nt][half * 2 + 0];
                v.y = acc[mt][nt][half * 2 + 1];
                *(float2*)(Qbase + (size_t)gm * NTOK + gn) = v;
            }
        }
    }
}

// ---------------------------------------------------------------------------
// attn_post: P = softmax(conv(BN(...))) — float4 staging loads.
// ---------------------------------------------------------------------------
__global__ __launch_bounds__(256)
void attn_post(const float* __restrict__ QK, const float* __restrict__ qq,
               const float* __restrict__ kk, const float* __restrict__ scale_l,
               const float* __restrict__ riem_scale_l, const float* __restrict__ temp_l,
               const float* __restrict__ bn_g_l, const float* __restrict__ bn_b_l,
               const float* __restrict__ conv_w_l, const float* __restrict__ conv_b_l,
               float* __restrict__ P) {
    __shared__ float s_qk[HEADS * NTOK];
    __shared__ float s_kk[HEADS * NTOK];
    __shared__ float s_out[HEADS * 224];
    __shared__ float s_qq[HEADS];
    __shared__ float cw[288], mch[24], bch[24], cb[12];

    int i = blockIdx.x, b = blockIdx.y;
    int tid = threadIdx.x;
    int lane = tid & 31, wid = tid >> 5;

    // float4 staging: NTOK = 49 float4 per head row; bases 16B-aligned.
    const int NF4 = HEADS * (NTOK / 4);     // 588
    for (int idx = tid; idx < NF4; idx += 256) {
        int h = idx / (NTOK / 4), j4 = idx - h * (NTOK / 4);
        const float4* qsrc = (const float4*)(QK + (((size_t)b * HEADS + h) * NTOK + i) * NTOK);
        const float4* ksrc = (const float4*)(kk + ((size_t)b * HEADS + h) * NTOK);
        ((float4*)(s_qk + h * NTOK))[j4] = qsrc[j4];
        ((float4*)(s_kk + h * NTOK))[j4] = ksrc[j4];
    }
    if (tid < HEADS) {
        s_qq[tid] = qq[((size_t)b * HEADS + tid) * NTOK + i];
        cb[tid] = conv_b_l[tid];
    }
    for (int idx = tid; idx < 288; idx += 256) cw[idx] = conv_w_l[idx];
    if (tid < 24) {
        mch[tid] = temp_l[tid] * BN_RSTD * bn_g_l[tid];
        bch[tid] = bn_b_l[tid];
    }
    __syncthreads();

    if (tid < NTOK) {
        float scale = scale_l[0], riem = riem_scale_l[0];
        float a[24];
        #pragma unroll
        for (int h = 0; h < HEADS; h++) {
            float qk = s_qk[h * NTOK + tid];
            a[h] = qk * scale;
            float qv = s_qq[h];
            float kv = s_kk[h * NTOK + tid];
            float d2 = qv * qv + kv * kv - 2.f * qk * qk;
            a[HEADS + h] = sqrtf(fmaxf(d2, 0.f) + 1e-12f) * riem;
        }
        #pragma unroll
        for (int c = 0; c < 24; c++) a[c] = a[c] * mch[c] + bch[c];
        #pragma unroll
        for (int hh = 0; hh < HEADS; hh++) {
            float o = cb[hh];
            #pragma unroll
            for (int c = 0; c < 24; c++) o += cw[hh * 24 + c] * a[c];
            s_out[hh * 224 + tid] = o;
        }
    }
    __syncthreads();

    for (int h = wid; h < HEADS; h += 8) {
        const float* rowp = s_out + h * 224;
        float mx = -1e30f;
        for (int c = lane; c < NTOK; c += 32) mx = fmaxf(mx, rowp[c]);
        mx = wmax(mx);
        float s = 0.f;
        for (int c = lane; c < NTOK; c += 32) s += expf(rowp[c] - mx);
        s = wsum(s);
        float inv = 1.f / s;
        float* pdst = P + (((size_t)b * HEADS + h) * NTOK + i) * NTOK;
        for (int c = lane; c < NTOK; c += 32)
            pdst[c] = expf(rowp[c] - mx) * inv;
    }
}

// ---------------------------------------------------------------------------
// av_prob: o = P @ v, P holds probabilities; V read from bf16 hi/lo.
// ---------------------------------------------------------------------------
#define PSW 224

__global__ __launch_bounds__(256)
void av_prob_kernel(const float* __restrict__ P,
                    const __nv_bfloat16* __restrict__ qkvh,
                    const __nv_bfloat16* __restrict__ qkvl,
                    __nv_bfloat16* __restrict__ oh, __nv_bfloat16* __restrict__ ol) {
    __shared__ float Ps[16 * PSW];
    __shared__ float vs[32][64];

    int bh = blockIdx.y;
    int b = bh / HEADS, hh = bh % HEADS;
    int i0 = blockIdx.x * 16;
    int d = threadIdx.x, iy = threadIdx.y;
    int tid = iy * 64 + d;

    // Load probabilities (zero-padded). float4 main body + scalar tail.
    for (int idx = tid; idx < 16 * PSW; idx += 256) {
        int row = idx / PSW, col = idx - row * PSW;
        int gi = i0 + row;
        Ps[idx] = (gi < NTOK && col < NTOK)
            ? P[((size_t)bh * NTOK + gi) * NTOK + col] : 0.f;
    }
    __syncthreads();

    float acc[4] = {0.f, 0.f, 0.f, 0.f};
    for (int j0 = 0; j0 < NTOK; j0 += 32) {
        // V fill via bf16x2 pairs: 32 rows x 32 pairs = 1024 elems, 4 iters.
        #pragma unroll
        for (int t = 0; t < 4; t++) {
            int e = tid + t * 256;
            int rr = e >> 5, c2 = e & 31;
            int gj = j0 + rr;
            float2 v2 = make_float2(0.f, 0.f);
            if (gj < NTOK) {
                size_t goff2 = ((size_t)(b * NTOK + gj) * QKVDIM + 2 * CDIM + hh * HD) / 2 + c2;
                __nv_bfloat162 vh = ((const __nv_bfloat162*)qkvh)[goff2];
                __nv_bfloat162 vl = ((const __nv_bfloat162*)qkvl)[goff2];
                v2.x = __bfloat162float(vh.x) + __bfloat162float(vl.x);
                v2.y = __bfloat162float(vh.y) + __bfloat162float(vl.y);
            }
            vs[rr][c2 * 2] = v2.x;
            vs[rr][c2 * 2 + 1] = v2.y;
        }
        __syncthreads();
        #pragma unroll
        for (int jj = 0; jj < 32; jj++) {
            float vv = vs[jj][d];
            #pragma unroll
            for (int r = 0; r < 4; r++)
                acc[r] += Ps[(iy + 4 * r) * PSW + j0 + jj] * vv;
        }
        __syncthreads();
    }
    #pragma unroll
    for (int r = 0; r < 4; r++) {
        int i = i0 + iy + 4 * r;
        if (i < NTOK) {
            size_t idx = ((size_t)(b * NTOK) + i) * CDIM + hh * HD + d;
            __nv_bfloat16 h, l;
            split_bf(acc[r], h, l);
            oh[idx] = h; ol[idx] = l;
        }
    }
}

// ---------------------------------------------------------------------------
// seq_pool
// ---------------------------------------------------------------------------
__global__ void pool_kernel(const float* __restrict__ x, const float* __restrict__ pw,
                            const float* __restrict__ pb, float* __restrict__ pooled) {
    int b = blockIdx.x;
    __shared__ float s[NTOK];
    __shared__ float red[32];
    int tid = threadIdx.x, lane = tid & 31, w = tid >> 5;

    for (int n = w; n < NTOK; n += 8) {
        const float* xp = x + ((size_t)b * NTOK + n) * CDIM;
        float acc = 0.f;
        for (int c = lane; c < CDIM; c += 32) acc += xp[c] * pw[c];
        acc = wsum(acc);
        if (lane == 0) s[n] = acc + pb[0];
    }
    __syncthreads();

    float mx = -1e30f;
    for (int n = tid; n < NTOK; n += 256) mx = fmaxf(mx, s[n]);
    mx = wmax(mx);
    if (lane == 0) red[w] = mx;
    __syncthreads();
    if (tid == 0) { float m = red[0]; for (int q = 1; q < 8; q++) m = fmaxf(m, red[q]); red[16] = m; }
    __syncthreads();
    mx = red[16];

    float ps = 0.f;
    for (int n = tid; n < NTOK; n += 256) { float e = expf(s[n] - mx); s[n] = e; ps += e; }
    ps = wsum(ps);
    if (lane == 0) red[w] = ps;
    __syncthreads();
    if (tid == 0) { float t = 0; for (int q = 0; q < 8; q++) t += red[q]; red[17] = 1.f / t; }
    __syncthreads();
    float inv = red[17];

    for (int c = tid; c < CDIM; c += 256) {
        float acc = 0.f;
        for (int n = 0; n < NTOK; n++)
            acc += s[n] * x[((size_t)b * NTOK + n) * CDIM + c];
        pooled[b * CDIM + c] = acc * inv;
    }
}

// ---------------------------------------------------------------------------
// fc
// ---------------------------------------------------------------------------
__global__ void fc_kernel(const float* __restrict__ pooled, const float* __restrict__ fw,
                          const float* __restrict__ fb, float* __restrict__ out) {
    int gw = (blockIdx.x * blockDim.x + threadIdx.x) >> 5;
    int lane = threadIdx.x & 31;
    if (gw >= BATCH * NCLS) return;
    int b = gw / NCLS, o = gw % NCLS;
    const float* pp = pooled + b * CDIM;
    const float* wp = fw + (size_t)o * CDIM;
    float acc = 0.f;
    for (int c = lane; c < CDIM; c += 32) acc += pp[c] * wp[c];
    acc = wsum(acc);
    if (lane == 0) out[gw] = acc + fb[o];
}

// ---------------------------------------------------------------------------
// Launch
// ---------------------------------------------------------------------------
extern "C" void kernel_launch(void* const* d_in, const int* in_sizes, int n_in,
                              void* d_out, int out_size) {
    const float* x_in      = (const float*)d_in[0];
    const float* pos_emb   = (const float*)d_in[1];
    const float* ln0_g     = (const float*)d_in[2];
    const float* ln0_b     = (const float*)d_in[3];
    const float* qkv_w     = (const float*)d_in[4];
    const float* qkv_b     = (const float*)d_in[5];
    const float* qkvln_g   = (const float*)d_in[6];
    const float* qkvln_b   = (const float*)d_in[7];
    const float* scale     = (const float*)d_in[8];
    const float* riem_sc   = (const float*)d_in[9];
    const float* temp      = (const float*)d_in[10];
    const float* bn_g      = (const float*)d_in[11];
    const float* bn_b      = (const float*)d_in[12];
    const float* conv_w    = (const float*)d_in[13];
    const float* conv_b    = (const float*)d_in[14];
    const float* proj_w    = (const float*)d_in[15];
    const float* proj_b    = (const float*)d_in[16];
    const float* ln1_g     = (const float*)d_in[17];
    const float* ln1_b     = (const float*)d_in[18];
    const float* ff1_w     = (const float*)d_in[19];
    const float* ff1_b     = (const float*)d_in[20];
    const float* ff2_w     = (const float*)d_in[21];
    const float* ff2_b     = (const float*)d_in[22];
    const float* norm_g    = (const float*)d_in[23];
    const float* norm_b    = (const float*)d_in[24];
    const float* pool_w    = (const float*)d_in[25];
    const float* pool_b    = (const float*)d_in[26];
    const float* fc_w      = (const float*)d_in[27];
    const float* fc_b      = (const float*)d_in[28];

    float* S = nullptr;
    cudaGetSymbolAddress((void**)&S, g_scratch);
    __nv_bfloat16* BF = nullptr;
    cudaGetSymbolAddress((void**)&BF, g_bf);

    float* gx      = S + OFF_X;
    float* gqkv    = S + OFF_QKV;
    float* gqq     = S + OFF_QQ;
    float* gkk     = S + OFF_KK;
    float* gP      = S + OFF_P;
    float* gQK     = S + OFF_QK;
    float* gpooled = S + OFF_POOLED;

    __nv_bfloat16* wqkv_h  = BF + BO_WQKV_HI,  *wqkv_l  = BF + BO_WQKV_LO;
    __nv_bfloat16* wproj_h = BF + BO_WPROJ_HI, *wproj_l = BF + BO_WPROJ_LO;
    __nv_bfloat16* wff1_h  = BF + BO_WFF1_HI,  *wff1_l  = BF + BO_WFF1_LO;
    __nv_bfloat16* wff2_h  = BF + BO_WFF2_HI,  *wff2_l  = BF + BO_WFF2_LO;
    __nv_bfloat16* h_h = BF + BO_H_HI, *h_l = BF + BO_H_LO;
    __nv_bfloat16* o_h = BF + BO_O_HI, *o_l = BF + BO_O_LO;
    __nv_bfloat16* x_h = BF + BO_X_HI, *x_l = BF + BO_X_LO;
    __nv_bfloat16* f_h = BF + BO_F_HI, *f_l = BF + BO_F_LO;
    __nv_bfloat16* qkv_hh = BF + BO_QKV_HI, *qkv_ll = BF + BO_QKV_LO;

    cudaFuncSetAttribute(gemm_mma<0>, cudaFuncAttributeMaxDynamicSharedMemorySize, GSMEM);
    cudaFuncSetAttribute(gemm_mma<1>, cudaFuncAttributeMaxDynamicSharedMemorySize, GSMEM);
    cudaFuncSetAttribute(gemm_mma<2>, cudaFuncAttributeMaxDynamicSharedMemorySize, GSMEM);
    cudaFuncSetAttribute(qk_mma, cudaFuncAttributeMaxDynamicSharedMemorySize, QKSMEM);

    cvt_hilo_kernel<<<2048, 256>>>((const float4*)qkv_w,  (__nv_bfloat162*)wqkv_h,
                                   (__nv_bfloat162*)wqkv_l,  NB_WQKV / 4);
    cvt_hilo_kernel<<<2048, 256>>>((const float4*)proj_w, (__nv_bfloat162*)wproj_h,
                                   (__nv_bfloat162*)wproj_l, NB_WPROJ / 4);
    cvt_hilo_kernel<<<2048, 256>>>((const float4*)ff1_w,  (__nv_bfloat162*)wff1_h,
                                   (__nv_bfloat162*)wff1_l,  NB_WFF1 / 4);
    cvt_hilo_kernel<<<2048, 256>>>((const float4*)ff2_w,  (__nv_bfloat162*)wff2_h,
                                   (__nv_bfloat162*)wff2_l,  NB_WFF2 / 4);

    addpos_kernel<<<(TOKENS * CDIM + 255) / 256, 256>>>(x_in, pos_emb, gx);

    const int MB = (TOKENS + 127) / 128;  // 25
    for (int l = 0; l < LAYERS; l++) {
        // h = LN0(x) -> bf16 hi/lo
        ln_kernel<1><<<TOKENS, 256, CDIM * sizeof(float)>>>(
            gx, nullptr, h_h, h_l, ln0_g + l * CDIM, ln0_b + l * CDIM, CDIM);
        // qkv = h @ qkv_w^T + b (fp32 pre-LN buffer)
        gemm_mma<0><<<dim3(QKVDIM / 128, MB), 256, GSMEM>>>(
            h_h, h_l, wqkv_h + (size_t)l * QKVDIM * CDIM, wqkv_l + (size_t)l * QKVDIM * CDIM,
            qkv_b + l * QKVDIM, gqkv, nullptr, nullptr, TOKENS, QKVDIM, CDIM);
        // qkv = LN(qkv) -> bf16 hi/lo only + per-head q/k norms
        ln_qkv_kernel<<<TOKENS, 256>>>(gqkv, qkvln_g + l * QKVDIM,
                                       qkvln_b + l * QKVDIM, qkv_hh, qkv_ll, gqq, gkk);
        // QK dots via tensor cores
        qk_mma<<<dim3(2, 2, BATCH * HEADS), 256, QKSMEM>>>(qkv_hh, qkv_ll, gQK);
        // riem + BN affine + conv + fused softmax -> P (probabilities)
        attn_post<<<dim3(NTOK, BATCH), 256>>>(
            gQK, gqq, gkk, scale + l, riem_sc + l, temp + l * 24,
            bn_g + l * 24, bn_b + l * 24, conv_w + l * 288, conv_b + l * 12, gP);
        // o = P @ v (V from bf16 hi/lo) -> bf16 hi/lo
        av_prob_kernel<<<dim3(13, BATCH * HEADS), dim3(64, 4)>>>(
            gP, qkv_hh, qkv_ll, o_h, o_l);
        // x = x + o @ proj_w^T + proj_b
        gemm_mma<1><<<dim3(CDIM / 128, MB), 256, GSMEM>>>(
            o_h, o_l, wproj_h + (size_t)l * CDIM * CDIM, wproj_l + (size_t)l * CDIM * CDIM,
            proj_b + l * CDIM, gx, nullptr, nullptr, TOKENS, CDIM, CDIM);
        // x = LN1(x) in-place + bf16 hi/lo
        ln_kernel<2><<<TOKENS, 256, CDIM * sizeof(float)>>>(
            gx, gx, x_h, x_l, ln1_g + l * CDIM, ln1_b + l * CDIM, CDIM);
        // f = gelu(x @ ff1^T + b) -> bf16 hi/lo
        gemm_mma<2><<<dim3(DFF / 128, MB), 256, GSMEM>>>(
            x_h, x_l, wff1_h + (size_t)l * DFF * CDIM, wff1_l + (size_t)l * DFF * CDIM,
            ff1_b + l * DFF, nullptr, f_h, f_l, TOKENS, DFF, CDIM);
        // x = x + f @ ff2^T + b
        gemm_mma<1><<<dim3(CDIM / 128, MB), 256, GSMEM>>>(
            f_h, f_l, wff2_h + (size_t)l * CDIM * DFF, wff2_l + (size_t)l * CDIM * DFF,
            ff2_b + l * CDIM, gx, nullptr, nullptr, TOKENS, CDIM, DFF);
    }

    ln_kernel<0><<<TOKENS, 256, CDIM * sizeof(float)>>>(
        gx, gx, nullptr, nullptr, norm_g, norm_b, CDIM);
    pool_kernel<<<BATCH, 256>>>(gx, pool_w, pool_b, gpooled);
    fc_kernel<<<(BATCH * NCLS * 32 + 255) / 256, 256>>>(gpooled, fc_w, fc_b,
                                                        (float*)d_out);
}

// round 17
// speedup vs baseline: 1.2122x; 1.0376x over previous
#include <cuda_runtime.h>
#include <cuda_bf16.h>
#include <math.h>
#include <stdint.h>

// ---------------------------------------------------------------------------
// Problem constants
// ---------------------------------------------------------------------------
#define LAYERS 12
#define CDIM   768
#define HEADS  12
#define HD     64
#define NTOK   196
#define BATCH  16
#define DFF    3072
#define NCLS   1000
#define TOKENS (BATCH * NTOK)        // 3136
#define QKVDIM (3 * CDIM)            // 2304
#define NROWS_ATT (BATCH * HEADS * NTOK) // 37632
#define BN_RSTD 0.99999500003749969f

// ---------------------------------------------------------------------------
// fp32 scratch
// ---------------------------------------------------------------------------
#define OFF_X      0
#define OFF_QKV    (OFF_X + (size_t)TOKENS * CDIM)
#define OFF_QQ     (OFF_QKV + (size_t)TOKENS * QKVDIM)
#define OFF_KK     (OFF_QQ + NROWS_ATT)
#define OFF_P      (OFF_KK + NROWS_ATT)
#define OFF_QK     (OFF_P + (size_t)BATCH * HEADS * NTOK * NTOK)
#define OFF_POOLED (OFF_QK + (size_t)BATCH * HEADS * NTOK * NTOK)
#define SCRATCH_TOTAL (OFF_POOLED + BATCH * CDIM)

__device__ __align__(256) float g_scratch[SCRATCH_TOTAL];

// ---------------------------------------------------------------------------
// bf16 scratch
// ---------------------------------------------------------------------------
#define NB_WQKV  ((size_t)LAYERS * QKVDIM * CDIM)
#define NB_WPROJ ((size_t)LAYERS * CDIM * CDIM)
#define NB_WFF1  ((size_t)LAYERS * DFF * CDIM)
#define NB_WFF2  ((size_t)LAYERS * CDIM * DFF)
#define NB_ACT   ((size_t)TOKENS * CDIM)
#define NB_F     ((size_t)TOKENS * DFF)
#define NB_QKVA  ((size_t)TOKENS * QKVDIM)

#define BO_WQKV_HI  ((size_t)0)
#define BO_WQKV_LO  (BO_WQKV_HI + NB_WQKV)
#define BO_WPROJ_HI (BO_WQKV_LO + NB_WQKV)
#define BO_WPROJ_LO (BO_WPROJ_HI + NB_WPROJ)
#define BO_WFF1_HI  (BO_WPROJ_LO + NB_WPROJ)
#define BO_WFF1_LO  (BO_WFF1_HI + NB_WFF1)
#define BO_WFF2_HI  (BO_WFF1_LO + NB_WFF1)
#define BO_WFF2_LO  (BO_WFF2_HI + NB_WFF2)
#define BO_H_HI     (BO_WFF2_LO + NB_WFF2)
#define BO_H_LO     (BO_H_HI + NB_ACT)
#define BO_O_HI     (BO_H_LO + NB_ACT)
#define BO_O_LO     (BO_O_HI + NB_ACT)
#define BO_X_HI     (BO_O_LO + NB_ACT)
#define BO_X_LO     (BO_X_HI + NB_ACT)
#define BO_F_HI     (BO_X_LO + NB_ACT)
#define BO_F_LO     (BO_F_HI + NB_F)
#define BO_QKV_HI   (BO_F_LO + NB_F)
#define BO_QKV_LO   (BO_QKV_HI + NB_QKVA)
#define BF_TOTAL    (BO_QKV_LO + NB_QKVA)

__device__ __align__(256) __nv_bfloat16 g_bf[BF_TOTAL];

// ---------------------------------------------------------------------------
// helpers
// ---------------------------------------------------------------------------
__device__ __forceinline__ uint32_t smem_u32(const void* p) {
    uint32_t a;
    asm("{ .reg .u64 t; cvta.to.shared.u64 t, %1; cvt.u32.u64 %0, t; }"
        : "=r"(a) : "l"(p));
    return a;
}
__device__ __forceinline__ float wsum(float v) {
    #pragma unroll
    for (int o = 16; o; o >>= 1) v += __shfl_xor_sync(0xffffffffu, v, o);
    return v;
}
__device__ __forceinline__ float wmax(float v) {
    #pragma unroll
    for (int o = 16; o; o >>= 1) v = fmaxf(v, __shfl_xor_sync(0xffffffffu, v, o));
    return v;
}
__device__ __forceinline__ void split_bf(float v, __nv_bfloat16& h, __nv_bfloat16& l) {
    h = __float2bfloat16(v);
    l = __float2bfloat16(v - __bfloat162float(h));
}
__device__ __forceinline__ void cp_async16(uint32_t dst, const void* src, int srcsize) {
    asm volatile("cp.async.cg.shared.global [%0], [%1], 16, %2;"
                 :: "r"(dst), "l"(src), "r"(srcsize) : "memory");
}
__device__ __forceinline__ void cp_commit() {
    asm volatile("cp.async.commit_group;" ::: "memory");
}
template <int N>
__device__ __forceinline__ void cp_wait() {
    asm volatile("cp.async.wait_group %0;" :: "n"(N) : "memory");
}
__device__ __forceinline__ void ldsm_x4(uint32_t addr, uint32_t* r) {
    asm volatile("ldmatrix.sync.aligned.m8n8.x4.shared.b16 {%0,%1,%2,%3}, [%4];"
        : "=r"(r[0]), "=r"(r[1]), "=r"(r[2]), "=r"(r[3]) : "r"(addr));
}
__device__ __forceinline__ void ldsm_x2(uint32_t addr, uint32_t* r) {
    asm volatile("ldmatrix.sync.aligned.m8n8.x2.shared.b16 {%0,%1}, [%2];"
        : "=r"(r[0]), "=r"(r[1]) : "r"(addr));
}
__device__ __forceinline__ void mma_bf16(float* d, const uint32_t* a, const uint32_t* b) {
    asm volatile("mma.sync.aligned.m16n8k16.row.col.f32.bf16.bf16.f32 "
        "{%0,%1,%2,%3}, {%4,%5,%6,%7}, {%8,%9}, {%0,%1,%2,%3};"
        : "+f"(d[0]), "+f"(d[1]), "+f"(d[2]), "+f"(d[3])
        : "r"(a[0]), "r"(a[1]), "r"(a[2]), "r"(a[3]), "r"(b[0]), "r"(b[1]));
}

// ---------------------------------------------------------------------------
// fp32 -> bf16 hi/lo conversion (vectorized)
// ---------------------------------------------------------------------------
__global__ void cvt_hilo_kernel(const float4* __restrict__ w,
                                __nv_bfloat162* __restrict__ hi,
                                __nv_bfloat162* __restrict__ lo, size_t n4) {
    size_t i = (size_t)blockIdx.x * blockDim.x + threadIdx.x;
    size_t stride = (size_t)gridDim.x * blockDim.x;
    for (; i < n4; i += stride) {
        float4 v = w[i];
        __nv_bfloat16 h0, l0, h1, l1, h2, l2, h3, l3;
        split_bf(v.x, h0, l0); split_bf(v.y, h1, l1);
        split_bf(v.z, h2, l2); split_bf(v.w, h3, l3);
        __nv_bfloat162 a, b;
        a.x = h0; a.y = h1; b.x = h2; b.y = h3;
        hi[2 * i] = a; hi[2 * i + 1] = b;
        a.x = l0; a.y = l1; b.x = l2; b.y = l3;
        lo[2 * i] = a; lo[2 * i + 1] = b;
    }
}

// ---------------------------------------------------------------------------
// x = x_in + pos_emb
// ---------------------------------------------------------------------------
__global__ void addpos_kernel(const float* __restrict__ x,
                              const float* __restrict__ pe,
                              float* __restrict__ gx) {
    int idx = blockIdx.x * blockDim.x + threadIdx.x;
    if (idx >= TOKENS * CDIM) return;
    int c = idx % CDIM;
    int n = (idx / CDIM) % NTOK;
    gx[idx] = x[idx] + pe[n * CDIM + c];
}

// ---------------------------------------------------------------------------
// LayerNorm, vectorized float4 I/O. MODE 0: fp32. MODE 1: bf16 hi/lo. MODE 2: both.
// ---------------------------------------------------------------------------
template <int MODE>
__global__ void ln_kernel(const float* __restrict__ in, float* __restrict__ outf,
                          __nv_bfloat16* __restrict__ oh, __nv_bfloat16* __restrict__ ol,
                          const float* __restrict__ g, const float* __restrict__ b,
                          int D) {
    extern __shared__ float row[];
    __shared__ float red[34];
    int r = blockIdx.x;
    int D4 = D >> 2;
    const float4* ip4 = (const float4*)(in + (size_t)r * D);
    float4* row4 = (float4*)row;
    int tid = threadIdx.x, lane = tid & 31, w = tid >> 5;

    float s = 0.f;
    for (int c4 = tid; c4 < D4; c4 += blockDim.x) {
        float4 v = ip4[c4];
        row4[c4] = v;
        s += v.x + v.y + v.z + v.w;
    }
    s = wsum(s);
    if (lane == 0) red[w] = s;
    __syncthreads();
    if (tid == 0) { float t = 0; for (int q = 0; q < 8; q++) t += red[q]; red[32] = t / D; }
    __syncthreads();
    float mean = red[32];

    float vs = 0.f;
    for (int c4 = tid; c4 < D4; c4 += blockDim.x) {
        float4 v = row4[c4];
        float d0 = v.x - mean, d1 = v.y - mean, d2 = v.z - mean, d3 = v.w - mean;
        vs += d0 * d0 + d1 * d1 + d2 * d2 + d3 * d3;
    }
    vs = wsum(vs);
    if (lane == 0) red[w] = vs;
    __syncthreads();
    if (tid == 0) { float t = 0; for (int q = 0; q < 8; q++) t += red[q]; red[33] = rsqrtf(t / D + 1e-5f); }
    __syncthreads();
    float rstd = red[33];

    const float4* g4 = (const float4*)g;
    const float4* b4 = (const float4*)b;
    for (int c4 = tid; c4 < D4; c4 += blockDim.x) {
        float4 v = row4[c4], gg = g4[c4], bb = b4[c4];
        float4 o;
        o.x = (v.x - mean) * rstd * gg.x + bb.x;
        o.y = (v.y - mean) * rstd * gg.y + bb.y;
        o.z = (v.z - mean) * rstd * gg.z + bb.z;
        o.w = (v.w - mean) * rstd * gg.w + bb.w;
        if (MODE == 0 || MODE == 2)
            ((float4*)(outf + (size_t)r * D))[c4] = o;
        if (MODE == 1 || MODE == 2) {
            __nv_bfloat16 h0, l0, h1, l1, h2, l2, h3, l3;
            split_bf(o.x, h0, l0); split_bf(o.y, h1, l1);
            split_bf(o.z, h2, l2); split_bf(o.w, h3, l3);
            __nv_bfloat162* oh2 = (__nv_bfloat162*)(oh + (size_t)r * D);
            __nv_bfloat162* ol2 = (__nv_bfloat162*)(ol + (size_t)r * D);
            __nv_bfloat162 p;
            p.x = h0; p.y = h1; oh2[c4 * 2] = p;
            p.x = h2; p.y = h3; oh2[c4 * 2 + 1] = p;
            p.x = l0; p.y = l1; ol2[c4 * 2] = p;
            p.x = l2; p.y = l3; ol2[c4 * 2 + 1] = p;
        }
    }
}

// ---------------------------------------------------------------------------
// Fused qkv LayerNorm: bf16 hi/lo out ONLY + per-head norms.
// ---------------------------------------------------------------------------
__global__ void ln_qkv_kernel(const float* __restrict__ qkvbuf,
                              const float* __restrict__ g, const float* __restrict__ b,
                              __nv_bfloat16* __restrict__ oh, __nv_bfloat16* __restrict__ ol,
                              float* __restrict__ qq, float* __restrict__ kk) {
    __shared__ float row[QKVDIM];
    __shared__ float red[34];
    int r = blockIdx.x;
    const float4* ip4 = (const float4*)(qkvbuf + (size_t)r * QKVDIM);
    float4* row4 = (float4*)row;
    int tid = threadIdx.x, lane = tid & 31, w = tid >> 5;
    const int D4 = QKVDIM >> 2;  // 576

    float s = 0.f;
    for (int c4 = tid; c4 < D4; c4 += 256) {
        float4 v = ip4[c4];
        row4[c4] = v;
        s += v.x + v.y + v.z + v.w;
    }
    s = wsum(s);
    if (lane == 0) red[w] = s;
    __syncthreads();
    if (tid == 0) { float t = 0; for (int q = 0; q < 8; q++) t += red[q]; red[32] = t / QKVDIM; }
    __syncthreads();
    float mean = red[32];

    float vs = 0.f;
    for (int c4 = tid; c4 < D4; c4 += 256) {
        float4 v = row4[c4];
        float d0 = v.x - mean, d1 = v.y - mean, d2 = v.z - mean, d3 = v.w - mean;
        vs += d0 * d0 + d1 * d1 + d2 * d2 + d3 * d3;
    }
    vs = wsum(vs);
    if (lane == 0) red[w] = vs;
    __syncthreads();
    if (tid == 0) { float t = 0; for (int q = 0; q < 8; q++) t += red[q]; red[33] = rsqrtf(t / QKVDIM + 1e-5f); }
    __syncthreads();
    float rstd = red[33];

    const float4* g4 = (const float4*)g;
    const float4* b4 = (const float4*)b;
    __nv_bfloat162* oh2 = (__nv_bfloat162*)(oh + (size_t)r * QKVDIM);
    __nv_bfloat162* ol2 = (__nv_bfloat162*)(ol + (size_t)r * QKVDIM);
    for (int c4 = tid; c4 < D4; c4 += 256) {
        float4 v = row4[c4], gg = g4[c4], bb = b4[c4];
        float4 o;
        o.x = (v.x - mean) * rstd * gg.x + bb.x;
        o.y = (v.y - mean) * rstd * gg.y + bb.y;
        o.z = (v.z - mean) * rstd * gg.z + bb.z;
        o.w = (v.w - mean) * rstd * gg.w + bb.w;
        row4[c4] = o;
        __nv_bfloat16 h0, l0, h1, l1, h2, l2, h3, l3;
        split_bf(o.x, h0, l0); split_bf(o.y, h1, l1);
        split_bf(o.z, h2, l2); split_bf(o.w, h3, l3);
        __nv_bfloat162 p;
        p.x = h0; p.y = h1; oh2[c4 * 2] = p;
        p.x = h2; p.y = h3; oh2[c4 * 2 + 1] = p;
        p.x = l0; p.y = l1; ol2[c4 * 2] = p;
        p.x = l2; p.y = l3; ol2[c4 * 2 + 1] = p;
    }
    __syncthreads();

    int bb_ = r / NTOK, n = r % NTOK;
    for (int seg = w; seg < 24; seg += 8) {
        int base = seg * 64;
        float v0 = row[base + lane], v1 = row[base + lane + 32];
        float ssum = wsum(v0 * v0 + v1 * v1);
        if (lane == 0) {
            int h = seg % 12;
            float* dst = (seg < 12) ? qq : kk;
            dst[((size_t)bb_ * HEADS + h) * NTOK + n] = ssum;
        }
    }
}

// ---------------------------------------------------------------------------
// mma.sync bf16x3 GEMM: 2-stage ring, 2 CTAs/SM.
// ---------------------------------------------------------------------------
#define APAD 40
#define TILE_BYTES (128 * APAD * 2)
#define STAGE_BYTES (4 * TILE_BYTES)
#define NSTAGE 2
#define GSMEM (NSTAGE * STAGE_BYTES)   // 81920

__device__ __forceinline__ void load_stage(
    uint32_t sbase, const __nv_bfloat16* __restrict__ Ah,
    const __nv_bfloat16* __restrict__ Al, const __nv_bfloat16* __restrict__ Bh,
    const __nv_bfloat16* __restrict__ Bl, int m0, int n0, int M, int K, int kc,
    int tid) {
    const __nv_bfloat16* gsrc[4] = {Ah, Al, Bh, Bl};
    #pragma unroll
    for (int tI = 0; tI < 4; tI++) {
        bool isA = tI < 2;
        int row0 = isA ? m0 : n0;
        uint32_t tb = sbase + tI * TILE_BYTES;
        #pragma unroll
        for (int c = 0; c < 2; c++) {
            int e = tid + c * 256;
            int rowi = e >> 2, qc = e & 3;
            int gr = row0 + rowi;
            int ok = (!isA || gr < M) ? 16 : 0;
            const __nv_bfloat16* src =
                gsrc[tI] + (size_t)(ok ? gr : row0) * K + kc + qc * 8;
            cp_async16(tb + rowi * 80 + qc * 16, src, ok);
        }
    }
}

template <int EPI>
__global__ __launch_bounds__(256, 2)
void gemm_mma(const __nv_bfloat16* __restrict__ Ah, const __nv_bfloat16* __restrict__ Al,
              const __nv_bfloat16* __restrict__ Bh, const __nv_bfloat16* __restrict__ Bl,
              const float* __restrict__ bias, float* __restrict__ Cf,
              __nv_bfloat16* __restrict__ Ch, __nv_bfloat16* __restrict__ Cl,
              int M, int N, int K) {
    extern __shared__ char smem[];
    uint32_t sb = smem_u32(smem);

    int tid = threadIdx.x, lane = tid & 31, wid = tid >> 5;
    int wm = wid >> 2, wn = wid & 3;
    int m0 = blockIdx.y * 128, n0 = blockIdx.x * 128;
    int NIT = K >> 5;

    float acc[4][4][4];
    #pragma unroll
    for (int i = 0; i < 4; i++)
        #pragma unroll
        for (int j = 0; j < 4; j++)
            #pragma unroll
            for (int q = 0; q < 4; q++) acc[i][j][q] = 0.f;

    int ar = lane & 15, ac = lane >> 4;
    int br = lane & 7, bc = (lane >> 3) & 1;

    load_stage(sb, Ah, Al, Bh, Bl, m0, n0, M, K, 0, tid);
    cp_commit();

    for (int it = 0; it < NIT; it++) {
        uint32_t buf = sb + (uint32_t)(it & 1) * STAGE_BYTES;
        if (it + 1 < NIT) {
            load_stage(sb + (uint32_t)((it + 1) & 1) * STAGE_BYTES,
                       Ah, Al, Bh, Bl, m0, n0, M, K, (it + 1) * 32, tid);
            cp_commit();
            cp_wait<1>();
        } else {
            cp_wait<0>();
        }
        __syncthreads();

        uint32_t AhB = buf, AlB = buf + TILE_BYTES;
        uint32_t BhB = buf + 2 * TILE_BYTES, BlB = buf + 3 * TILE_BYTES;

        #pragma unroll
        for (int ks = 0; ks < 2; ks++) {
            uint32_t aH[4][4], aL[4][4], bF[4][2];
            int koff = (ks * 16 + ac * 8) * 2;
            int koffb = (ks * 16 + bc * 8) * 2;
            #pragma unroll
            for (int mt = 0; mt < 4; mt++) {
                uint32_t ra = (uint32_t)((wm * 64 + mt * 16 + ar) * 80) + koff;
                ldsm_x4(AhB + ra, aH[mt]);
                ldsm_x4(AlB + ra, aL[mt]);
            }
            #pragma unroll
            for (int nt = 0; nt < 4; nt++) {
                uint32_t rb = (uint32_t)((wn * 32 + nt * 8 + br) * 80) + koffb;
                ldsm_x2(BhB + rb, bF[nt]);
            }
            #pragma unroll
            for (int mt = 0; mt < 4; mt++)
                #pragma unroll
                for (int nt = 0; nt < 4; nt++) {
                    mma_bf16(acc[mt][nt], aH[mt], bF[nt]);
                    mma_bf16(acc[mt][nt], aL[mt], bF[nt]);
                }
            #pragma unroll
            for (int nt = 0; nt < 4; nt++) {
                uint32_t rb = (uint32_t)((wn * 32 + nt * 8 + br) * 80) + koffb;
                ldsm_x2(BlB + rb, bF[nt]);
            }
            #pragma unroll
            for (int mt = 0; mt < 4; mt++)
                #pragma unroll
                for (int nt = 0; nt < 4; nt++)
                    mma_bf16(acc[mt][nt], aH[mt], bF[nt]);
        }
        __syncthreads();
    }

    int qrow = lane >> 2, qcol = 2 * (lane & 3);
    #pragma unroll
    for (int mt = 0; mt < 4; mt++) {
        #pragma unroll
        for (int half = 0; half < 2; half++) {
            int gm = m0 + wm * 64 + mt * 16 + qrow + half * 8;
            if (gm >= M) continue;
            #pragma unroll
            for (int nt = 0; nt < 4; nt++) {
                int gn = n0 + wn * 32 + nt * 8 + qcol;
                float v0 = acc[mt][nt][half * 2 + 0] + bias[gn + 0];
                float v1 = acc[mt][nt][half * 2 + 1] + bias[gn + 1];
                size_t o = (size_t)gm * N + gn;
                if (EPI == 1) { v0 += Cf[o]; v1 += Cf[o + 1]; }
                if (EPI == 2) {
                    v0 = 0.5f * v0 * (1.f + erff(v0 * 0.70710678118654752f));
                    v1 = 0.5f * v1 * (1.f + erff(v1 * 0.70710678118654752f));
                    __nv_bfloat16 h, l;
                    split_bf(v0, h, l); Ch[o] = h;     Cl[o] = l;
                    split_bf(v1, h, l); Ch[o + 1] = h; Cl[o + 1] = l;
                } else {
                    Cf[o] = v0; Cf[o + 1] = v1;
                }
            }
        }
    }
}

// ---------------------------------------------------------------------------
// qk_mma (2 CTAs/SM hint)
// ---------------------------------------------------------------------------
#define QKPAD 144
#define QKTILE (128 * QKPAD)
#define QKSMEM (4 * QKTILE)

__global__ __launch_bounds__(256, 2)
void qk_mma(const __nv_bfloat16* __restrict__ qkvh,
            const __nv_bfloat16* __restrict__ qkvl,
            float* __restrict__ QK) {
    extern __shared__ char smem[];
    uint32_t sb = smem_u32(smem);

    int tid = threadIdx.x, lane = tid & 31, wid = tid >> 5;
    int wm = wid >> 2, wn = wid & 3;
    int bh = blockIdx.z;
    int b = bh / HEADS, h = bh % HEADS;
    int m0 = blockIdx.y * 128, n0 = blockIdx.x * 128;

    {
        const __nv_bfloat16* srcs[4] = {qkvh, qkvl, qkvh, qkvl};
        int offs[4] = {h * HD, h * HD, CDIM + h * HD, CDIM + h * HD};
        int r0s[4] = {m0, m0, n0, n0};
        #pragma unroll
        for (int tI = 0; tI < 4; tI++) {
            uint32_t tb = sb + tI * QKTILE;
            #pragma unroll
            for (int t = 0; t < 4; t++) {
                int e = tid + t * 256;
                int rowi = e >> 3, qc = e & 7;
                int gr = r0s[tI] + rowi;
                int ok = (gr < NTOK) ? 16 : 0;
                const __nv_bfloat16* src = srcs[tI] +
                    (size_t)(b * NTOK + (ok ? gr : 0)) * QKVDIM + offs[tI] + qc * 8;
                cp_async16(tb + rowi * QKPAD + qc * 16, src, ok);
            }
        }
    }
    cp_commit();
    cp_wait<0>();
    __syncthreads();

    float acc[4][4][4];
    #pragma unroll
    for (int i = 0; i < 4; i++)
        #pragma unroll
        for (int j = 0; j < 4; j++)
            #pragma unroll
            for (int q = 0; q < 4; q++) acc[i][j][q] = 0.f;

    int ar = lane & 15, ac = lane >> 4;
    int br = lane & 7, bc = (lane >> 3) & 1;
    uint32_t qhB = sb, qlB = sb + QKTILE, khB = sb + 2 * QKTILE, klB = sb + 3 * QKTILE;

    #pragma unroll
    for (int ks = 0; ks < 4; ks++) {
        uint32_t aH[4][4], aL[4][4], bF[4][2];
        int koff = (ks * 16 + ac * 8) * 2;
        int koffb = (ks * 16 + bc * 8) * 2;
        #pragma unroll
        for (int mt = 0; mt < 4; mt++) {
            uint32_t ra = (uint32_t)((wm * 64 + mt * 16 + ar) * QKPAD) + koff;
            ldsm_x4(qhB + ra, aH[mt]);
            ldsm_x4(qlB + ra, aL[mt]);
        }
        #pragma unroll
        for (int nt = 0; nt < 4; nt++) {
            uint32_t rb = (uint32_t)((wn * 32 + nt * 8 + br) * QKPAD) + koffb;
            ldsm_x2(khB + rb, bF[nt]);
        }
        #pragma unroll
        for (int mt = 0; mt < 4; mt++)
            #pragma unroll
            for (int nt = 0; nt < 4; nt++) {
                mma_bf16(acc[mt][nt], aH[mt], bF[nt]);
                mma_bf16(acc[mt][nt], aL[mt], bF[nt]);
            }
        #pragma unroll
        for (int nt = 0; nt < 4; nt++) {
            uint32_t rb = (uint32_t)((wn * 32 + nt * 8 + br) * QKPAD) + koffb;
            ldsm_x2(klB + rb, bF[nt]);
        }
        #pragma unroll
        for (int mt = 0; mt < 4; mt++)
            #pragma unroll
            for (int nt = 0; nt < 4; nt++)
                mma_bf16(acc[mt][nt], aH[mt], bF[nt]);
    }

    int qrow = lane >> 2, qcol = 2 * (lane & 3);
    float* Qbase = QK + (size_t)bh * NTOK * NTOK;
    #pragma unroll
    for (int mt = 0; mt < 4; mt++) {
        #pragma unroll
        for (int half = 0; half < 2; half++) {
            int gm = m0 + wm * 64 + mt * 16 + qrow + half * 8;
            if (gm >= NTOK) continue;
            #pragma unroll
            for (int nt = 0; nt < 4; nt++) {
                int gn = n0 + wn * 32 + nt * 8 + qcol;
                if (gn >= NTOK) continue;
                float2 v;
                v.x = acc[mt][nt][half * 2 + 0];
                v.y = acc[mt][nt][half * 2 + 1];
                *(float2*)(Qbase + (size_t)gm * NTOK + gn) = v;
            }
        }
    }
}

// ---------------------------------------------------------------------------
// attn_post: P = softmax(conv(BN(...))) — float4 staging loads.
// ---------------------------------------------------------------------------
__global__ __launch_bounds__(256)
void attn_post(const float* __restrict__ QK, const float* __restrict__ qq,
               const float* __restrict__ kk, const float* __restrict__ scale_l,
               const float* __restrict__ riem_scale_l, const float* __restrict__ temp_l,
               const float* __restrict__ bn_g_l, const float* __restrict__ bn_b_l,
               const float* __restrict__ conv_w_l, const float* __restrict__ conv_b_l,
               float* __restrict__ P) {
    __shared__ float s_qk[HEADS * NTOK];
    __shared__ float s_kk[HEADS * NTOK];
    __shared__ float s_out[HEADS * 224];
    __shared__ float s_qq[HEADS];
    __shared__ float cw[288], mch[24], bch[24], cb[12];

    int i = blockIdx.x, b = blockIdx.y;
    int tid = threadIdx.x;
    int lane = tid & 31, wid = tid >> 5;

    const int NF4 = HEADS * (NTOK / 4);     // 588
    for (int idx = tid; idx < NF4; idx += 256) {
        int h = idx / (NTOK / 4), j4 = idx - h * (NTOK / 4);
        const float4* qsrc = (const float4*)(QK + (((size_t)b * HEADS + h) * NTOK + i) * NTOK);
        const float4* ksrc = (const float4*)(kk + ((size_t)b * HEADS + h) * NTOK);
        ((float4*)(s_qk + h * NTOK))[j4] = qsrc[j4];
        ((float4*)(s_kk + h * NTOK))[j4] = ksrc[j4];
    }
    if (tid < HEADS) {
        s_qq[tid] = qq[((size_t)b * HEADS + tid) * NTOK + i];
        cb[tid] = conv_b_l[tid];
    }
    for (int idx = tid; idx < 288; idx += 256) cw[idx] = conv_w_l[idx];
    if (tid < 24) {
        mch[tid] = temp_l[tid] * BN_RSTD * bn_g_l[tid];
        bch[tid] = bn_b_l[tid];
    }
    __syncthreads();

    if (tid < NTOK) {
        float scale = scale_l[0], riem = riem_scale_l[0];
        float a[24];
        #pragma unroll
        for (int h = 0; h < HEADS; h++) {
            float qk = s_qk[h * NTOK + tid];
            a[h] = qk * scale;
            float qv = s_qq[h];
            float kv = s_kk[h * NTOK + tid];
            float d2 = qv * qv + kv * kv - 2.f * qk * qk;
            a[HEADS + h] = sqrtf(fmaxf(d2, 0.f) + 1e-12f) * riem;
        }
        #pragma unroll
        for (int c = 0; c < 24; c++) a[c] = a[c] * mch[c] + bch[c];
        #pragma unroll
        for (int hh = 0; hh < HEADS; hh++) {
            float o = cb[hh];
            #pragma unroll
            for (int c = 0; c < 24; c++) o += cw[hh * 24 + c] * a[c];
            s_out[hh * 224 + tid] = o;
        }
    }
    __syncthreads();

    for (int h = wid; h < HEADS; h += 8) {
        const float* rowp = s_out + h * 224;
        float mx = -1e30f;
        for (int c = lane; c < NTOK; c += 32) mx = fmaxf(mx, rowp[c]);
        mx = wmax(mx);
        float s = 0.f;
        for (int c = lane; c < NTOK; c += 32) s += expf(rowp[c] - mx);
        s = wsum(s);
        float inv = 1.f / s;
        float* pdst = P + (((size_t)b * HEADS + h) * NTOK + i) * NTOK;
        for (int c = lane; c < NTOK; c += 32)
            pdst[c] = expf(rowp[c] - mx) * inv;
    }
}

// ---------------------------------------------------------------------------
// av_prob: o = P @ v, P holds probabilities; V loaded ONCE to smem (dynamic).
// smem: Ps[16*224] floats + vs[196*64] floats = 64512 B.
// ---------------------------------------------------------------------------
#define PSW 224
#define AV_SMEM ((16 * PSW + NTOK * 64) * 4)

__global__ __launch_bounds__(256)
void av_prob_kernel(const float* __restrict__ P,
                    const __nv_bfloat16* __restrict__ qkvh,
                    const __nv_bfloat16* __restrict__ qkvl,
                    __nv_bfloat16* __restrict__ oh, __nv_bfloat16* __restrict__ ol) {
    extern __shared__ float dsm[];
    float* Ps = dsm;                 // 16 x 224
    float* vsm = dsm + 16 * PSW;     // 196 x 64

    int bh = blockIdx.y;
    int b = bh / HEADS, hh = bh % HEADS;
    int i0 = blockIdx.x * 16;
    int d = threadIdx.x, iy = threadIdx.y;
    int tid = iy * 64 + d;

    // Load probabilities (zero-padded)
    for (int idx = tid; idx < 16 * PSW; idx += 256) {
        int row = idx / PSW, col = idx - row * PSW;
        int gi = i0 + row;
        Ps[idx] = (gi < NTOK && col < NTOK)
            ? P[((size_t)bh * NTOK + gi) * NTOK + col] : 0.f;
    }
    // Load full V tile once (bf16 hi+lo pairs -> fp32)
    for (int idx = tid; idx < NTOK * 32; idx += 256) {
        int rr = idx >> 5, c2 = idx & 31;
        size_t goff2 = ((size_t)(b * NTOK + rr) * QKVDIM + 2 * CDIM + hh * HD) / 2 + c2;
        __nv_bfloat162 vh = ((const __nv_bfloat162*)qkvh)[goff2];
        __nv_bfloat162 vl = ((const __nv_bfloat162*)qkvl)[goff2];
        vsm[rr * 64 + c2 * 2]     = __bfloat162float(vh.x) + __bfloat162float(vl.x);
        vsm[rr * 64 + c2 * 2 + 1] = __bfloat162float(vh.y) + __bfloat162float(vl.y);
    }
    __syncthreads();

    float acc[4] = {0.f, 0.f, 0.f, 0.f};
    #pragma unroll 4
    for (int jj = 0; jj < NTOK; jj++) {
        float vv = vsm[jj * 64 + d];
        #pragma unroll
        for (int r = 0; r < 4; r++)
            acc[r] += Ps[(iy + 4 * r) * PSW + jj] * vv;
    }
    #pragma unroll
    for (int r = 0; r < 4; r++) {
        int i = i0 + iy + 4 * r;
        if (i < NTOK) {
            size_t idx = ((size_t)(b * NTOK) + i) * CDIM + hh * HD + d;
            __nv_bfloat16 h, l;
            split_bf(acc[r], h, l);
            oh[idx] = h; ol[idx] = l;
        }
    }
}

// ---------------------------------------------------------------------------
// seq_pool
// ---------------------------------------------------------------------------
__global__ void pool_kernel(const float* __restrict__ x, const float* __restrict__ pw,
                            const float* __restrict__ pb, float* __restrict__ pooled) {
    int b = blockIdx.x;
    __shared__ float s[NTOK];
    __shared__ float red[32];
    int tid = threadIdx.x, lane = tid & 31, w = tid >> 5;

    for (int n = w; n < NTOK; n += 8) {
        const float* xp = x + ((size_t)b * NTOK + n) * CDIM;
        float acc = 0.f;
        for (int c = lane; c < CDIM; c += 32) acc += xp[c] * pw[c];
        acc = wsum(acc);
        if (lane == 0) s[n] = acc + pb[0];
    }
    __syncthreads();

    float mx = -1e30f;
    for (int n = tid; n < NTOK; n += 256) mx = fmaxf(mx, s[n]);
    mx = wmax(mx);
    if (lane == 0) red[w] = mx;
    __syncthreads();
    if (tid == 0) { float m = red[0]; for (int q = 1; q < 8; q++) m = fmaxf(m, red[q]); red[16] = m; }
    __syncthreads();
    mx = red[16];

    float ps = 0.f;
    for (int n = tid; n < NTOK; n += 256) { float e = expf(s[n] - mx); s[n] = e; ps += e; }
    ps = wsum(ps);
    if (lane == 0) red[w] = ps;
    __syncthreads();
    if (tid == 0) { float t = 0; for (int q = 0; q < 8; q++) t += red[q]; red[17] = 1.f / t; }
    __syncthreads();
    float inv = red[17];

    for (int c = tid; c < CDIM; c += 256) {
        float acc = 0.f;
        for (int n = 0; n < NTOK; n++)
            acc += s[n] * x[((size_t)b * NTOK + n) * CDIM + c];
        pooled[b * CDIM + c] = acc * inv;
    }
}

// ---------------------------------------------------------------------------
// fc
// ---------------------------------------------------------------------------
__global__ void fc_kernel(const float* __restrict__ pooled, const float* __restrict__ fw,
                          const float* __restrict__ fb, float* __restrict__ out) {
    int gw = (blockIdx.x * blockDim.x + threadIdx.x) >> 5;
    int lane = threadIdx.x & 31;
    if (gw >= BATCH * NCLS) return;
    int b = gw / NCLS, o = gw % NCLS;
    const float* pp = pooled + b * CDIM;
    const float* wp = fw + (size_t)o * CDIM;
    float acc = 0.f;
    for (int c = lane; c < CDIM; c += 32) acc += pp[c] * wp[c];
    acc = wsum(acc);
    if (lane == 0) out[gw] = acc + fb[o];
}

// ---------------------------------------------------------------------------
// Launch
// ---------------------------------------------------------------------------
extern "C" void kernel_launch(void* const* d_in, const int* in_sizes, int n_in,
                              void* d_out, int out_size) {
    const float* x_in      = (const float*)d_in[0];
    const float* pos_emb   = (const float*)d_in[1];
    const float* ln0_g     = (const float*)d_in[2];
    const float* ln0_b     = (const float*)d_in[3];
    const float* qkv_w     = (const float*)d_in[4];
    const float* qkv_b     = (const float*)d_in[5];
    const float* qkvln_g   = (const float*)d_in[6];
    const float* qkvln_b   = (const float*)d_in[7];
    const float* scale     = (const float*)d_in[8];
    const float* riem_sc   = (const float*)d_in[9];
    const float* temp      = (const float*)d_in[10];
    const float* bn_g      = (const float*)d_in[11];
    const float* bn_b      = (const float*)d_in[12];
    const float* conv_w    = (const float*)d_in[13];
    const float* conv_b    = (const float*)d_in[14];
    const float* proj_w    = (const float*)d_in[15];
    const float* proj_b    = (const float*)d_in[16];
    const float* ln1_g     = (const float*)d_in[17];
    const float* ln1_b     = (const float*)d_in[18];
    const float* ff1_w     = (const float*)d_in[19];
    const float* ff1_b     = (const float*)d_in[20];
    const float* ff2_w     = (const float*)d_in[21];
    const float* ff2_b     = (const float*)d_in[22];
    const float* norm_g    = (const float*)d_in[23];
    const float* norm_b    = (const float*)d_in[24];
    const float* pool_w    = (const float*)d_in[25];
    const float* pool_b    = (const float*)d_in[26];
    const float* fc_w      = (const float*)d_in[27];
    const float* fc_b      = (const float*)d_in[28];

    float* S = nullptr;
    cudaGetSymbolAddress((void**)&S, g_scratch);
    __nv_bfloat16* BF = nullptr;
    cudaGetSymbolAddress((void**)&BF, g_bf);

    float* gx      = S + OFF_X;
    float* gqkv    = S + OFF_QKV;
    float* gqq     = S + OFF_QQ;
    float* gkk     = S + OFF_KK;
    float* gP      = S + OFF_P;
    float* gQK     = S + OFF_QK;
    float* gpooled = S + OFF_POOLED;

    __nv_bfloat16* wqkv_h  = BF + BO_WQKV_HI,  *wqkv_l  = BF + BO_WQKV_LO;
    __nv_bfloat16* wproj_h = BF + BO_WPROJ_HI, *wproj_l = BF + BO_WPROJ_LO;
    __nv_bfloat16* wff1_h  = BF + BO_WFF1_HI,  *wff1_l  = BF + BO_WFF1_LO;
    __nv_bfloat16* wff2_h  = BF + BO_WFF2_HI,  *wff2_l  = BF + BO_WFF2_LO;
    __nv_bfloat16* h_h = BF + BO_H_HI, *h_l = BF + BO_H_LO;
    __nv_bfloat16* o_h = BF + BO_O_HI, *o_l = BF + BO_O_LO;
    __nv_bfloat16* x_h = BF + BO_X_HI, *x_l = BF + BO_X_LO;
    __nv_bfloat16* f_h = BF + BO_F_HI, *f_l = BF + BO_F_LO;
    __nv_bfloat16* qkv_hh = BF + BO_QKV_HI, *qkv_ll = BF + BO_QKV_LO;

    cudaFuncSetAttribute(gemm_mma<0>, cudaFuncAttributeMaxDynamicSharedMemorySize, GSMEM);
    cudaFuncSetAttribute(gemm_mma<1>, cudaFuncAttributeMaxDynamicSharedMemorySize, GSMEM);
    cudaFuncSetAttribute(gemm_mma<2>, cudaFuncAttributeMaxDynamicSharedMemorySize, GSMEM);
    cudaFuncSetAttribute(qk_mma, cudaFuncAttributeMaxDynamicSharedMemorySize, QKSMEM);
    cudaFuncSetAttribute(av_prob_kernel, cudaFuncAttributeMaxDynamicSharedMemorySize, AV_SMEM);

    cvt_hilo_kernel<<<2048, 256>>>((const float4*)qkv_w,  (__nv_bfloat162*)wqkv_h,
                                   (__nv_bfloat162*)wqkv_l,  NB_WQKV / 4);
    cvt_hilo_kernel<<<2048, 256>>>((const float4*)proj_w, (__nv_bfloat162*)wproj_h,
                                   (__nv_bfloat162*)wproj_l, NB_WPROJ / 4);
    cvt_hilo_kernel<<<2048, 256>>>((const float4*)ff1_w,  (__nv_bfloat162*)wff1_h,
                                   (__nv_bfloat162*)wff1_l,  NB_WFF1 / 4);
    cvt_hilo_kernel<<<2048, 256>>>((const float4*)ff2_w,  (__nv_bfloat162*)wff2_h,
                                   (__nv_bfloat162*)wff2_l,  NB_WFF2 / 4);

    addpos_kernel<<<(TOKENS * CDIM + 255) / 256, 256>>>(x_in, pos_emb, gx);

    const int MB = (TOKENS + 127) / 128;  // 25
    for (int l = 0; l < LAYERS; l++) {
        // h = LN0(x) -> bf16 hi/lo
        ln_kernel<1><<<TOKENS, 256, CDIM * sizeof(float)>>>(
            gx, nullptr, h_h, h_l, ln0_g + l * CDIM, ln0_b + l * CDIM, CDIM);
        // qkv = h @ qkv_w^T + b
        gemm_mma<0><<<dim3(QKVDIM / 128, MB), 256, GSMEM>>>(
            h_h, h_l, wqkv_h + (size_t)l * QKVDIM * CDIM, wqkv_l + (size_t)l * QKVDIM * CDIM,
            qkv_b + l * QKVDIM, gqkv, nullptr, nullptr, TOKENS, QKVDIM, CDIM);
        // qkv = LN(qkv) -> bf16 hi/lo + per-head q/k norms
        ln_qkv_kernel<<<TOKENS, 256>>>(gqkv, qkvln_g + l * QKVDIM,
                                       qkvln_b + l * QKVDIM, qkv_hh, qkv_ll, gqq, gkk);
        // QK dots via tensor cores
        qk_mma<<<dim3(2, 2, BATCH * HEADS), 256, QKSMEM>>>(qkv_hh, qkv_ll, gQK);
        // riem + BN affine + conv + fused softmax -> P (probabilities)
        attn_post<<<dim3(NTOK, BATCH), 256>>>(
            gQK, gqq, gkk, scale + l, riem_sc + l, temp + l * 24,
            bn_g + l * 24, bn_b + l * 24, conv_w + l * 288, conv_b + l * 12, gP);
        // o = P @ v (V loaded once to smem) -> bf16 hi/lo
        av_prob_kernel<<<dim3(13, BATCH * HEADS), dim3(64, 4), AV_SMEM>>>(
            gP, qkv_hh, qkv_ll, o_h, o_l);
        // x = x + o @ proj_w^T + proj_b
        gemm_mma<1><<<dim3(CDIM / 128, MB), 256, GSMEM>>>(
            o_h, o_l, wproj_h + (size_t)l * CDIM * CDIM, wproj_l + (size_t)l * CDIM * CDIM,
            proj_b + l * CDIM, gx, nullptr, nullptr, TOKENS, CDIM, CDIM);
        // x = LN1(x) in-place + bf16 hi/lo
        ln_kernel<2><<<TOKENS, 256, CDIM * sizeof(float)>>>(
            gx, gx, x_h, x_l, ln1_g + l * CDIM, ln1_b + l * CDIM, CDIM);
        // f = gelu(x @ ff1^T + b) -> bf16 hi/lo
        gemm_mma<2><<<dim3(DFF / 128, MB), 256, GSMEM>>>(
            x_h, x_l, wff1_h + (size_t)l * DFF * CDIM, wff1_l + (size_t)l * DFF * CDIM,
            ff1_b + l * DFF, nullptr, f_h, f_l, TOKENS, DFF, CDIM);
        // x = x + f @ ff2^T + b
        gemm_mma<1><<<dim3(CDIM / 128, MB), 256, GSMEM>>>(
            f_h, f_l, wff2_h + (size_t)l * CDIM * DFF, wff2_l + (size_t)l * CDIM * DFF,
            ff2_b + l * CDIM, gx, nullptr, nullptr, TOKENS, CDIM, DFF);
    }

    ln_kernel<0><<<TOKENS, 256, CDIM * sizeof(float)>>>(
        gx, gx, nullptr, nullptr, norm_g, norm_b, CDIM);
    pool_kernel<<<BATCH, 256>>>(gx, pool_w, pool_b, gpooled);
    fc_kernel<<<(BATCH * NCLS * 32 + 255) / 256, 256>>>(gpooled, fc_w, fc_b,
                                                        (float*)d_out);
}